// round 9
// baseline (speedup 1.0000x reference)
#include <cuda_runtime.h>
#include <cuda_bf16.h>
#include <cstdint>
#include <cstddef>

#define BS   256
#define HID  1024
#define NT   100
#define ACT  32
#define KIN  8000
#define G3   3072
#define OUTD 64

// ---------------- device scratch ----------------
__device__ float g_h0[BS * HID];
__device__ float g_outs[(size_t)NT * BS * HID];
__device__ unsigned g_bars[4 * 32];

// A fragment image: [buf2][m16blk 16][k16chunk 64][lane 32][reg 4] u32
__device__ __align__(16) uint32_t g_AF_hi[2 * 16 * 64 * 32 * 4];   // 1 MB
__device__ __align__(16) uint32_t g_AF_lo[2 * 16 * 64 * 32 * 4];
// Wh packed bf16: [slice 32][k 1024][col 96], col = sub*48+gate*16+h16
__device__ __align__(16) unsigned short g_wBp_hi[32 * HID * 96];
__device__ __align__(16) unsigned short g_wBp_lo[32 * HID * 96];

// ---------------- helpers ----------------
__device__ __forceinline__ float2 ffma2(float2 a, float2 b, float2 c) {
    union U { float2 f; unsigned long long u; };
    U A, B, C, D;
    A.f = a; B.f = b; C.f = c;
    asm("fma.rn.f32x2 %0, %1, %2, %3;" : "=l"(D.u) : "l"(A.u), "l"(B.u), "l"(C.u));
    return D.f;
}
__device__ __forceinline__ float fast_sigmoid(float x) {
    return __fdividef(1.0f, 1.0f + __expf(-x));
}
__device__ __forceinline__ float fast_tanh(float x) {
    float e = __expf(2.0f * x);
    return 1.0f - __fdividef(2.0f, e + 1.0f);
}
__device__ __forceinline__ void split2(float x, unsigned short& h, unsigned short& l) {
    __nv_bfloat16 hb = __float2bfloat16(x);
    float hf = __bfloat162float(hb);
    __nv_bfloat16 lb = __float2bfloat16(x - hf);
    h = *reinterpret_cast<unsigned short*>(&hb);
    l = *reinterpret_cast<unsigned short*>(&lb);
}

#define CP4(dst, src)  asm volatile("cp.async.ca.shared.global [%0], [%1], 4;\n"  :: "r"(dst), "l"(src))
#define CP16(dst, src) asm volatile("cp.async.cg.shared.global [%0], [%1], 16;\n" :: "r"(dst), "l"(src))
#define CP_COMMIT()    asm volatile("cp.async.commit_group;\n")
#define CP_WAIT(n)     asm volatile("cp.async.wait_group %0;\n" :: "n"(n))

__device__ __forceinline__ uint32_t smem_u32(const void* p) {
    uint32_t a;
    asm("{ .reg .u64 t; cvta.to.shared.u64 t, %1; cvt.u32.u64 %0, t; }" : "=r"(a) : "l"(p));
    return a;
}
__device__ __forceinline__ void mma16816(float* c, const uint32_t* a, const uint32_t* b) {
    asm volatile("mma.sync.aligned.m16n8k16.row.col.f32.bf16.bf16.f32 "
        "{%0,%1,%2,%3}, {%4,%5,%6,%7}, {%8,%9}, {%0,%1,%2,%3};"
        : "+f"(c[0]), "+f"(c[1]), "+f"(c[2]), "+f"(c[3])
        : "r"(a[0]), "r"(a[1]), "r"(a[2]), "r"(a[3]), "r"(b[0]), "r"(b[1]));
}
#define LDSM4T(r, addr)                                                         \
    asm volatile("ldmatrix.sync.aligned.m8n8.x4.trans.shared.b16 {%0,%1,%2,%3}, [%4];" \
        : "=r"((r)[0]), "=r"((r)[1]), "=r"((r)[2]), "=r"((r)[3]) : "r"(addr))
#define LDGCG4(r, p)                                                            \
    asm volatile("ld.global.cg.v4.u32 {%0,%1,%2,%3}, [%4];"                     \
        : "=r"((r)[0]), "=r"((r)[1]), "=r"((r)[2]), "=r"((r)[3]) : "l"(p))
#define STGCG(p, v) asm volatile("st.global.cg.u32 [%0], %1;" :: "l"(p), "r"(v))

// ===========================================================================
__global__ void k_zero() {
    if (threadIdx.x < 4 * 32) g_bars[threadIdx.x] = 0u;
}

// ===========================================================================
// k_packW: Wh -> [s 32][k 1024][c 96] bf16 hi/lo. grid (32,16), 256 thr.
// ===========================================================================
__global__ void __launch_bounds__(256) k_packW(const float* __restrict__ Wh) {
    const int s = blockIdx.x, kg = blockIdx.y;
    for (int i = threadIdx.x; i < 64 * 96; i += 256) {
        int k = kg * 64 + i / 96;
        int c = i % 96;
        int sub = c / 48, rem = c % 48;
        int gate = rem / 16, h16 = rem % 16;
        float x = Wh[(size_t)k * G3 + gate * HID + s * 32 + sub * 16 + h16];
        size_t dst = ((size_t)s * HID + k) * 96 + c;
        split2(x, g_wBp_hi[dst], g_wBp_lo[dst]);
    }
}

// ===========================================================================
// k_cvtH0f: h0 fp32 -> A-fragment image, buf 0. grid (256), 256 thr.
// ===========================================================================
__global__ void __launch_bounds__(256) k_cvtH0f(const float* __restrict__ H0) {
    const int m = blockIdx.x;
    const int mb = m >> 4;
    const int lr = m & 7;
    const int rr = (m >> 3) & 1;
    #pragma unroll
    for (int q = 0; q < 2; q++) {
        int p = threadIdx.x + q * 256;     // hid pair index 0..511
        int hid = p * 2;
        float2 v = *reinterpret_cast<const float2*>(H0 + (size_t)m * HID + hid);
        unsigned short h0h, h0l, h1h, h1l;
        split2(v.x, h0h, h0l);
        split2(v.y, h1h, h1l);
        int kc = hid >> 4;
        int khid = hid & 15;
        int pp = khid >> 3;
        int lane = (lr << 2) | ((khid & 7) >> 1);
        int reg = rr + 2 * pp;
        size_t idx = ((((size_t)0 * 16 + mb) * 64 + kc) * 32 + lane) * 4 + reg;
        g_AF_hi[idx] = ((uint32_t)h1h << 16) | h0h;
        g_AF_lo[idx] = ((uint32_t)h1l << 16) | h0l;
    }
}

// ===========================================================================
// k_h0v2 (unchanged)
// ===========================================================================
#define HBK   16
#define HKPER 2000
#define HNT   125
#define HASZ  (HBK * 36)
#define HBSZ  (HBK * 64)
#define HSTG  (HASZ + HBSZ)
#define HGRP  (3 * HSTG)
#define HSMF  (4 * HGRP)

__global__ void __launch_bounds__(512) k_h0v2(const float* __restrict__ X,
                                              const float* __restrict__ W,
                                              const float* __restrict__ bias,
                                              float* __restrict__ H0) {
    extern __shared__ float sm[];
    const int tid  = threadIdx.x;
    const int g    = tid >> 7;
    const int wtid = tid & 127;
    const int tx   = wtid & 15;
    const int ty   = wtid >> 4;
    const int m0 = blockIdx.y * 32, n0 = blockIdx.x * 64;
    float* gb = sm + g * HGRP;

    float b4x = bias[n0 + (tid & 15) * 4 + 0];
    float b4y = bias[n0 + (tid & 15) * 4 + 1];
    float b4z = bias[n0 + (tid & 15) * 4 + 2];
    float b4w = bias[n0 + (tid & 15) * 4 + 3];

    float2 acc[4][2] = {};

    auto load_tile = [&](int stage, int tl) {
        const int kb = g * HKPER + tl * HBK;
        float* dstA = gb + stage * HSTG;
        const float* asrc = X + (size_t)m0 * KIN + kb;
        #pragma unroll
        for (int i = wtid; i < HBK * 32; i += 128) {
            int k = i & 15, m = i >> 4;
            uint32_t d = (uint32_t)__cvta_generic_to_shared(dstA + k * 36 + m);
            CP4(d, asrc + (size_t)m * KIN + k);
        }
        const float* bsrc = W + (size_t)kb * HID + n0;
        float* dstB = dstA + HASZ;
        #pragma unroll
        for (int i = wtid; i < HBK * 16; i += 128) {
            int k = i >> 4, n4 = i & 15;
            uint32_t d = (uint32_t)__cvta_generic_to_shared(dstB + k * 64 + n4 * 4);
            CP16(d, bsrc + (size_t)k * HID + n4 * 4);
        }
    };

    auto compute = [&](int stage) {
        const float* As_ = gb + stage * HSTG;
        const float* B_  = As_ + HASZ;
        #pragma unroll
        for (int k = 0; k < HBK; k++) {
            float4 a4 = *reinterpret_cast<const float4*>(As_ + k * 36 + ty * 4);
            float2 A0 = make_float2(a4.x, a4.x), A1 = make_float2(a4.y, a4.y);
            float2 A2 = make_float2(a4.z, a4.z), A3 = make_float2(a4.w, a4.w);
            float4 b = *reinterpret_cast<const float4*>(B_ + k * 64 + tx * 4);
            float2 b0 = make_float2(b.x, b.y), b1 = make_float2(b.z, b.w);
            acc[0][0] = ffma2(A0, b0, acc[0][0]); acc[0][1] = ffma2(A0, b1, acc[0][1]);
            acc[1][0] = ffma2(A1, b0, acc[1][0]); acc[1][1] = ffma2(A1, b1, acc[1][1]);
            acc[2][0] = ffma2(A2, b0, acc[2][0]); acc[2][1] = ffma2(A2, b1, acc[2][1]);
            acc[3][0] = ffma2(A3, b0, acc[3][0]); acc[3][1] = ffma2(A3, b1, acc[3][1]);
        }
    };

    load_tile(0, 0); CP_COMMIT();
    load_tile(1, 1); CP_COMMIT();
    int cs = 0, ls = 2;
    for (int tl = 0; tl < HNT; tl++) {
        CP_WAIT(1);
        __syncthreads();
        if (tl + 2 < HNT) load_tile(ls, tl + 2);
        CP_COMMIT();
        compute(cs);
        cs = (cs == 2) ? 0 : cs + 1;
        ls = (ls == 2) ? 0 : ls + 1;
    }
    __syncthreads();

    #pragma unroll
    for (int r = 0; r < 4; r++) {
        float4 v = make_float4(acc[r][0].x, acc[r][0].y, acc[r][1].x, acc[r][1].y);
        *reinterpret_cast<float4*>(gb + (ty * 4 + r) * 64 + tx * 4) = v;
    }
    __syncthreads();

    {
        int row = tid >> 4, c0 = (tid & 15) * 4;
        float s0 = 0.f, s1 = 0.f, s2 = 0.f, s3 = 0.f;
        #pragma unroll
        for (int gg = 0; gg < 4; gg++) {
            float4 p = *reinterpret_cast<const float4*>(sm + gg * HGRP + row * 64 + c0);
            s0 += p.x; s1 += p.y; s2 += p.z; s3 += p.w;
        }
        s0 += b4x; s1 += b4y; s2 += b4z; s3 += b4w;
        float4 o = make_float4(s0 > 0.f ? s0 : 0.f, s1 > 0.f ? s1 : 0.f,
                               s2 > 0.f ? s2 : 0.f, s3 > 0.f ? s3 : 0.f);
        *reinterpret_cast<float4*>(H0 + (size_t)(m0 + row) * HID + n0 + c0) = o;
    }
}

// ===========================================================================
// k_steps v3: persistent HMMA GRU.
//  - A via direct fragment LDG.cg (no smem for A)
//  - B streamed via cp.async, BK=64 (16 chunks), 3 stages
//  - fused input GEMM, h_prev in registers, per-mq barrier
// grid (32 slices, 4 mq), 256 thr (8 warps: 4m x 2n), CTA tile 64x96.
// ===========================================================================
#define BSTG_B   26624                       // stage: hi 64*208 + lo 64*208
#define SM_BST(i) ((i) * BSTG_B)
#define SM_WI    (3 * BSTG_B)                // 79872
#define SM_AS    (SM_WI + 96 * 36 * 4)       // 93696
#define SMEM_ST  (SM_AS + 2 * 64 * 36 * 4)   // 112128 B

__global__ void __launch_bounds__(256, 1) k_steps(const float* __restrict__ h0,
                                                  const float* __restrict__ action,
                                                  const float* __restrict__ Wi,
                                                  const float* __restrict__ bi,
                                                  const float* __restrict__ bhn,
                                                  float* __restrict__ outs) {
    extern __shared__ char smem[];
    const uint32_t sb = smem_u32(smem);
    float* wi_s = reinterpret_cast<float*>(smem + SM_WI);
    float* a_s  = reinterpret_cast<float*>(smem + SM_AS);

    const int tid = threadIdx.x;
    const int w = tid >> 5, l = tid & 31;
    const int s = blockIdx.x;          // hid slice (32 cols)
    const int mq = blockIdx.y;         // m quarter (64 rows)
    const int wm = w & 3;              // warp m group (16 rows)
    const int wn = w >> 2;             // warp n half (sub 0/1)
    const int lr = l >> 2;
    const int lc2 = (l & 3) * 2;
    const int mb = mq * 4 + wm;        // m16 block id
    const int kcp = s * 2 + wn;        // producer k16 chunk for A-frag store
    const int b_krow = l & 15;
    const int b_noff = wn * 48 + (l >> 4) * 8;
    const int hidbase = s * 32 + wn * 16;

    float bh[2][2];
    #pragma unroll
    for (int pp = 0; pp < 2; pp++) {
        float2 v = *reinterpret_cast<const float2*>(bhn + hidbase + pp * 8 + lc2);
        bh[pp][0] = v.x; bh[pp][1] = v.y;
    }
    float biv[3][2][2];
    #pragma unroll
    for (int gate = 0; gate < 3; gate++)
        #pragma unroll
        for (int pp = 0; pp < 2; pp++) {
            float2 v = *reinterpret_cast<const float2*>(bi + gate * HID + hidbase + pp * 8 + lc2);
            biv[gate][pp][0] = v.x; biv[gate][pp][1] = v.y;
        }
    float hpreg[2][2][2];
    #pragma unroll
    for (int rr = 0; rr < 2; rr++) {
        const int m = mq * 64 + wm * 16 + lr + rr * 8;
        #pragma unroll
        for (int pp = 0; pp < 2; pp++) {
            float2 v = *reinterpret_cast<const float2*>(h0 + (size_t)m * HID + hidbase + pp * 8 + lc2);
            hpreg[rr][pp][0] = v.x; hpreg[rr][pp][1] = v.y;
        }
    }

    // Wi slice resident: wi_s[col 96][36]; col = gate*32 + cl, hid = s*32 + cl
    for (int i = tid; i < 96 * 32; i += 256) {
        int col = i >> 5, k = i & 31;
        int gate = col >> 5, cl = col & 31;
        wi_s[col * 36 + k] = Wi[(size_t)k * G3 + gate * HID + s * 32 + cl];
    }
    __syncthreads();

    const char* srcBH = (const char*)(g_wBp_hi + (size_t)s * HID * 96);
    const char* srcBL = (const char*)(g_wBp_lo + (size_t)s * HID * 96);

    auto load_B = [&](int ch, int st) {   // 64 k-rows x 192B, hi + lo
        uint32_t base = sb + SM_BST(st);
        #pragma unroll
        for (int i = tid; i < 768; i += 256) {
            int r = i / 12, sg = i % 12;
            const char* sp = srcBH + ((size_t)(ch * 64 + r)) * 192 + sg * 16;
            CP16(base + r * 208 + sg * 16, sp);
            const char* sp2 = srcBL + ((size_t)(ch * 64 + r)) * 192 + sg * 16;
            CP16(base + 13312 + r * 208 + sg * 16, sp2);
        }
    };
    auto load_act = [&](int tt) {
        uint32_t ab = sb + SM_AS + (tt & 1) * (64 * 36 * 4);
        #pragma unroll
        for (int i = tid; i < 512; i += 256) {
            int row = i >> 3, seg = i & 7;
            const float* src = action + ((size_t)(mq * 64 + row) * NT + tt) * ACT + seg * 4;
            CP16(ab + row * 144 + seg * 16, src);
        }
    };

    load_B(0, 0); load_act(0); CP_COMMIT();
    load_B(1, 1); CP_COMMIT();

    uint32_t aHb[2][4][4], aLb[2][4][4];   // [chunk parity][kc-in-chunk][frag]

    #pragma unroll 1
    for (int t = 0; t < NT; t++) {
        const int rbuf = t & 1;
        const uint32_t* AFH = g_AF_hi + (((size_t)rbuf * 16 + mb) * 64) * 128;
        const uint32_t* AFL = g_AF_lo + (((size_t)rbuf * 16 + mb) * 64) * 128;

        auto load_Afrags = [&](int ch, int ab) {
            #pragma unroll
            for (int kc4 = 0; kc4 < 4; kc4++) {
                const uint32_t* p = AFH + (size_t)(ch * 4 + kc4) * 128 + l * 4;
                LDGCG4(aHb[ab][kc4], p);
                const uint32_t* p2 = AFL + (size_t)(ch * 4 + kc4) * 128 + l * 4;
                LDGCG4(aLb[ab][kc4], p2);
            }
        };

        // ---- per-mq barrier: h_{t-1} A-frag writes visible after release ----
        if (t > 0) {
            if (tid == 0) {
                unsigned* ctr = &g_bars[mq * 32];
                const unsigned target = 32u * (unsigned)t;
                atomicAdd(ctr, 1u);
                unsigned v;
                do {
                    asm volatile("ld.volatile.global.u32 %0, [%1];" : "=r"(v) : "l"(ctr));
                } while (v < target);
            }
            __syncthreads();
            __threadfence();
        }

        load_Afrags(0, 0);

        float c[6][4] = {};

        auto compute = [&](int st, int ab) {
            uint32_t base = sb + SM_BST(st);
            #pragma unroll
            for (int kc4 = 0; kc4 < 4; kc4++) {
                const int k0 = kc4 * 16;
                const uint32_t* aH = aHb[ab][kc4];
                const uint32_t* aL = aLb[ab][kc4];
                uint32_t bH[6][2], bL[6][2];
                #pragma unroll
                for (int g2 = 0; g2 < 3; g2++) {
                    uint32_t adB = base + (k0 + b_krow) * 208 + (b_noff + g2 * 16) * 2;
                    uint32_t r4[4];
                    LDSM4T(r4, adB);
                    bH[g2 * 2][0] = r4[0]; bH[g2 * 2][1] = r4[1];
                    bH[g2 * 2 + 1][0] = r4[2]; bH[g2 * 2 + 1][1] = r4[3];
                    LDSM4T(r4, adB + 13312);
                    bL[g2 * 2][0] = r4[0]; bL[g2 * 2][1] = r4[1];
                    bL[g2 * 2 + 1][0] = r4[2]; bL[g2 * 2 + 1][1] = r4[3];
                }
                #pragma unroll
                for (int g = 0; g < 6; g++) {
                    mma16816(c[g], aH, bH[g]);
                    mma16816(c[g], aH, bL[g]);
                    mma16816(c[g], aL, bH[g]);
                }
            }
        };

        #pragma unroll 1
        for (int ch = 0; ch < 16; ch++) {
            CP_WAIT(1);
            __syncthreads();
            if (ch + 2 < 16) load_B(ch + 2, (ch + 2) % 3);
            CP_COMMIT();
            if (ch + 1 < 16) load_Afrags(ch + 1, (ch + 1) & 1);
            compute(ch % 3, ch & 1);
        }
        __syncthreads();   // computes done before stage 0/1 refill

        if (t + 1 < NT) {
            load_B(0, 0); load_act(t + 1); CP_COMMIT();
            load_B(1, 1); CP_COMMIT();
        }

        // ---- fused input GEMM: giv = a_t @ Wi + bi ----
        float giv[2][12];
        #pragma unroll
        for (int rr = 0; rr < 2; rr++)
            #pragma unroll
            for (int gate = 0; gate < 3; gate++)
                #pragma unroll
                for (int pp = 0; pp < 2; pp++) {
                    giv[rr][gate * 4 + pp * 2 + 0] = biv[gate][pp][0];
                    giv[rr][gate * 4 + pp * 2 + 1] = biv[gate][pp][1];
                }
        {
            const float* ab = a_s + (t & 1) * (64 * 36);
            const float* r0 = ab + (wm * 16 + lr) * 36;
            const float* r1 = r0 + 8 * 36;
            #pragma unroll
            for (int k4 = 0; k4 < 8; k4++) {
                float4 a0 = *reinterpret_cast<const float4*>(r0 + k4 * 4);
                float4 a1 = *reinterpret_cast<const float4*>(r1 + k4 * 4);
                #pragma unroll
                for (int gate = 0; gate < 3; gate++)
                    #pragma unroll
                    for (int pp = 0; pp < 2; pp++)
                        #pragma unroll
                        for (int e = 0; e < 2; e++) {
                            int col = gate * 32 + wn * 16 + pp * 8 + lc2 + e;
                            float4 wv = *reinterpret_cast<const float4*>(wi_s + col * 36 + k4 * 4);
                            int j = gate * 4 + pp * 2 + e;
                            giv[0][j] += a0.x * wv.x + a0.y * wv.y + a0.z * wv.z + a0.w * wv.w;
                            giv[1][j] += a1.x * wv.x + a1.y * wv.y + a1.z * wv.z + a1.w * wv.w;
                        }
            }
        }

        // ---- epilogue: gates, blend, store outs + next A-frags ----
        const int wbuf = (t + 1) & 1;
        uint32_t* dAFH = g_AF_hi + (((size_t)wbuf * 16 + mb) * 64 + kcp) * 128 + l * 4;
        uint32_t* dAFL = g_AF_lo + (((size_t)wbuf * 16 + mb) * 64 + kcp) * 128 + l * 4;
        #pragma unroll
        for (int rr = 0; rr < 2; rr++) {
            const int m = mq * 64 + wm * 16 + lr + rr * 8;
            float* orow = outs + ((size_t)t * BS + m) * HID;
            #pragma unroll
            for (int pp = 0; pp < 2; pp++) {
                const int hid = hidbase + pp * 8 + lc2;
                float h[2];
                #pragma unroll
                for (int e = 0; e < 2; e++) {
                    float rv = c[pp][2 * rr + e];
                    float zv = c[2 + pp][2 * rr + e];
                    float nv = c[4 + pp][2 * rr + e];
                    float rg = fast_sigmoid(rv + giv[rr][0 * 4 + pp * 2 + e]);
                    float zg = fast_sigmoid(zv + giv[rr][1 * 4 + pp * 2 + e]);
                    float ng = fast_tanh(giv[rr][2 * 4 + pp * 2 + e] + rg * (nv + bh[pp][e]));
                    h[e] = (1.0f - zg) * ng + zg * hpreg[rr][pp][e];
                    hpreg[rr][pp][e] = h[e];
                }
                *reinterpret_cast<float2*>(orow + hid) = make_float2(h[0], h[1]);
                if (t + 1 < NT) {
                    unsigned short hi0, hi1, lo0, lo1;
                    split2(h[0], hi0, lo0);
                    split2(h[1], hi1, lo1);
                    int reg = rr + 2 * pp;
                    STGCG(dAFH + reg, ((uint32_t)hi1 << 16) | hi0);
                    STGCG(dAFL + reg, ((uint32_t)lo1 << 16) | lo0);
                }
            }
        }

        if (t + 1 < NT) {
            __threadfence();
            __syncthreads();
        }
    }
}

// ===========================================================================
// k_out (unchanged)
// ===========================================================================
__global__ void __launch_bounds__(256) k_out(const float* __restrict__ outs,
                                             const float* __restrict__ Wo,
                                             const float* __restrict__ bo,
                                             float* __restrict__ out) {
    __shared__ float As[32][33];
    __shared__ float Bs[32][64];
    const int tx = threadIdx.x, ty = threadIdx.y;
    const int tid = ty * 16 + tx;
    const int R0 = blockIdx.x * 32;
    float2 acc[2][2] = {};

    for (int k0 = 0; k0 < HID; k0 += 32) {
        #pragma unroll
        for (int i = tid; i < 32 * 32; i += 256) {
            int m = i >> 5, k = i & 31;
            As[k][m] = outs[(size_t)(R0 + m) * HID + k0 + k];
        }
        #pragma unroll
        for (int i = tid; i < 32 * 64; i += 256) {
            int k = i >> 6, n = i & 63;
            Bs[k][n] = Wo[(size_t)(k0 + k) * OUTD + n];
        }
        __syncthreads();
        #pragma unroll
        for (int k = 0; k < 32; k++) {
            float a0 = As[k][ty * 2 + 0], a1 = As[k][ty * 2 + 1];
            float2 A0 = make_float2(a0, a0), A1 = make_float2(a1, a1);
            const float2* bp = reinterpret_cast<const float2*>(&Bs[k][tx * 4]);
            float2 b0 = bp[0], b1 = bp[1];
            acc[0][0] = ffma2(A0, b0, acc[0][0]);
            acc[0][1] = ffma2(A0, b1, acc[0][1]);
            acc[1][0] = ffma2(A1, b0, acc[1][0]);
            acc[1][1] = ffma2(A1, b1, acc[1][1]);
        }
        __syncthreads();
    }

    #pragma unroll
    for (int r = 0; r < 2; r++) {
        int R = R0 + ty * 2 + r;
        int tt = R >> 8;
        int b  = R & (BS - 1);
        #pragma unroll
        for (int c = 0; c < 2; c++) {
            int n = tx * 4 + c * 2;
            out[((size_t)b * NT + tt) * OUTD + n]     = acc[r][c].x + bo[n];
            out[((size_t)b * NT + tt) * OUTD + n + 1] = acc[r][c].y + bo[n + 1];
        }
    }
}

extern "C" void kernel_launch(void* const* d_in, const int* in_sizes, int n_in,
                              void* d_out, int out_size) {
    const float* history = (const float*)d_in[0];
    const float* action  = (const float*)d_in[1];
    const float* W_in    = (const float*)d_in[2];
    const float* b_in    = (const float*)d_in[3];
    const float* Wi      = (const float*)d_in[4];
    const float* bi      = (const float*)d_in[5];
    const float* Wh      = (const float*)d_in[6];
    const float* bhn     = (const float*)d_in[7];
    const float* Wo      = (const float*)d_in[8];
    const float* bo      = (const float*)d_in[9];
    float* out = (float*)d_out;

    float *h0buf = nullptr, *outsbuf = nullptr;
    cudaGetSymbolAddress((void**)&h0buf, g_h0);
    cudaGetSymbolAddress((void**)&outsbuf, g_outs);

    const int smem_h0 = HSMF * 4;
    cudaFuncSetAttribute(k_h0v2, cudaFuncAttributeMaxDynamicSharedMemorySize, smem_h0);
    cudaFuncSetAttribute(k_steps, cudaFuncAttributeMaxDynamicSharedMemorySize, SMEM_ST);

    k_zero<<<1, 128>>>();
    k_h0v2<<<dim3(HID / 64, BS / 32), 512, smem_h0>>>(history, W_in, b_in, h0buf);
    k_packW<<<dim3(32, 16), 256>>>(Wh);
    k_cvtH0f<<<BS, 256>>>(h0buf);

    k_steps<<<dim3(32, 4), 256, SMEM_ST>>>(h0buf, action, Wi, bi, bhn, outsbuf);

    k_out<<<dim3(NT * BS / 32), dim3(16, 16)>>>(outsbuf, Wo, bo, out);
}

// round 10
// speedup vs baseline: 1.4159x; 1.4159x over previous
#include <cuda_runtime.h>
#include <cuda_bf16.h>
#include <cstdint>
#include <cstddef>

#define BS   256
#define HID  1024
#define NT   100
#define ACT  32
#define KIN  8000
#define G3   3072
#define OUTD 64

// ---------------- device scratch (allocation-free rule) ----------------
__device__ float g_h0[BS * HID];
__device__ float g_outs[(size_t)NT * BS * HID];     // [t][b][hid]
__device__ unsigned g_bars[4 * 32];                 // per-mq barrier counters

// h (A) bf16 images, double buffered across steps: [buf 2][m 256][k 1024]
__device__ __align__(16) unsigned short g_hA_hi[2 * BS * HID];   // 1 MB
__device__ __align__(16) unsigned short g_hA_lo[2 * BS * HID];
// Wh (B) packed bf16: [slice 32][k 1024][col 96]
// col c = sub*48 + gate*16 + h16;  hid = s*32 + sub*16 + h16
__device__ __align__(16) unsigned short g_wBp_hi[32 * HID * 96]; // 6.3 MB
__device__ __align__(16) unsigned short g_wBp_lo[32 * HID * 96];

// ---------------- helpers ----------------
__device__ __forceinline__ float2 ffma2(float2 a, float2 b, float2 c) {
    union U { float2 f; unsigned long long u; };
    U A, B, C, D;
    A.f = a; B.f = b; C.f = c;
    asm("fma.rn.f32x2 %0, %1, %2, %3;" : "=l"(D.u) : "l"(A.u), "l"(B.u), "l"(C.u));
    return D.f;
}
__device__ __forceinline__ float fast_sigmoid(float x) {
    return __fdividef(1.0f, 1.0f + __expf(-x));
}
__device__ __forceinline__ float fast_tanh(float x) {
    float e = __expf(2.0f * x);
    return 1.0f - __fdividef(2.0f, e + 1.0f);
}
__device__ __forceinline__ void split2(float x, unsigned short& h, unsigned short& l) {
    __nv_bfloat16 hb = __float2bfloat16(x);
    float hf = __bfloat162float(hb);
    __nv_bfloat16 lb = __float2bfloat16(x - hf);
    h = *reinterpret_cast<unsigned short*>(&hb);
    l = *reinterpret_cast<unsigned short*>(&lb);
}

#define CP4(dst, src)  asm volatile("cp.async.ca.shared.global [%0], [%1], 4;\n"  :: "r"(dst), "l"(src))
#define CP16(dst, src) asm volatile("cp.async.cg.shared.global [%0], [%1], 16;\n" :: "r"(dst), "l"(src))
#define CP_COMMIT()    asm volatile("cp.async.commit_group;\n")
#define CP_WAIT(n)     asm volatile("cp.async.wait_group %0;\n" :: "n"(n))

__device__ __forceinline__ uint32_t smem_u32(const void* p) {
    uint32_t a;
    asm("{ .reg .u64 t; cvta.to.shared.u64 t, %1; cvt.u32.u64 %0, t; }" : "=r"(a) : "l"(p));
    return a;
}
__device__ __forceinline__ void mma16816(float* c, const uint32_t* a, const uint32_t* b) {
    asm volatile("mma.sync.aligned.m16n8k16.row.col.f32.bf16.bf16.f32 "
        "{%0,%1,%2,%3}, {%4,%5,%6,%7}, {%8,%9}, {%0,%1,%2,%3};"
        : "+f"(c[0]), "+f"(c[1]), "+f"(c[2]), "+f"(c[3])
        : "r"(a[0]), "r"(a[1]), "r"(a[2]), "r"(a[3]), "r"(b[0]), "r"(b[1]));
}
#define LDSM4(r, addr)                                                          \
    asm volatile("ldmatrix.sync.aligned.m8n8.x4.shared.b16 {%0,%1,%2,%3}, [%4];"\
        : "=r"((r)[0]), "=r"((r)[1]), "=r"((r)[2]), "=r"((r)[3]) : "r"(addr))
#define LDSM4T(r, addr)                                                         \
    asm volatile("ldmatrix.sync.aligned.m8n8.x4.trans.shared.b16 {%0,%1,%2,%3}, [%4];" \
        : "=r"((r)[0]), "=r"((r)[1]), "=r"((r)[2]), "=r"((r)[3]) : "r"(addr))

// ===========================================================================
__global__ void k_zero() {
    if (threadIdx.x < 4 * 32) g_bars[threadIdx.x] = 0u;
}

// ===========================================================================
// k_packW: Wh[k][3072] -> packed [32][1024][96] bf16 hi/lo. grid (32,16), 256.
// ===========================================================================
__global__ void __launch_bounds__(256) k_packW(const float* __restrict__ Wh) {
    const int s = blockIdx.x, kg = blockIdx.y;
    for (int i = threadIdx.x; i < 64 * 96; i += 256) {
        int k = kg * 64 + i / 96;
        int c = i % 96;
        int sub = c / 48, rem = c % 48;
        int gate = rem / 16, h16 = rem % 16;
        float x = Wh[(size_t)k * G3 + gate * HID + s * 32 + sub * 16 + h16];
        size_t dst = ((size_t)s * HID + k) * 96 + c;
        split2(x, g_wBp_hi[dst], g_wBp_lo[dst]);
    }
}

// ===========================================================================
// k_cvtH0: h0 fp32 -> A image buf 0. grid (256), 256 thr.
// ===========================================================================
__global__ void __launch_bounds__(256) k_cvtH0(const float* __restrict__ H0) {
    const int m = blockIdx.x;
    for (int k = threadIdx.x * 4; k < HID; k += 1024) {
        float4 v = *reinterpret_cast<const float4*>(H0 + (size_t)m * HID + k);
        size_t d = (size_t)m * HID + k;
        split2(v.x, g_hA_hi[d],     g_hA_lo[d]);
        split2(v.y, g_hA_hi[d + 1], g_hA_lo[d + 1]);
        split2(v.z, g_hA_hi[d + 2], g_hA_lo[d + 2]);
        split2(v.w, g_hA_hi[d + 3], g_hA_lo[d + 3]);
    }
}

// ===========================================================================
// k_h0v2 (unchanged, race-fixed)
// ===========================================================================
#define HBK   16
#define HKPER 2000
#define HNT   125
#define HASZ  (HBK * 36)
#define HBSZ  (HBK * 64)
#define HSTG  (HASZ + HBSZ)
#define HGRP  (3 * HSTG)
#define HSMF  (4 * HGRP)

__global__ void __launch_bounds__(512) k_h0v2(const float* __restrict__ X,
                                              const float* __restrict__ W,
                                              const float* __restrict__ bias,
                                              float* __restrict__ H0) {
    extern __shared__ float sm[];
    const int tid  = threadIdx.x;
    const int g    = tid >> 7;
    const int wtid = tid & 127;
    const int tx   = wtid & 15;
    const int ty   = wtid >> 4;
    const int m0 = blockIdx.y * 32, n0 = blockIdx.x * 64;
    float* gb = sm + g * HGRP;

    float b4x = bias[n0 + (tid & 15) * 4 + 0];
    float b4y = bias[n0 + (tid & 15) * 4 + 1];
    float b4z = bias[n0 + (tid & 15) * 4 + 2];
    float b4w = bias[n0 + (tid & 15) * 4 + 3];

    float2 acc[4][2] = {};

    auto load_tile = [&](int stage, int tl) {
        const int kb = g * HKPER + tl * HBK;
        float* dstA = gb + stage * HSTG;
        const float* asrc = X + (size_t)m0 * KIN + kb;
        #pragma unroll
        for (int i = wtid; i < HBK * 32; i += 128) {
            int k = i & 15, m = i >> 4;
            uint32_t d = (uint32_t)__cvta_generic_to_shared(dstA + k * 36 + m);
            CP4(d, asrc + (size_t)m * KIN + k);
        }
        const float* bsrc = W + (size_t)kb * HID + n0;
        float* dstB = dstA + HASZ;
        #pragma unroll
        for (int i = wtid; i < HBK * 16; i += 128) {
            int k = i >> 4, n4 = i & 15;
            uint32_t d = (uint32_t)__cvta_generic_to_shared(dstB + k * 64 + n4 * 4);
            CP16(d, bsrc + (size_t)k * HID + n4 * 4);
        }
    };

    auto compute = [&](int stage) {
        const float* As_ = gb + stage * HSTG;
        const float* B_  = As_ + HASZ;
        #pragma unroll
        for (int k = 0; k < HBK; k++) {
            float4 a4 = *reinterpret_cast<const float4*>(As_ + k * 36 + ty * 4);
            float2 A0 = make_float2(a4.x, a4.x), A1 = make_float2(a4.y, a4.y);
            float2 A2 = make_float2(a4.z, a4.z), A3 = make_float2(a4.w, a4.w);
            float4 b = *reinterpret_cast<const float4*>(B_ + k * 64 + tx * 4);
            float2 b0 = make_float2(b.x, b.y), b1 = make_float2(b.z, b.w);
            acc[0][0] = ffma2(A0, b0, acc[0][0]); acc[0][1] = ffma2(A0, b1, acc[0][1]);
            acc[1][0] = ffma2(A1, b0, acc[1][0]); acc[1][1] = ffma2(A1, b1, acc[1][1]);
            acc[2][0] = ffma2(A2, b0, acc[2][0]); acc[2][1] = ffma2(A2, b1, acc[2][1]);
            acc[3][0] = ffma2(A3, b0, acc[3][0]); acc[3][1] = ffma2(A3, b1, acc[3][1]);
        }
    };

    load_tile(0, 0); CP_COMMIT();
    load_tile(1, 1); CP_COMMIT();
    int cs = 0, ls = 2;
    for (int tl = 0; tl < HNT; tl++) {
        CP_WAIT(1);
        __syncthreads();
        if (tl + 2 < HNT) load_tile(ls, tl + 2);
        CP_COMMIT();
        compute(cs);
        cs = (cs == 2) ? 0 : cs + 1;
        ls = (ls == 2) ? 0 : ls + 1;
    }
    __syncthreads();

    #pragma unroll
    for (int r = 0; r < 4; r++) {
        float4 v = make_float4(acc[r][0].x, acc[r][0].y, acc[r][1].x, acc[r][1].y);
        *reinterpret_cast<float4*>(gb + (ty * 4 + r) * 64 + tx * 4) = v;
    }
    __syncthreads();

    {
        int row = tid >> 4, c0 = (tid & 15) * 4;
        float s0 = 0.f, s1 = 0.f, s2 = 0.f, s3 = 0.f;
        #pragma unroll
        for (int gg = 0; gg < 4; gg++) {
            float4 p = *reinterpret_cast<const float4*>(sm + gg * HGRP + row * 64 + c0);
            s0 += p.x; s1 += p.y; s2 += p.z; s3 += p.w;
        }
        s0 += b4x; s1 += b4y; s2 += b4z; s3 += b4w;
        float4 o = make_float4(s0 > 0.f ? s0 : 0.f, s1 > 0.f ? s1 : 0.f,
                               s2 > 0.f ? s2 : 0.f, s3 > 0.f ? s3 : 0.f);
        *reinterpret_cast<float4*>(H0 + (size_t)(m0 + row) * HID + n0 + c0) = o;
    }
}

// ===========================================================================
// k_steps_mma v4: R7 structure with BK=64 (16 chunks/step, half the syncs).
// grid (32 slices, 4 mq) = 128 CTAs, 256 thr (8 warps: 4m x 2n), tile 64x96.
//  - A/B via cp.async, 3 stages of 45056 B
//  - Wi slice resident; action double-buffered; h_prev in regs; per-mq barrier
// ===========================================================================
#define OFF_AH 0
#define OFF_AL 9216
#define OFF_BH 18432
#define OFF_BL 31744
#define STG_B  45056
#define APITCH_B 144            // 9 x 16B (odd) -> ldsm conflict-free
#define BPITCH_B 208            // 13 x 16B (odd)
#define SM_WI  (3 * STG_B)                  // 135168: Wi tile [96][36] fp32
#define SM_AS  (SM_WI + 96 * 36 * 4)        // 148992: action [2][64][36] fp32
#define SMEM_MMA (SM_AS + 2 * 64 * 36 * 4)  // 167424 B

__global__ void __launch_bounds__(256, 1) k_steps_mma(const float* __restrict__ h0,
                                                      const float* __restrict__ action,
                                                      const float* __restrict__ Wi,
                                                      const float* __restrict__ bi,
                                                      const float* __restrict__ bhn,
                                                      float* __restrict__ outs) {
    extern __shared__ char smem[];
    const uint32_t sb = smem_u32(smem);
    float* wi_s = reinterpret_cast<float*>(smem + SM_WI);
    float* a_s  = reinterpret_cast<float*>(smem + SM_AS);

    const int tid = threadIdx.x;
    const int w = tid >> 5, l = tid & 31;
    const int s = blockIdx.x;          // hid slice (32 cols)
    const int mq = blockIdx.y;         // m quarter (64 rows)
    const int wm = w & 3;              // warp m group (16 rows)
    const int wn = w >> 2;             // warp n half (sub 0/1)
    const int lr = l >> 2;             // frag row 0..7
    const int lc2 = (l & 3) * 2;       // frag col pair base

    const int a_row  = wm * 16 + (l & 15);
    const int a_koff = (l >> 4) * 8;
    const int b_krow = l & 15;
    const int b_noff = wn * 48 + (l >> 4) * 8;

    const int hidbase = s * 32 + wn * 16;

    float bh[2][2];
    #pragma unroll
    for (int pp = 0; pp < 2; pp++) {
        float2 v = *reinterpret_cast<const float2*>(bhn + hidbase + pp * 8 + lc2);
        bh[pp][0] = v.x; bh[pp][1] = v.y;
    }
    float biv[3][2][2];
    #pragma unroll
    for (int gate = 0; gate < 3; gate++)
        #pragma unroll
        for (int pp = 0; pp < 2; pp++) {
            float2 v = *reinterpret_cast<const float2*>(bi + gate * HID + hidbase + pp * 8 + lc2);
            biv[gate][pp][0] = v.x; biv[gate][pp][1] = v.y;
        }
    float hpreg[2][2][2];
    #pragma unroll
    for (int rr = 0; rr < 2; rr++) {
        const int m = mq * 64 + wm * 16 + lr + rr * 8;
        #pragma unroll
        for (int pp = 0; pp < 2; pp++) {
            float2 v = *reinterpret_cast<const float2*>(h0 + (size_t)m * HID + hidbase + pp * 8 + lc2);
            hpreg[rr][pp][0] = v.x; hpreg[rr][pp][1] = v.y;
        }
    }

    // Wi slice resident: wi_s[col 96][36]; col = gate*32 + cl, hid = s*32 + cl
    for (int i = tid; i < 96 * 32; i += 256) {
        int col = i >> 5, k = i & 31;
        int gate = col >> 5, cl = col & 31;
        wi_s[col * 36 + k] = Wi[(size_t)k * G3 + gate * HID + s * 32 + cl];
    }
    __syncthreads();

    const char* srcBH = (const char*)(g_wBp_hi + (size_t)s * HID * 96);
    const char* srcBL = (const char*)(g_wBp_lo + (size_t)s * HID * 96);

    auto load_B = [&](int ch, int st) {    // 64 k-rows x 192B, hi + lo
        uint32_t base = sb + st * STG_B;
        #pragma unroll
        for (int i = tid; i < 768; i += 256) {
            int r = i / 12, sg = i % 12;
            const char* sp = srcBH + ((size_t)(ch * 64 + r)) * 192 + sg * 16;
            CP16(base + OFF_BH + r * BPITCH_B + sg * 16, sp);
            const char* sp2 = srcBL + ((size_t)(ch * 64 + r)) * 192 + sg * 16;
            CP16(base + OFF_BL + r * BPITCH_B + sg * 16, sp2);
        }
    };
    auto load_act = [&](int tt) {
        uint32_t ab = sb + SM_AS + (tt & 1) * (64 * 36 * 4);
        #pragma unroll
        for (int i = tid; i < 512; i += 256) {
            int row = i >> 3, seg = i & 7;
            const float* src = action + ((size_t)(mq * 64 + row) * NT + tt) * ACT + seg * 4;
            CP16(ab + row * 144 + seg * 16, src);
        }
    };

    // step-0 prefetch: B chunks 0,1 + action(0)
    load_B(0, 0); load_act(0); CP_COMMIT();
    load_B(1, 1); CP_COMMIT();

    #pragma unroll 1
    for (int t = 0; t < NT; t++) {
        const int rbuf = t & 1;
        const char* srcAH = (const char*)(g_hA_hi + (size_t)rbuf * BS * HID + (size_t)mq * 64 * HID);
        const char* srcAL = (const char*)(g_hA_lo + (size_t)rbuf * BS * HID + (size_t)mq * 64 * HID);

        auto load_A = [&](int ch, int st) {   // 64 rows x 128B (64 k), hi + lo
            uint32_t base = sb + st * STG_B;
            #pragma unroll
            for (int i = tid; i < 512; i += 256) {
                int row = i >> 3, seg = i & 7;
                const char* sa = srcAH + (size_t)row * (HID * 2) + ch * 128 + seg * 16;
                CP16(base + OFF_AH + row * APITCH_B + seg * 16, sa);
                const char* sa2 = srcAL + (size_t)row * (HID * 2) + ch * 128 + seg * 16;
                CP16(base + OFF_AL + row * APITCH_B + seg * 16, sa2);
            }
        };

        // ---- per-mq barrier: h_{t-1} A-image writes visible after release ----
        if (t > 0) {
            if (tid == 0) {
                unsigned* ctr = &g_bars[mq * 32];
                const unsigned target = 32u * (unsigned)t;
                atomicAdd(ctr, 1u);
                unsigned v;
                do {
                    asm volatile("ld.volatile.global.u32 %0, [%1];" : "=r"(v) : "l"(ctr));
                } while (v < target);
            }
            __syncthreads();
            __threadfence();
        }

        load_A(0, 0); CP_COMMIT();
        load_A(1, 1); CP_COMMIT();

        float c[6][4] = {};

        auto compute = [&](int st) {
            uint32_t base = sb + st * STG_B;
            #pragma unroll
            for (int kk = 0; kk < 4; kk++) {
                const int k0 = kk * 16;
                uint32_t aH[4], aL[4];
                uint32_t adA = base + OFF_AH + a_row * APITCH_B + (k0 + a_koff) * 2;
                LDSM4(aH, adA);
                LDSM4(aL, adA + (OFF_AL - OFF_AH));
                uint32_t bH[6][2], bL[6][2];
                #pragma unroll
                for (int g2 = 0; g2 < 3; g2++) {
                    uint32_t adB = base + OFF_BH + (k0 + b_krow) * BPITCH_B + (b_noff + g2 * 16) * 2;
                    uint32_t r4[4];
                    LDSM4T(r4, adB);
                    bH[g2 * 2][0] = r4[0]; bH[g2 * 2][1] = r4[1];
                    bH[g2 * 2 + 1][0] = r4[2]; bH[g2 * 2 + 1][1] = r4[3];
                    LDSM4T(r4, adB + (OFF_BL - OFF_BH));
                    bL[g2 * 2][0] = r4[0]; bL[g2 * 2][1] = r4[1];
                    bL[g2 * 2 + 1][0] = r4[2]; bL[g2 * 2 + 1][1] = r4[3];
                }
                #pragma unroll
                for (int g = 0; g < 6; g++) {
                    mma16816(c[g], aH, bH[g]);
                    mma16816(c[g], aH, bL[g]);
                    mma16816(c[g], aL, bH[g]);
                }
            }
        };

        #pragma unroll 1
        for (int ch = 0; ch < 16; ch++) {
            CP_WAIT(1);
            __syncthreads();
            if (ch + 2 < 16) {
                int st2 = (ch + 2) % 3;
                load_A(ch + 2, st2);
                load_B(ch + 2, st2);
            }
            CP_COMMIT();
            compute(ch % 3);
        }
        __syncthreads();   // all computes done before stage smem reused

        // prefetch next step's B chunks + action (input data; pre-barrier OK)
        if (t + 1 < NT) {
            load_B(0, 0); load_act(t + 1); CP_COMMIT();
            load_B(1, 1); CP_COMMIT();
        }

        // ---- fused input GEMM: giv = a_t @ Wi + bi (lane-local) ----
        float giv[2][12];
        #pragma unroll
        for (int rr = 0; rr < 2; rr++)
            #pragma unroll
            for (int gate = 0; gate < 3; gate++)
                #pragma unroll
                for (int pp = 0; pp < 2; pp++) {
                    giv[rr][gate * 4 + pp * 2 + 0] = biv[gate][pp][0];
                    giv[rr][gate * 4 + pp * 2 + 1] = biv[gate][pp][1];
                }
        {
            const float* ab = a_s + (t & 1) * (64 * 36);
            const float* r0 = ab + (wm * 16 + lr) * 36;
            const float* r1 = r0 + 8 * 36;
            #pragma unroll
            for (int k4 = 0; k4 < 8; k4++) {
                float4 a0 = *reinterpret_cast<const float4*>(r0 + k4 * 4);
                float4 a1 = *reinterpret_cast<const float4*>(r1 + k4 * 4);
                #pragma unroll
                for (int gate = 0; gate < 3; gate++)
                    #pragma unroll
                    for (int pp = 0; pp < 2; pp++)
                        #pragma unroll
                        for (int e = 0; e < 2; e++) {
                            int col = gate * 32 + wn * 16 + pp * 8 + lc2 + e;
                            float4 wv = *reinterpret_cast<const float4*>(wi_s + col * 36 + k4 * 4);
                            int j = gate * 4 + pp * 2 + e;
                            giv[0][j] += a0.x * wv.x + a0.y * wv.y + a0.z * wv.z + a0.w * wv.w;
                            giv[1][j] += a1.x * wv.x + a1.y * wv.y + a1.z * wv.z + a1.w * wv.w;
                        }
            }
        }

        // ---- epilogue: lane-local GRU pointwise, h_prev in regs ----
        #pragma unroll
        for (int rr = 0; rr < 2; rr++) {
            const int m = mq * 64 + wm * 16 + lr + rr * 8;
            float* orow = outs + ((size_t)t * BS + m) * HID;
            #pragma unroll
            for (int pp = 0; pp < 2; pp++) {
                const int hid = hidbase + pp * 8 + lc2;
                float h[2];
                #pragma unroll
                for (int e = 0; e < 2; e++) {
                    float rv = c[pp][2 * rr + e];
                    float zv = c[2 + pp][2 * rr + e];
                    float nv = c[4 + pp][2 * rr + e];
                    float rg = fast_sigmoid(rv + giv[rr][0 * 4 + pp * 2 + e]);
                    float zg = fast_sigmoid(zv + giv[rr][1 * 4 + pp * 2 + e]);
                    float ng = fast_tanh(giv[rr][2 * 4 + pp * 2 + e] + rg * (nv + bh[pp][e]));
                    h[e] = (1.0f - zg) * ng + zg * hpreg[rr][pp][e];
                    hpreg[rr][pp][e] = h[e];
                }
                *reinterpret_cast<float2*>(orow + hid) = make_float2(h[0], h[1]);
                if (t + 1 < NT) {
                    const int wbuf = (t + 1) & 1;
                    size_t d = (size_t)wbuf * BS * HID + (size_t)m * HID + hid;
                    unsigned short hi0, hi1, lo0, lo1;
                    split2(h[0], hi0, lo0);
                    split2(h[1], hi1, lo1);
                    *reinterpret_cast<uint32_t*>(g_hA_hi + d) = ((uint32_t)hi1 << 16) | hi0;
                    *reinterpret_cast<uint32_t*>(g_hA_lo + d) = ((uint32_t)lo1 << 16) | lo0;
                }
            }
        }

        // publish A-image writes before arriving at next step's barrier
        if (t + 1 < NT) {
            __threadfence();
            __syncthreads();
        }
    }
}

// ===========================================================================
// k_out (unchanged)
// ===========================================================================
__global__ void __launch_bounds__(256) k_out(const float* __restrict__ outs,
                                             const float* __restrict__ Wo,
                                             const float* __restrict__ bo,
                                             float* __restrict__ out) {
    __shared__ float As[32][33];
    __shared__ float Bs[32][64];
    const int tx = threadIdx.x, ty = threadIdx.y;
    const int tid = ty * 16 + tx;
    const int R0 = blockIdx.x * 32;
    float2 acc[2][2] = {};

    for (int k0 = 0; k0 < HID; k0 += 32) {
        #pragma unroll
        for (int i = tid; i < 32 * 32; i += 256) {
            int m = i >> 5, k = i & 31;
            As[k][m] = outs[(size_t)(R0 + m) * HID + k0 + k];
        }
        #pragma unroll
        for (int i = tid; i < 32 * 64; i += 256) {
            int k = i >> 6, n = i & 63;
            Bs[k][n] = Wo[(size_t)(k0 + k) * OUTD + n];
        }
        __syncthreads();
        #pragma unroll
        for (int k = 0; k < 32; k++) {
            float a0 = As[k][ty * 2 + 0], a1 = As[k][ty * 2 + 1];
            float2 A0 = make_float2(a0, a0), A1 = make_float2(a1, a1);
            const float2* bp = reinterpret_cast<const float2*>(&Bs[k][tx * 4]);
            float2 b0 = bp[0], b1 = bp[1];
            acc[0][0] = ffma2(A0, b0, acc[0][0]);
            acc[0][1] = ffma2(A0, b1, acc[0][1]);
            acc[1][0] = ffma2(A1, b0, acc[1][0]);
            acc[1][1] = ffma2(A1, b1, acc[1][1]);
        }
        __syncthreads();
    }

    #pragma unroll
    for (int r = 0; r < 2; r++) {
        int R = R0 + ty * 2 + r;
        int tt = R >> 8;
        int b  = R & (BS - 1);
        #pragma unroll
        for (int c = 0; c < 2; c++) {
            int n = tx * 4 + c * 2;
            out[((size_t)b * NT + tt) * OUTD + n]     = acc[r][c].x + bo[n];
            out[((size_t)b * NT + tt) * OUTD + n + 1] = acc[r][c].y + bo[n + 1];
        }
    }
}

extern "C" void kernel_launch(void* const* d_in, const int* in_sizes, int n_in,
                              void* d_out, int out_size) {
    const float* history = (const float*)d_in[0];
    const float* action  = (const float*)d_in[1];
    const float* W_in    = (const float*)d_in[2];
    const float* b_in    = (const float*)d_in[3];
    const float* Wi      = (const float*)d_in[4];
    const float* bi      = (const float*)d_in[5];
    const float* Wh      = (const float*)d_in[6];
    const float* bhn     = (const float*)d_in[7];
    const float* Wo      = (const float*)d_in[8];
    const float* bo      = (const float*)d_in[9];
    float* out = (float*)d_out;

    float *h0buf = nullptr, *outsbuf = nullptr;
    cudaGetSymbolAddress((void**)&h0buf, g_h0);
    cudaGetSymbolAddress((void**)&outsbuf, g_outs);

    const int smem_h0 = HSMF * 4;
    cudaFuncSetAttribute(k_h0v2, cudaFuncAttributeMaxDynamicSharedMemorySize, smem_h0);
    cudaFuncSetAttribute(k_steps_mma, cudaFuncAttributeMaxDynamicSharedMemorySize, SMEM_MMA);

    k_zero<<<1, 128>>>();
    k_h0v2<<<dim3(HID / 64, BS / 32), 512, smem_h0>>>(history, W_in, b_in, h0buf);
    k_packW<<<dim3(32, 16), 256>>>(Wh);
    k_cvtH0<<<BS, 256>>>(h0buf);

    k_steps_mma<<<dim3(32, 4), 256, SMEM_MMA>>>(h0buf, action, Wi, bi, bhn, outsbuf);

    k_out<<<dim3(NT * BS / 32), dim3(16, 16)>>>(outsbuf, Wo, bo, out);
}

// round 11
// speedup vs baseline: 1.5946x; 1.1262x over previous
#include <cuda_runtime.h>
#include <cuda_bf16.h>
#include <cstdint>
#include <cstddef>

#define BS   256
#define HID  1024
#define NT   100
#define ACT  32
#define KIN  8000
#define G3   3072
#define OUTD 64

// ---------------- device scratch (allocation-free rule) ----------------
__device__ float g_h0[BS * HID];
__device__ unsigned g_bars[4 * 32];                 // per-mq barrier counters

// h history as bf16 hi/lo images: [t][b][hid]  (A source AND k_out input)
__device__ __align__(16) unsigned short g_obf_hi[(size_t)NT * BS * HID]; // 52 MB
__device__ __align__(16) unsigned short g_obf_lo[(size_t)NT * BS * HID];
// h0 bf16 image
__device__ __align__(16) unsigned short g_h0b_hi[BS * HID];
__device__ __align__(16) unsigned short g_h0b_lo[BS * HID];
// Wh (B) packed bf16: [slice 32][k 1024][col 96], col = sub*48+gate*16+h16
__device__ __align__(16) unsigned short g_wBp_hi[32 * HID * 96]; // 6.3 MB
__device__ __align__(16) unsigned short g_wBp_lo[32 * HID * 96];
// Wo packed bf16: [k 1024][n 64]
__device__ __align__(16) unsigned short g_wo_hi[HID * OUTD];
__device__ __align__(16) unsigned short g_wo_lo[HID * OUTD];

// ---------------- helpers ----------------
__device__ __forceinline__ float2 ffma2(float2 a, float2 b, float2 c) {
    union U { float2 f; unsigned long long u; };
    U A, B, C, D;
    A.f = a; B.f = b; C.f = c;
    asm("fma.rn.f32x2 %0, %1, %2, %3;" : "=l"(D.u) : "l"(A.u), "l"(B.u), "l"(C.u));
    return D.f;
}
__device__ __forceinline__ float fast_sigmoid(float x) {
    return __fdividef(1.0f, 1.0f + __expf(-x));
}
__device__ __forceinline__ float fast_tanh(float x) {
    float e = __expf(2.0f * x);
    return 1.0f - __fdividef(2.0f, e + 1.0f);
}
__device__ __forceinline__ void split2(float x, unsigned short& h, unsigned short& l) {
    __nv_bfloat16 hb = __float2bfloat16(x);
    float hf = __bfloat162float(hb);
    __nv_bfloat16 lb = __float2bfloat16(x - hf);
    h = *reinterpret_cast<unsigned short*>(&hb);
    l = *reinterpret_cast<unsigned short*>(&lb);
}

#define CP4(dst, src)  asm volatile("cp.async.ca.shared.global [%0], [%1], 4;\n"  :: "r"(dst), "l"(src))
#define CP16(dst, src) asm volatile("cp.async.cg.shared.global [%0], [%1], 16;\n" :: "r"(dst), "l"(src))
#define CP_COMMIT()    asm volatile("cp.async.commit_group;\n")
#define CP_WAIT(n)     asm volatile("cp.async.wait_group %0;\n" :: "n"(n))

__device__ __forceinline__ uint32_t smem_u32(const void* p) {
    uint32_t a;
    asm("{ .reg .u64 t; cvta.to.shared.u64 t, %1; cvt.u32.u64 %0, t; }" : "=r"(a) : "l"(p));
    return a;
}
__device__ __forceinline__ void mma16816(float* c, const uint32_t* a, const uint32_t* b) {
    asm volatile("mma.sync.aligned.m16n8k16.row.col.f32.bf16.bf16.f32 "
        "{%0,%1,%2,%3}, {%4,%5,%6,%7}, {%8,%9}, {%0,%1,%2,%3};"
        : "+f"(c[0]), "+f"(c[1]), "+f"(c[2]), "+f"(c[3])
        : "r"(a[0]), "r"(a[1]), "r"(a[2]), "r"(a[3]), "r"(b[0]), "r"(b[1]));
}
#define LDSM4(r, addr)                                                          \
    asm volatile("ldmatrix.sync.aligned.m8n8.x4.shared.b16 {%0,%1,%2,%3}, [%4];"\
        : "=r"((r)[0]), "=r"((r)[1]), "=r"((r)[2]), "=r"((r)[3]) : "r"(addr))
#define LDSM4T(r, addr)                                                         \
    asm volatile("ldmatrix.sync.aligned.m8n8.x4.trans.shared.b16 {%0,%1,%2,%3}, [%4];" \
        : "=r"((r)[0]), "=r"((r)[1]), "=r"((r)[2]), "=r"((r)[3]) : "r"(addr))

// ===========================================================================
__global__ void k_zero() {
    if (threadIdx.x < 4 * 32) g_bars[threadIdx.x] = 0u;
}

// ===========================================================================
// k_packW: Wh[k][3072] -> packed [32][1024][96] bf16 hi/lo. grid (32,16), 256.
// ===========================================================================
__global__ void __launch_bounds__(256) k_packW(const float* __restrict__ Wh) {
    const int s = blockIdx.x, kg = blockIdx.y;
    for (int i = threadIdx.x; i < 64 * 96; i += 256) {
        int k = kg * 64 + i / 96;
        int c = i % 96;
        int sub = c / 48, rem = c % 48;
        int gate = rem / 16, h16 = rem % 16;
        float x = Wh[(size_t)k * G3 + gate * HID + s * 32 + sub * 16 + h16];
        size_t dst = ((size_t)s * HID + k) * 96 + c;
        split2(x, g_wBp_hi[dst], g_wBp_lo[dst]);
    }
}

// ===========================================================================
// k_packWo: Wo[1024][64] -> bf16 hi/lo. grid 256, 256 thr.
// ===========================================================================
__global__ void __launch_bounds__(256) k_packWo(const float* __restrict__ Wo) {
    int i = blockIdx.x * 256 + threadIdx.x;   // 65536 total
    float x = Wo[i];
    split2(x, g_wo_hi[i], g_wo_lo[i]);
}

// ===========================================================================
// k_cvtH0: h0 fp32 -> bf16 hi/lo image. grid (256), 256 thr.
// ===========================================================================
__global__ void __launch_bounds__(256) k_cvtH0(const float* __restrict__ H0) {
    const int m = blockIdx.x;
    for (int k = threadIdx.x * 4; k < HID; k += 1024) {
        float4 v = *reinterpret_cast<const float4*>(H0 + (size_t)m * HID + k);
        size_t d = (size_t)m * HID + k;
        split2(v.x, g_h0b_hi[d],     g_h0b_lo[d]);
        split2(v.y, g_h0b_hi[d + 1], g_h0b_lo[d + 1]);
        split2(v.z, g_h0b_hi[d + 2], g_h0b_lo[d + 2]);
        split2(v.w, g_h0b_hi[d + 3], g_h0b_lo[d + 3]);
    }
}

// ===========================================================================
// k_h0v2 (unchanged, race-fixed)
// ===========================================================================
#define HBK   16
#define HKPER 2000
#define HNT   125
#define HASZ  (HBK * 36)
#define HBSZ  (HBK * 64)
#define HSTG  (HASZ + HBSZ)
#define HGRP  (3 * HSTG)
#define HSMF  (4 * HGRP)

__global__ void __launch_bounds__(512) k_h0v2(const float* __restrict__ X,
                                              const float* __restrict__ W,
                                              const float* __restrict__ bias,
                                              float* __restrict__ H0) {
    extern __shared__ float sm[];
    const int tid  = threadIdx.x;
    const int g    = tid >> 7;
    const int wtid = tid & 127;
    const int tx   = wtid & 15;
    const int ty   = wtid >> 4;
    const int m0 = blockIdx.y * 32, n0 = blockIdx.x * 64;
    float* gb = sm + g * HGRP;

    float b4x = bias[n0 + (tid & 15) * 4 + 0];
    float b4y = bias[n0 + (tid & 15) * 4 + 1];
    float b4z = bias[n0 + (tid & 15) * 4 + 2];
    float b4w = bias[n0 + (tid & 15) * 4 + 3];

    float2 acc[4][2] = {};

    auto load_tile = [&](int stage, int tl) {
        const int kb = g * HKPER + tl * HBK;
        float* dstA = gb + stage * HSTG;
        const float* asrc = X + (size_t)m0 * KIN + kb;
        #pragma unroll
        for (int i = wtid; i < HBK * 32; i += 128) {
            int k = i & 15, m = i >> 4;
            uint32_t d = (uint32_t)__cvta_generic_to_shared(dstA + k * 36 + m);
            CP4(d, asrc + (size_t)m * KIN + k);
        }
        const float* bsrc = W + (size_t)kb * HID + n0;
        float* dstB = dstA + HASZ;
        #pragma unroll
        for (int i = wtid; i < HBK * 16; i += 128) {
            int k = i >> 4, n4 = i & 15;
            uint32_t d = (uint32_t)__cvta_generic_to_shared(dstB + k * 64 + n4 * 4);
            CP16(d, bsrc + (size_t)k * HID + n4 * 4);
        }
    };

    auto compute = [&](int stage) {
        const float* As_ = gb + stage * HSTG;
        const float* B_  = As_ + HASZ;
        #pragma unroll
        for (int k = 0; k < HBK; k++) {
            float4 a4 = *reinterpret_cast<const float4*>(As_ + k * 36 + ty * 4);
            float2 A0 = make_float2(a4.x, a4.x), A1 = make_float2(a4.y, a4.y);
            float2 A2 = make_float2(a4.z, a4.z), A3 = make_float2(a4.w, a4.w);
            float4 b = *reinterpret_cast<const float4*>(B_ + k * 64 + tx * 4);
            float2 b0 = make_float2(b.x, b.y), b1 = make_float2(b.z, b.w);
            acc[0][0] = ffma2(A0, b0, acc[0][0]); acc[0][1] = ffma2(A0, b1, acc[0][1]);
            acc[1][0] = ffma2(A1, b0, acc[1][0]); acc[1][1] = ffma2(A1, b1, acc[1][1]);
            acc[2][0] = ffma2(A2, b0, acc[2][0]); acc[2][1] = ffma2(A2, b1, acc[2][1]);
            acc[3][0] = ffma2(A3, b0, acc[3][0]); acc[3][1] = ffma2(A3, b1, acc[3][1]);
        }
    };

    load_tile(0, 0); CP_COMMIT();
    load_tile(1, 1); CP_COMMIT();
    int cs = 0, ls = 2;
    for (int tl = 0; tl < HNT; tl++) {
        CP_WAIT(1);
        __syncthreads();
        if (tl + 2 < HNT) load_tile(ls, tl + 2);
        CP_COMMIT();
        compute(cs);
        cs = (cs == 2) ? 0 : cs + 1;
        ls = (ls == 2) ? 0 : ls + 1;
    }
    __syncthreads();

    #pragma unroll
    for (int r = 0; r < 4; r++) {
        float4 v = make_float4(acc[r][0].x, acc[r][0].y, acc[r][1].x, acc[r][1].y);
        *reinterpret_cast<float4*>(gb + (ty * 4 + r) * 64 + tx * 4) = v;
    }
    __syncthreads();

    {
        int row = tid >> 4, c0 = (tid & 15) * 4;
        float s0 = 0.f, s1 = 0.f, s2 = 0.f, s3 = 0.f;
        #pragma unroll
        for (int gg = 0; gg < 4; gg++) {
            float4 p = *reinterpret_cast<const float4*>(sm + gg * HGRP + row * 64 + c0);
            s0 += p.x; s1 += p.y; s2 += p.z; s3 += p.w;
        }
        s0 += b4x; s1 += b4y; s2 += b4z; s3 += b4w;
        float4 o = make_float4(s0 > 0.f ? s0 : 0.f, s1 > 0.f ? s1 : 0.f,
                               s2 > 0.f ? s2 : 0.f, s3 > 0.f ? s3 : 0.f);
        *reinterpret_cast<float4*>(H0 + (size_t)(m0 + row) * HID + n0 + c0) = o;
    }
}

// ===========================================================================
// k_steps_mma v5: as R10 (BK=64, 16 chunks) but the h image is single-copy
// [t][b][hid] bf16 hi/lo — serves as next-step A source AND k_out input.
// fp32 outs writes removed (epilogue stores halved).
// ===========================================================================
#define OFF_AH 0
#define OFF_AL 9216
#define OFF_BH 18432
#define OFF_BL 31744
#define STG_B  45056
#define APITCH_B 144
#define BPITCH_B 208
#define SM_WI  (3 * STG_B)
#define SM_AS  (SM_WI + 96 * 36 * 4)
#define SMEM_MMA (SM_AS + 2 * 64 * 36 * 4)  // 167424 B

__global__ void __launch_bounds__(256, 1) k_steps_mma(const float* __restrict__ h0,
                                                      const float* __restrict__ action,
                                                      const float* __restrict__ Wi,
                                                      const float* __restrict__ bi,
                                                      const float* __restrict__ bhn) {
    extern __shared__ char smem[];
    const uint32_t sb = smem_u32(smem);
    float* wi_s = reinterpret_cast<float*>(smem + SM_WI);
    float* a_s  = reinterpret_cast<float*>(smem + SM_AS);

    const int tid = threadIdx.x;
    const int w = tid >> 5, l = tid & 31;
    const int s = blockIdx.x;
    const int mq = blockIdx.y;
    const int wm = w & 3;
    const int wn = w >> 2;
    const int lr = l >> 2;
    const int lc2 = (l & 3) * 2;

    const int a_row  = wm * 16 + (l & 15);
    const int a_koff = (l >> 4) * 8;
    const int b_krow = l & 15;
    const int b_noff = wn * 48 + (l >> 4) * 8;

    const int hidbase = s * 32 + wn * 16;

    float bh[2][2];
    #pragma unroll
    for (int pp = 0; pp < 2; pp++) {
        float2 v = *reinterpret_cast<const float2*>(bhn + hidbase + pp * 8 + lc2);
        bh[pp][0] = v.x; bh[pp][1] = v.y;
    }
    float biv[3][2][2];
    #pragma unroll
    for (int gate = 0; gate < 3; gate++)
        #pragma unroll
        for (int pp = 0; pp < 2; pp++) {
            float2 v = *reinterpret_cast<const float2*>(bi + gate * HID + hidbase + pp * 8 + lc2);
            biv[gate][pp][0] = v.x; biv[gate][pp][1] = v.y;
        }
    float hpreg[2][2][2];
    #pragma unroll
    for (int rr = 0; rr < 2; rr++) {
        const int m = mq * 64 + wm * 16 + lr + rr * 8;
        #pragma unroll
        for (int pp = 0; pp < 2; pp++) {
            float2 v = *reinterpret_cast<const float2*>(h0 + (size_t)m * HID + hidbase + pp * 8 + lc2);
            hpreg[rr][pp][0] = v.x; hpreg[rr][pp][1] = v.y;
        }
    }

    for (int i = tid; i < 96 * 32; i += 256) {
        int col = i >> 5, k = i & 31;
        int gate = col >> 5, cl = col & 31;
        wi_s[col * 36 + k] = Wi[(size_t)k * G3 + gate * HID + s * 32 + cl];
    }
    __syncthreads();

    const char* srcBH = (const char*)(g_wBp_hi + (size_t)s * HID * 96);
    const char* srcBL = (const char*)(g_wBp_lo + (size_t)s * HID * 96);

    auto load_B = [&](int ch, int st) {
        uint32_t base = sb + st * STG_B;
        #pragma unroll
        for (int i = tid; i < 768; i += 256) {
            int r = i / 12, sg = i % 12;
            const char* sp = srcBH + ((size_t)(ch * 64 + r)) * 192 + sg * 16;
            CP16(base + OFF_BH + r * BPITCH_B + sg * 16, sp);
            const char* sp2 = srcBL + ((size_t)(ch * 64 + r)) * 192 + sg * 16;
            CP16(base + OFF_BL + r * BPITCH_B + sg * 16, sp2);
        }
    };
    auto load_act = [&](int tt) {
        uint32_t ab = sb + SM_AS + (tt & 1) * (64 * 36 * 4);
        #pragma unroll
        for (int i = tid; i < 512; i += 256) {
            int row = i >> 3, seg = i & 7;
            const float* src = action + ((size_t)(mq * 64 + row) * NT + tt) * ACT + seg * 4;
            CP16(ab + row * 144 + seg * 16, src);
        }
    };

    load_B(0, 0); load_act(0); CP_COMMIT();
    load_B(1, 1); CP_COMMIT();

    #pragma unroll 1
    for (int t = 0; t < NT; t++) {
        const unsigned short* hsH = (t == 0) ? g_h0b_hi : g_obf_hi + (size_t)(t - 1) * BS * HID;
        const unsigned short* hsL = (t == 0) ? g_h0b_lo : g_obf_lo + (size_t)(t - 1) * BS * HID;
        const char* srcAH = (const char*)(hsH + (size_t)mq * 64 * HID);
        const char* srcAL = (const char*)(hsL + (size_t)mq * 64 * HID);

        auto load_A = [&](int ch, int st) {
            uint32_t base = sb + st * STG_B;
            #pragma unroll
            for (int i = tid; i < 512; i += 256) {
                int row = i >> 3, seg = i & 7;
                const char* sa = srcAH + (size_t)row * (HID * 2) + ch * 128 + seg * 16;
                CP16(base + OFF_AH + row * APITCH_B + seg * 16, sa);
                const char* sa2 = srcAL + (size_t)row * (HID * 2) + ch * 128 + seg * 16;
                CP16(base + OFF_AL + row * APITCH_B + seg * 16, sa2);
            }
        };

        if (t > 0) {
            if (tid == 0) {
                unsigned* ctr = &g_bars[mq * 32];
                const unsigned target = 32u * (unsigned)t;
                atomicAdd(ctr, 1u);
                unsigned v;
                do {
                    asm volatile("ld.volatile.global.u32 %0, [%1];" : "=r"(v) : "l"(ctr));
                } while (v < target);
            }
            __syncthreads();
            __threadfence();
        }

        load_A(0, 0); CP_COMMIT();
        load_A(1, 1); CP_COMMIT();

        float c[6][4] = {};

        auto compute = [&](int st) {
            uint32_t base = sb + st * STG_B;
            #pragma unroll
            for (int kk = 0; kk < 4; kk++) {
                const int k0 = kk * 16;
                uint32_t aH[4], aL[4];
                uint32_t adA = base + OFF_AH + a_row * APITCH_B + (k0 + a_koff) * 2;
                LDSM4(aH, adA);
                LDSM4(aL, adA + (OFF_AL - OFF_AH));
                uint32_t bH[6][2], bL[6][2];
                #pragma unroll
                for (int g2 = 0; g2 < 3; g2++) {
                    uint32_t adB = base + OFF_BH + (k0 + b_krow) * BPITCH_B + (b_noff + g2 * 16) * 2;
                    uint32_t r4[4];
                    LDSM4T(r4, adB);
                    bH[g2 * 2][0] = r4[0]; bH[g2 * 2][1] = r4[1];
                    bH[g2 * 2 + 1][0] = r4[2]; bH[g2 * 2 + 1][1] = r4[3];
                    LDSM4T(r4, adB + (OFF_BL - OFF_BH));
                    bL[g2 * 2][0] = r4[0]; bL[g2 * 2][1] = r4[1];
                    bL[g2 * 2 + 1][0] = r4[2]; bL[g2 * 2 + 1][1] = r4[3];
                }
                #pragma unroll
                for (int g = 0; g < 6; g++) {
                    mma16816(c[g], aH, bH[g]);
                    mma16816(c[g], aH, bL[g]);
                    mma16816(c[g], aL, bH[g]);
                }
            }
        };

        #pragma unroll 1
        for (int ch = 0; ch < 16; ch++) {
            CP_WAIT(1);
            __syncthreads();
            if (ch + 2 < 16) {
                int st2 = (ch + 2) % 3;
                load_A(ch + 2, st2);
                load_B(ch + 2, st2);
            }
            CP_COMMIT();
            compute(ch % 3);
        }
        __syncthreads();

        if (t + 1 < NT) {
            load_B(0, 0); load_act(t + 1); CP_COMMIT();
            load_B(1, 1); CP_COMMIT();
        }

        // ---- fused input GEMM ----
        float giv[2][12];
        #pragma unroll
        for (int rr = 0; rr < 2; rr++)
            #pragma unroll
            for (int gate = 0; gate < 3; gate++)
                #pragma unroll
                for (int pp = 0; pp < 2; pp++) {
                    giv[rr][gate * 4 + pp * 2 + 0] = biv[gate][pp][0];
                    giv[rr][gate * 4 + pp * 2 + 1] = biv[gate][pp][1];
                }
        {
            const float* ab = a_s + (t & 1) * (64 * 36);
            const float* r0 = ab + (wm * 16 + lr) * 36;
            const float* r1 = r0 + 8 * 36;
            #pragma unroll
            for (int k4 = 0; k4 < 8; k4++) {
                float4 a0 = *reinterpret_cast<const float4*>(r0 + k4 * 4);
                float4 a1 = *reinterpret_cast<const float4*>(r1 + k4 * 4);
                #pragma unroll
                for (int gate = 0; gate < 3; gate++)
                    #pragma unroll
                    for (int pp = 0; pp < 2; pp++)
                        #pragma unroll
                        for (int e = 0; e < 2; e++) {
                            int col = gate * 32 + wn * 16 + pp * 8 + lc2 + e;
                            float4 wv = *reinterpret_cast<const float4*>(wi_s + col * 36 + k4 * 4);
                            int j = gate * 4 + pp * 2 + e;
                            giv[0][j] += a0.x * wv.x + a0.y * wv.y + a0.z * wv.z + a0.w * wv.w;
                            giv[1][j] += a1.x * wv.x + a1.y * wv.y + a1.z * wv.z + a1.w * wv.w;
                        }
            }
        }

        // ---- epilogue: gates+blend; single bf16 hi/lo store ----
        #pragma unroll
        for (int rr = 0; rr < 2; rr++) {
            const int m = mq * 64 + wm * 16 + lr + rr * 8;
            #pragma unroll
            for (int pp = 0; pp < 2; pp++) {
                const int hid = hidbase + pp * 8 + lc2;
                float h[2];
                #pragma unroll
                for (int e = 0; e < 2; e++) {
                    float rv = c[pp][2 * rr + e];
                    float zv = c[2 + pp][2 * rr + e];
                    float nv = c[4 + pp][2 * rr + e];
                    float rg = fast_sigmoid(rv + giv[rr][0 * 4 + pp * 2 + e]);
                    float zg = fast_sigmoid(zv + giv[rr][1 * 4 + pp * 2 + e]);
                    float ng = fast_tanh(giv[rr][2 * 4 + pp * 2 + e] + rg * (nv + bh[pp][e]));
                    h[e] = (1.0f - zg) * ng + zg * hpreg[rr][pp][e];
                    hpreg[rr][pp][e] = h[e];
                }
                size_t d = ((size_t)t * BS + m) * HID + hid;
                unsigned short hi0, hi1, lo0, lo1;
                split2(h[0], hi0, lo0);
                split2(h[1], hi1, lo1);
                *reinterpret_cast<uint32_t*>(g_obf_hi + d) = ((uint32_t)hi1 << 16) | hi0;
                *reinterpret_cast<uint32_t*>(g_obf_lo + d) = ((uint32_t)lo1 << 16) | lo0;
            }
        }

        if (t + 1 < NT) {
            __threadfence();
            __syncthreads();
        }
    }
}

// ===========================================================================
// k_out_mma: out[b][t][:] = outs_bf16 @ Wo_bf16 + bo  (HMMA, 3-product hi/lo)
// M=25600 (R = t*BS+b), N=64, K=1024. grid 400, 256 thr (8 warps: 4m x 2n).
// ===========================================================================
#define O_AH 0
#define O_AL 9216
#define O_BH 18432
#define O_BL 27648
#define OSTG 36864
#define O_PITCH 144
#define SMEM_OUT (3 * OSTG)     // 110592 B

__global__ void __launch_bounds__(256) k_out_mma(const float* __restrict__ bo,
                                                 float* __restrict__ out) {
    extern __shared__ char smem[];
    const uint32_t sb = smem_u32(smem);
    const int tid = threadIdx.x;
    const int w = tid >> 5, l = tid & 31;
    const int wm = w & 3;              // m group (16 rows)
    const int wn = w >> 2;             // n half (32 cols)
    const int lr = l >> 2;
    const int lc2 = (l & 3) * 2;
    const int R0 = blockIdx.x * 64;

    const int a_row  = wm * 16 + (l & 15);
    const int a_koff = (l >> 4) * 8;
    const int b_krow = l & 15;
    const int b_lhalf = (l >> 4) * 8;

    const char* srcAH = (const char*)(g_obf_hi + (size_t)R0 * HID);
    const char* srcAL = (const char*)(g_obf_lo + (size_t)R0 * HID);

    auto load = [&](int ch, int st) {
        uint32_t base = sb + st * OSTG;
        #pragma unroll
        for (int i = tid; i < 512; i += 256) {
            int r = i >> 3, sg = i & 7;
            CP16(base + O_AH + r * O_PITCH + sg * 16,
                 srcAH + (size_t)r * (HID * 2) + ch * 128 + sg * 16);
            CP16(base + O_AL + r * O_PITCH + sg * 16,
                 srcAL + (size_t)r * (HID * 2) + ch * 128 + sg * 16);
        }
        #pragma unroll
        for (int i = tid; i < 512; i += 256) {
            int r = i >> 3, sg = i & 7;
            CP16(base + O_BH + r * O_PITCH + sg * 16,
                 (const char*)g_wo_hi + ((size_t)(ch * 64 + r) * OUTD) * 2 + sg * 16);
            CP16(base + O_BL + r * O_PITCH + sg * 16,
                 (const char*)g_wo_lo + ((size_t)(ch * 64 + r) * OUTD) * 2 + sg * 16);
        }
    };

    load(0, 0); CP_COMMIT();
    load(1, 1); CP_COMMIT();

    float c[4][4] = {};

    auto compute = [&](int st) {
        uint32_t base = sb + st * OSTG;
        #pragma unroll
        for (int kk = 0; kk < 4; kk++) {
            const int k0 = kk * 16;
            uint32_t aH[4], aL[4];
            uint32_t adA = base + O_AH + a_row * O_PITCH + (k0 + a_koff) * 2;
            LDSM4(aH, adA);
            LDSM4(aL, adA + (O_AL - O_AH));
            uint32_t bH[4][2], bL[4][2];
            #pragma unroll
            for (int n16 = 0; n16 < 2; n16++) {
                uint32_t adB = base + O_BH + (k0 + b_krow) * O_PITCH
                             + (wn * 32 + n16 * 16 + b_lhalf) * 2;
                uint32_t r4[4];
                LDSM4T(r4, adB);
                bH[n16 * 2][0] = r4[0]; bH[n16 * 2][1] = r4[1];
                bH[n16 * 2 + 1][0] = r4[2]; bH[n16 * 2 + 1][1] = r4[3];
                LDSM4T(r4, adB + (O_BL - O_BH));
                bL[n16 * 2][0] = r4[0]; bL[n16 * 2][1] = r4[1];
                bL[n16 * 2 + 1][0] = r4[2]; bL[n16 * 2 + 1][1] = r4[3];
            }
            #pragma unroll
            for (int g = 0; g < 4; g++) {
                mma16816(c[g], aH, bH[g]);
                mma16816(c[g], aH, bL[g]);
                mma16816(c[g], aL, bH[g]);
            }
        }
    };

    #pragma unroll 1
    for (int ch = 0; ch < 16; ch++) {
        CP_WAIT(1);
        __syncthreads();
        if (ch + 2 < 16) load(ch + 2, (ch + 2) % 3);
        CP_COMMIT();
        compute(ch % 3);
    }

    // epilogue: add bo, permute (R = t*BS + b) -> out[b][t][:]
    #pragma unroll
    for (int g = 0; g < 4; g++) {
        const int col = wn * 32 + g * 8 + lc2;
        float2 bov = *reinterpret_cast<const float2*>(bo + col);
        #pragma unroll
        for (int rr = 0; rr < 2; rr++) {
            int R = R0 + wm * 16 + lr + rr * 8;
            int tt = R >> 8;
            int b  = R & (BS - 1);
            float2 o = make_float2(c[g][2 * rr] + bov.x, c[g][2 * rr + 1] + bov.y);
            *reinterpret_cast<float2*>(out + ((size_t)b * NT + tt) * OUTD + col) = o;
        }
    }
}

extern "C" void kernel_launch(void* const* d_in, const int* in_sizes, int n_in,
                              void* d_out, int out_size) {
    const float* history = (const float*)d_in[0];
    const float* action  = (const float*)d_in[1];
    const float* W_in    = (const float*)d_in[2];
    const float* b_in    = (const float*)d_in[3];
    const float* Wi      = (const float*)d_in[4];
    const float* bi      = (const float*)d_in[5];
    const float* Wh      = (const float*)d_in[6];
    const float* bhn     = (const float*)d_in[7];
    const float* Wo      = (const float*)d_in[8];
    const float* bo      = (const float*)d_in[9];
    float* out = (float*)d_out;

    float* h0buf = nullptr;
    cudaGetSymbolAddress((void**)&h0buf, g_h0);

    const int smem_h0 = HSMF * 4;
    cudaFuncSetAttribute(k_h0v2, cudaFuncAttributeMaxDynamicSharedMemorySize, smem_h0);
    cudaFuncSetAttribute(k_steps_mma, cudaFuncAttributeMaxDynamicSharedMemorySize, SMEM_MMA);
    cudaFuncSetAttribute(k_out_mma, cudaFuncAttributeMaxDynamicSharedMemorySize, SMEM_OUT);

    k_zero<<<1, 128>>>();
    k_h0v2<<<dim3(HID / 64, BS / 32), 512, smem_h0>>>(history, W_in, b_in, h0buf);
    k_packW<<<dim3(32, 16), 256>>>(Wh);
    k_packWo<<<HID * OUTD / 256, 256>>>(Wo);
    k_cvtH0<<<BS, 256>>>(h0buf);

    k_steps_mma<<<dim3(32, 4), 256, SMEM_MMA>>>(h0buf, action, Wi, bi, bhn);

    k_out_mma<<<NT * BS / 64, 256, SMEM_OUT>>>(bo, out);
}

// round 12
// speedup vs baseline: 1.7099x; 1.0724x over previous
#include <cuda_runtime.h>
#include <cuda_bf16.h>
#include <cstdint>
#include <cstddef>

#define BS   256
#define HID  1024
#define NT   100
#define ACT  32
#define KIN  8000
#define G3   3072
#define OUTD 64

// ---------------- device scratch (allocation-free rule) ----------------
__device__ float g_h0[BS * HID];
__device__ unsigned g_bars[4 * 32];

// h history bf16 hi/lo: [t][b][hid] (A source AND k_out input)
__device__ __align__(16) unsigned short g_obf_hi[(size_t)NT * BS * HID];
__device__ __align__(16) unsigned short g_obf_lo[(size_t)NT * BS * HID];
// h0 bf16 image
__device__ __align__(16) unsigned short g_h0b_hi[BS * HID];
__device__ __align__(16) unsigned short g_h0b_lo[BS * HID];
// Wh packed bf16: [slice 32][k 1024][col 96], col = sub*48+gate*16+h16
__device__ __align__(16) unsigned short g_wBp_hi[32 * HID * 96];
__device__ __align__(16) unsigned short g_wBp_lo[32 * HID * 96];
// Wo packed bf16: [k 1024][n 64]
__device__ __align__(16) unsigned short g_wo_hi[HID * OUTD];
__device__ __align__(16) unsigned short g_wo_lo[HID * OUTD];
// W_in packed bf16: [k 8000][n 1024]
__device__ __align__(16) unsigned short g_win_hi[(size_t)KIN * HID];  // 16 MB
__device__ __align__(16) unsigned short g_win_lo[(size_t)KIN * HID];
// X (history flattened) bf16: [m 256][k 8000]
__device__ __align__(16) unsigned short g_x_hi[BS * KIN];             // 4 MB
__device__ __align__(16) unsigned short g_x_lo[BS * KIN];

// ---------------- helpers ----------------
__device__ __forceinline__ float fast_sigmoid(float x) {
    return __fdividef(1.0f, 1.0f + __expf(-x));
}
__device__ __forceinline__ float fast_tanh(float x) {
    float e = __expf(2.0f * x);
    return 1.0f - __fdividef(2.0f, e + 1.0f);
}
__device__ __forceinline__ void split2(float x, unsigned short& h, unsigned short& l) {
    __nv_bfloat16 hb = __float2bfloat16(x);
    float hf = __bfloat162float(hb);
    __nv_bfloat16 lb = __float2bfloat16(x - hf);
    h = *reinterpret_cast<unsigned short*>(&hb);
    l = *reinterpret_cast<unsigned short*>(&lb);
}

#define CP16(dst, src) asm volatile("cp.async.cg.shared.global [%0], [%1], 16;\n" :: "r"(dst), "l"(src))
#define CP_COMMIT()    asm volatile("cp.async.commit_group;\n")
#define CP_WAIT(n)     asm volatile("cp.async.wait_group %0;\n" :: "n"(n))

__device__ __forceinline__ uint32_t smem_u32(const void* p) {
    uint32_t a;
    asm("{ .reg .u64 t; cvta.to.shared.u64 t, %1; cvt.u32.u64 %0, t; }" : "=r"(a) : "l"(p));
    return a;
}
__device__ __forceinline__ void mma16816(float* c, const uint32_t* a, const uint32_t* b) {
    asm volatile("mma.sync.aligned.m16n8k16.row.col.f32.bf16.bf16.f32 "
        "{%0,%1,%2,%3}, {%4,%5,%6,%7}, {%8,%9}, {%0,%1,%2,%3};"
        : "+f"(c[0]), "+f"(c[1]), "+f"(c[2]), "+f"(c[3])
        : "r"(a[0]), "r"(a[1]), "r"(a[2]), "r"(a[3]), "r"(b[0]), "r"(b[1]));
}
#define LDSM4(r, addr)                                                          \
    asm volatile("ldmatrix.sync.aligned.m8n8.x4.shared.b16 {%0,%1,%2,%3}, [%4];"\
        : "=r"((r)[0]), "=r"((r)[1]), "=r"((r)[2]), "=r"((r)[3]) : "r"(addr))
#define LDSM4T(r, addr)                                                         \
    asm volatile("ldmatrix.sync.aligned.m8n8.x4.trans.shared.b16 {%0,%1,%2,%3}, [%4];" \
        : "=r"((r)[0]), "=r"((r)[1]), "=r"((r)[2]), "=r"((r)[3]) : "r"(addr))

// ===========================================================================
__global__ void k_zero() {
    if (threadIdx.x < 4 * 32) g_bars[threadIdx.x] = 0u;
}

// ===========================================================================
// k_packW: Wh -> [32][1024][96] bf16 hi/lo. grid (32,16), 256 thr.
// ===========================================================================
__global__ void __launch_bounds__(256) k_packW(const float* __restrict__ Wh) {
    const int s = blockIdx.x, kg = blockIdx.y;
    for (int i = threadIdx.x; i < 64 * 96; i += 256) {
        int k = kg * 64 + i / 96;
        int c = i % 96;
        int sub = c / 48, rem = c % 48;
        int gate = rem / 16, h16 = rem % 16;
        float x = Wh[(size_t)k * G3 + gate * HID + s * 32 + sub * 16 + h16];
        size_t dst = ((size_t)s * HID + k) * 96 + c;
        split2(x, g_wBp_hi[dst], g_wBp_lo[dst]);
    }
}

// ===========================================================================
// k_packWo / k_packWin / k_cvtX : simple elementwise splits
// ===========================================================================
__global__ void __launch_bounds__(256) k_packWo(const float* __restrict__ Wo) {
    int i = blockIdx.x * 256 + threadIdx.x;
    split2(Wo[i], g_wo_hi[i], g_wo_lo[i]);
}
__global__ void __launch_bounds__(256) k_packWin(const float* __restrict__ Win) {
    size_t i = (size_t)blockIdx.x * 256 + threadIdx.x;
    split2(Win[i], g_win_hi[i], g_win_lo[i]);
}
__global__ void __launch_bounds__(256) k_cvtX(const float* __restrict__ X) {
    size_t i = (size_t)blockIdx.x * 256 + threadIdx.x;
    split2(X[i], g_x_hi[i], g_x_lo[i]);
}

// ===========================================================================
// k_h0_mma: h0 = relu(X_bf16 @ Win_bf16 + b_in)   (HMMA 3-product hi/lo)
// M=256, N=1024, K=8000. grid (16 ntile, 8 mtile) = 128 CTAs, tile 32x64.
// 256 thr = 8 warps: wm2 x wn4 (warp tile 16x16). Writes fp32 h0 + bf16 image.
// ===========================================================================
#define H_AH 0
#define H_AL 4608
#define H_BH 9216
#define H_BL 18432
#define HSTG2 27648
#define SMEM_H0 (3 * HSTG2)     // 82944 B
#define H_NCH 125               // 8000 / 64

__global__ void __launch_bounds__(256) k_h0_mma(const float* __restrict__ b_in,
                                                float* __restrict__ H0) {
    extern __shared__ char smem[];
    const uint32_t sb = smem_u32(smem);
    const int tid = threadIdx.x;
    const int w = tid >> 5, l = tid & 31;
    const int wm = w & 1;              // 16 rows
    const int wn = w >> 1;             // 16 cols
    const int lr = l >> 2;
    const int lc2 = (l & 3) * 2;
    const int m0 = blockIdx.y * 32, n0 = blockIdx.x * 64;

    const int a_row  = wm * 16 + (l & 15);
    const int a_koff = (l >> 4) * 8;
    const int b_krow = l & 15;
    const int b_lhalf = (l >> 4) * 8;

    const char* srcAH = (const char*)(g_x_hi + (size_t)m0 * KIN);
    const char* srcAL = (const char*)(g_x_lo + (size_t)m0 * KIN);

    auto load = [&](int ch, int st) {
        uint32_t base = sb + st * HSTG2;
        {   // A: 32 rows x 8 segs, hi+lo (1 pair per thread)
            int r = tid >> 3, sg = tid & 7;
            CP16(base + H_AH + r * 144 + sg * 16,
                 srcAH + (size_t)r * (KIN * 2) + ch * 128 + sg * 16);
            CP16(base + H_AL + r * 144 + sg * 16,
                 srcAL + (size_t)r * (KIN * 2) + ch * 128 + sg * 16);
        }
        #pragma unroll
        for (int i = tid; i < 512; i += 256) {   // B: 64 rows x 8 segs
            int r = i >> 3, sg = i & 7;
            CP16(base + H_BH + r * 144 + sg * 16,
                 (const char*)g_win_hi + ((size_t)(ch * 64 + r) * HID + n0) * 2 + sg * 16);
            CP16(base + H_BL + r * 144 + sg * 16,
                 (const char*)g_win_lo + ((size_t)(ch * 64 + r) * HID + n0) * 2 + sg * 16);
        }
    };

    load(0, 0); CP_COMMIT();
    load(1, 1); CP_COMMIT();

    float c[2][4] = {};

    auto compute = [&](int st) {
        uint32_t base = sb + st * HSTG2;
        #pragma unroll
        for (int kk = 0; kk < 4; kk++) {
            const int k0 = kk * 16;
            uint32_t aH[4], aL[4];
            uint32_t adA = base + H_AH + a_row * 144 + (k0 + a_koff) * 2;
            LDSM4(aH, adA);
            LDSM4(aL, adA + (H_AL - H_AH));
            uint32_t bH[2][2], bL[2][2];
            uint32_t adB = base + H_BH + (k0 + b_krow) * 144 + (wn * 16 + b_lhalf) * 2;
            uint32_t r4[4];
            LDSM4T(r4, adB);
            bH[0][0] = r4[0]; bH[0][1] = r4[1]; bH[1][0] = r4[2]; bH[1][1] = r4[3];
            LDSM4T(r4, adB + (H_BL - H_BH));
            bL[0][0] = r4[0]; bL[0][1] = r4[1]; bL[1][0] = r4[2]; bL[1][1] = r4[3];
            #pragma unroll
            for (int g = 0; g < 2; g++) {
                mma16816(c[g], aH, bH[g]);
                mma16816(c[g], aH, bL[g]);
                mma16816(c[g], aL, bH[g]);
            }
        }
    };

    #pragma unroll 1
    for (int ch = 0; ch < H_NCH; ch++) {
        CP_WAIT(1);
        __syncthreads();
        compute(ch % 3);
        if (ch + 2 < H_NCH) load(ch + 2, (ch + 2) % 3);
        CP_COMMIT();
    }

    // epilogue: relu + bias, write fp32 h0 + bf16 hi/lo image
    #pragma unroll
    for (int g = 0; g < 2; g++) {
        const int col = n0 + wn * 16 + g * 8 + lc2;
        float2 bv = *reinterpret_cast<const float2*>(b_in + col);
        #pragma unroll
        for (int rr = 0; rr < 2; rr++) {
            const int m = m0 + wm * 16 + lr + rr * 8;
            float v0 = c[g][2 * rr]     + bv.x;
            float v1 = c[g][2 * rr + 1] + bv.y;
            v0 = v0 > 0.f ? v0 : 0.f;
            v1 = v1 > 0.f ? v1 : 0.f;
            size_t d = (size_t)m * HID + col;
            *reinterpret_cast<float2*>(H0 + d) = make_float2(v0, v1);
            unsigned short h0h, h0l, h1h, h1l;
            split2(v0, h0h, h0l);
            split2(v1, h1h, h1l);
            *reinterpret_cast<uint32_t*>(g_h0b_hi + d) = ((uint32_t)h1h << 16) | h0h;
            *reinterpret_cast<uint32_t*>(g_h0b_lo + d) = ((uint32_t)h1l << 16) | h0l;
        }
    }
}

// ===========================================================================
// k_steps_mma v6: as R11, with load-after-compute reorder in the chunk loop.
// ===========================================================================
#define OFF_AH 0
#define OFF_AL 9216
#define OFF_BH 18432
#define OFF_BL 31744
#define STG_B  45056
#define APITCH_B 144
#define BPITCH_B 208
#define SM_WI  (3 * STG_B)
#define SM_AS  (SM_WI + 96 * 36 * 4)
#define SMEM_MMA (SM_AS + 2 * 64 * 36 * 4)  // 167424 B

__global__ void __launch_bounds__(256, 1) k_steps_mma(const float* __restrict__ h0,
                                                      const float* __restrict__ action,
                                                      const float* __restrict__ Wi,
                                                      const float* __restrict__ bi,
                                                      const float* __restrict__ bhn) {
    extern __shared__ char smem[];
    const uint32_t sb = smem_u32(smem);
    float* wi_s = reinterpret_cast<float*>(smem + SM_WI);
    float* a_s  = reinterpret_cast<float*>(smem + SM_AS);

    const int tid = threadIdx.x;
    const int w = tid >> 5, l = tid & 31;
    const int s = blockIdx.x;
    const int mq = blockIdx.y;
    const int wm = w & 3;
    const int wn = w >> 2;
    const int lr = l >> 2;
    const int lc2 = (l & 3) * 2;

    const int a_row  = wm * 16 + (l & 15);
    const int a_koff = (l >> 4) * 8;
    const int b_krow = l & 15;
    const int b_noff = wn * 48 + (l >> 4) * 8;

    const int hidbase = s * 32 + wn * 16;

    float bh[2][2];
    #pragma unroll
    for (int pp = 0; pp < 2; pp++) {
        float2 v = *reinterpret_cast<const float2*>(bhn + hidbase + pp * 8 + lc2);
        bh[pp][0] = v.x; bh[pp][1] = v.y;
    }
    float biv[3][2][2];
    #pragma unroll
    for (int gate = 0; gate < 3; gate++)
        #pragma unroll
        for (int pp = 0; pp < 2; pp++) {
            float2 v = *reinterpret_cast<const float2*>(bi + gate * HID + hidbase + pp * 8 + lc2);
            biv[gate][pp][0] = v.x; biv[gate][pp][1] = v.y;
        }
    float hpreg[2][2][2];
    #pragma unroll
    for (int rr = 0; rr < 2; rr++) {
        const int m = mq * 64 + wm * 16 + lr + rr * 8;
        #pragma unroll
        for (int pp = 0; pp < 2; pp++) {
            float2 v = *reinterpret_cast<const float2*>(h0 + (size_t)m * HID + hidbase + pp * 8 + lc2);
            hpreg[rr][pp][0] = v.x; hpreg[rr][pp][1] = v.y;
        }
    }

    for (int i = tid; i < 96 * 32; i += 256) {
        int col = i >> 5, k = i & 31;
        int gate = col >> 5, cl = col & 31;
        wi_s[col * 36 + k] = Wi[(size_t)k * G3 + gate * HID + s * 32 + cl];
    }
    __syncthreads();

    const char* srcBH = (const char*)(g_wBp_hi + (size_t)s * HID * 96);
    const char* srcBL = (const char*)(g_wBp_lo + (size_t)s * HID * 96);

    auto load_B = [&](int ch, int st) {
        uint32_t base = sb + st * STG_B;
        #pragma unroll
        for (int i = tid; i < 768; i += 256) {
            int r = i / 12, sg = i % 12;
            CP16(base + OFF_BH + r * BPITCH_B + sg * 16,
                 srcBH + ((size_t)(ch * 64 + r)) * 192 + sg * 16);
            CP16(base + OFF_BL + r * BPITCH_B + sg * 16,
                 srcBL + ((size_t)(ch * 64 + r)) * 192 + sg * 16);
        }
    };
    auto load_act = [&](int tt) {
        uint32_t ab = sb + SM_AS + (tt & 1) * (64 * 36 * 4);
        #pragma unroll
        for (int i = tid; i < 512; i += 256) {
            int row = i >> 3, seg = i & 7;
            const float* src = action + ((size_t)(mq * 64 + row) * NT + tt) * ACT + seg * 4;
            CP16(ab + row * 144 + seg * 16, src);
        }
    };

    load_B(0, 0); load_act(0); CP_COMMIT();
    load_B(1, 1); CP_COMMIT();

    #pragma unroll 1
    for (int t = 0; t < NT; t++) {
        const unsigned short* hsH = (t == 0) ? g_h0b_hi : g_obf_hi + (size_t)(t - 1) * BS * HID;
        const unsigned short* hsL = (t == 0) ? g_h0b_lo : g_obf_lo + (size_t)(t - 1) * BS * HID;
        const char* srcAH = (const char*)(hsH + (size_t)mq * 64 * HID);
        const char* srcAL = (const char*)(hsL + (size_t)mq * 64 * HID);

        auto load_A = [&](int ch, int st) {
            uint32_t base = sb + st * STG_B;
            #pragma unroll
            for (int i = tid; i < 512; i += 256) {
                int row = i >> 3, seg = i & 7;
                CP16(base + OFF_AH + row * APITCH_B + seg * 16,
                     srcAH + (size_t)row * (HID * 2) + ch * 128 + seg * 16);
                CP16(base + OFF_AL + row * APITCH_B + seg * 16,
                     srcAL + (size_t)row * (HID * 2) + ch * 128 + seg * 16);
            }
        };

        if (t > 0) {
            if (tid == 0) {
                unsigned* ctr = &g_bars[mq * 32];
                const unsigned target = 32u * (unsigned)t;
                atomicAdd(ctr, 1u);
                unsigned v;
                do {
                    asm volatile("ld.volatile.global.u32 %0, [%1];" : "=r"(v) : "l"(ctr));
                } while (v < target);
            }
            __syncthreads();
            __threadfence();
        }

        load_A(0, 0); CP_COMMIT();
        load_A(1, 1); CP_COMMIT();

        float c[6][4] = {};

        auto compute = [&](int st) {
            uint32_t base = sb + st * STG_B;
            #pragma unroll
            for (int kk = 0; kk < 4; kk++) {
                const int k0 = kk * 16;
                uint32_t aH[4], aL[4];
                uint32_t adA = base + OFF_AH + a_row * APITCH_B + (k0 + a_koff) * 2;
                LDSM4(aH, adA);
                LDSM4(aL, adA + (OFF_AL - OFF_AH));
                uint32_t bH[6][2], bL[6][2];
                #pragma unroll
                for (int g2 = 0; g2 < 3; g2++) {
                    uint32_t adB = base + OFF_BH + (k0 + b_krow) * BPITCH_B + (b_noff + g2 * 16) * 2;
                    uint32_t r4[4];
                    LDSM4T(r4, adB);
                    bH[g2 * 2][0] = r4[0]; bH[g2 * 2][1] = r4[1];
                    bH[g2 * 2 + 1][0] = r4[2]; bH[g2 * 2 + 1][1] = r4[3];
                    LDSM4T(r4, adB + (OFF_BL - OFF_BH));
                    bL[g2 * 2][0] = r4[0]; bL[g2 * 2][1] = r4[1];
                    bL[g2 * 2 + 1][0] = r4[2]; bL[g2 * 2 + 1][1] = r4[3];
                }
                #pragma unroll
                for (int g = 0; g < 6; g++) {
                    mma16816(c[g], aH, bH[g]);
                    mma16816(c[g], aH, bL[g]);
                    mma16816(c[g], aL, bH[g]);
                }
            }
        };

        #pragma unroll 1
        for (int ch = 0; ch < 16; ch++) {
            CP_WAIT(1);
            __syncthreads();
            compute(ch % 3);
            if (ch + 2 < 16) {
                int st2 = (ch + 2) % 3;
                load_A(ch + 2, st2);
                load_B(ch + 2, st2);
            }
            CP_COMMIT();
        }
        __syncthreads();

        if (t + 1 < NT) {
            load_B(0, 0); load_act(t + 1); CP_COMMIT();
            load_B(1, 1); CP_COMMIT();
        }

        // ---- fused input GEMM ----
        float giv[2][12];
        #pragma unroll
        for (int rr = 0; rr < 2; rr++)
            #pragma unroll
            for (int gate = 0; gate < 3; gate++)
                #pragma unroll
                for (int pp = 0; pp < 2; pp++) {
                    giv[rr][gate * 4 + pp * 2 + 0] = biv[gate][pp][0];
                    giv[rr][gate * 4 + pp * 2 + 1] = biv[gate][pp][1];
                }
        {
            const float* ab = a_s + (t & 1) * (64 * 36);
            const float* r0 = ab + (wm * 16 + lr) * 36;
            const float* r1 = r0 + 8 * 36;
            #pragma unroll
            for (int k4 = 0; k4 < 8; k4++) {
                float4 a0 = *reinterpret_cast<const float4*>(r0 + k4 * 4);
                float4 a1 = *reinterpret_cast<const float4*>(r1 + k4 * 4);
                #pragma unroll
                for (int gate = 0; gate < 3; gate++)
                    #pragma unroll
                    for (int pp = 0; pp < 2; pp++)
                        #pragma unroll
                        for (int e = 0; e < 2; e++) {
                            int col = gate * 32 + wn * 16 + pp * 8 + lc2 + e;
                            float4 wv = *reinterpret_cast<const float4*>(wi_s + col * 36 + k4 * 4);
                            int j = gate * 4 + pp * 2 + e;
                            giv[0][j] += a0.x * wv.x + a0.y * wv.y + a0.z * wv.z + a0.w * wv.w;
                            giv[1][j] += a1.x * wv.x + a1.y * wv.y + a1.z * wv.z + a1.w * wv.w;
                        }
            }
        }

        // ---- epilogue: gates+blend; single bf16 hi/lo store ----
        #pragma unroll
        for (int rr = 0; rr < 2; rr++) {
            const int m = mq * 64 + wm * 16 + lr + rr * 8;
            #pragma unroll
            for (int pp = 0; pp < 2; pp++) {
                const int hid = hidbase + pp * 8 + lc2;
                float h[2];
                #pragma unroll
                for (int e = 0; e < 2; e++) {
                    float rv = c[pp][2 * rr + e];
                    float zv = c[2 + pp][2 * rr + e];
                    float nv = c[4 + pp][2 * rr + e];
                    float rg = fast_sigmoid(rv + giv[rr][0 * 4 + pp * 2 + e]);
                    float zg = fast_sigmoid(zv + giv[rr][1 * 4 + pp * 2 + e]);
                    float ng = fast_tanh(giv[rr][2 * 4 + pp * 2 + e] + rg * (nv + bh[pp][e]));
                    h[e] = (1.0f - zg) * ng + zg * hpreg[rr][pp][e];
                    hpreg[rr][pp][e] = h[e];
                }
                size_t d = ((size_t)t * BS + m) * HID + hid;
                unsigned short hi0, hi1, lo0, lo1;
                split2(h[0], hi0, lo0);
                split2(h[1], hi1, lo1);
                *reinterpret_cast<uint32_t*>(g_obf_hi + d) = ((uint32_t)hi1 << 16) | hi0;
                *reinterpret_cast<uint32_t*>(g_obf_lo + d) = ((uint32_t)lo1 << 16) | lo0;
            }
        }

        if (t + 1 < NT) {
            __threadfence();
            __syncthreads();
        }
    }
}

// ===========================================================================
// k_out_mma (load-after-compute reorder applied)
// ===========================================================================
#define O_AH 0
#define O_AL 9216
#define O_BH 18432
#define O_BL 27648
#define OSTG 36864
#define O_PITCH 144
#define SMEM_OUT (3 * OSTG)

__global__ void __launch_bounds__(256) k_out_mma(const float* __restrict__ bo,
                                                 float* __restrict__ out) {
    extern __shared__ char smem[];
    const uint32_t sb = smem_u32(smem);
    const int tid = threadIdx.x;
    const int w = tid >> 5, l = tid & 31;
    const int wm = w & 3;
    const int wn = w >> 2;
    const int lr = l >> 2;
    const int lc2 = (l & 3) * 2;
    const int R0 = blockIdx.x * 64;

    const int a_row  = wm * 16 + (l & 15);
    const int a_koff = (l >> 4) * 8;
    const int b_krow = l & 15;
    const int b_lhalf = (l >> 4) * 8;

    const char* srcAH = (const char*)(g_obf_hi + (size_t)R0 * HID);
    const char* srcAL = (const char*)(g_obf_lo + (size_t)R0 * HID);

    auto load = [&](int ch, int st) {
        uint32_t base = sb + st * OSTG;
        #pragma unroll
        for (int i = tid; i < 512; i += 256) {
            int r = i >> 3, sg = i & 7;
            CP16(base + O_AH + r * O_PITCH + sg * 16,
                 srcAH + (size_t)r * (HID * 2) + ch * 128 + sg * 16);
            CP16(base + O_AL + r * O_PITCH + sg * 16,
                 srcAL + (size_t)r * (HID * 2) + ch * 128 + sg * 16);
        }
        #pragma unroll
        for (int i = tid; i < 512; i += 256) {
            int r = i >> 3, sg = i & 7;
            CP16(base + O_BH + r * O_PITCH + sg * 16,
                 (const char*)g_wo_hi + ((size_t)(ch * 64 + r) * OUTD) * 2 + sg * 16);
            CP16(base + O_BL + r * O_PITCH + sg * 16,
                 (const char*)g_wo_lo + ((size_t)(ch * 64 + r) * OUTD) * 2 + sg * 16);
        }
    };

    load(0, 0); CP_COMMIT();
    load(1, 1); CP_COMMIT();

    float c[4][4] = {};

    auto compute = [&](int st) {
        uint32_t base = sb + st * OSTG;
        #pragma unroll
        for (int kk = 0; kk < 4; kk++) {
            const int k0 = kk * 16;
            uint32_t aH[4], aL[4];
            uint32_t adA = base + O_AH + a_row * O_PITCH + (k0 + a_koff) * 2;
            LDSM4(aH, adA);
            LDSM4(aL, adA + (O_AL - O_AH));
            uint32_t bH[4][2], bL[4][2];
            #pragma unroll
            for (int n16 = 0; n16 < 2; n16++) {
                uint32_t adB = base + O_BH + (k0 + b_krow) * O_PITCH
                             + (wn * 32 + n16 * 16 + b_lhalf) * 2;
                uint32_t r4[4];
                LDSM4T(r4, adB);
                bH[n16 * 2][0] = r4[0]; bH[n16 * 2][1] = r4[1];
                bH[n16 * 2 + 1][0] = r4[2]; bH[n16 * 2 + 1][1] = r4[3];
                LDSM4T(r4, adB + (O_BL - O_BH));
                bL[n16 * 2][0] = r4[0]; bL[n16 * 2][1] = r4[1];
                bL[n16 * 2 + 1][0] = r4[2]; bL[n16 * 2 + 1][1] = r4[3];
            }
            #pragma unroll
            for (int g = 0; g < 4; g++) {
                mma16816(c[g], aH, bH[g]);
                mma16816(c[g], aH, bL[g]);
                mma16816(c[g], aL, bH[g]);
            }
        }
    };

    #pragma unroll 1
    for (int ch = 0; ch < 16; ch++) {
        CP_WAIT(1);
        __syncthreads();
        compute(ch % 3);
        if (ch + 2 < 16) load(ch + 2, (ch + 2) % 3);
        CP_COMMIT();
    }

    #pragma unroll
    for (int g = 0; g < 4; g++) {
        const int col = wn * 32 + g * 8 + lc2;
        float2 bov = *reinterpret_cast<const float2*>(bo + col);
        #pragma unroll
        for (int rr = 0; rr < 2; rr++) {
            int R = R0 + wm * 16 + lr + rr * 8;
            int tt = R >> 8;
            int b  = R & (BS - 1);
            float2 o = make_float2(c[g][2 * rr] + bov.x, c[g][2 * rr + 1] + bov.y);
            *reinterpret_cast<float2*>(out + ((size_t)b * NT + tt) * OUTD + col) = o;
        }
    }
}

extern "C" void kernel_launch(void* const* d_in, const int* in_sizes, int n_in,
                              void* d_out, int out_size) {
    const float* history = (const float*)d_in[0];
    const float* action  = (const float*)d_in[1];
    const float* W_in    = (const float*)d_in[2];
    const float* b_in    = (const float*)d_in[3];
    const float* Wi      = (const float*)d_in[4];
    const float* bi      = (const float*)d_in[5];
    const float* Wh      = (const float*)d_in[6];
    const float* bhn     = (const float*)d_in[7];
    const float* Wo      = (const float*)d_in[8];
    const float* bo      = (const float*)d_in[9];
    float* out = (float*)d_out;

    float* h0buf = nullptr;
    cudaGetSymbolAddress((void**)&h0buf, g_h0);

    cudaFuncSetAttribute(k_h0_mma, cudaFuncAttributeMaxDynamicSharedMemorySize, SMEM_H0);
    cudaFuncSetAttribute(k_steps_mma, cudaFuncAttributeMaxDynamicSharedMemorySize, SMEM_MMA);
    cudaFuncSetAttribute(k_out_mma, cudaFuncAttributeMaxDynamicSharedMemorySize, SMEM_OUT);

    k_zero<<<1, 128>>>();
    k_cvtX<<<BS * KIN / 256, 256>>>(history);
    k_packWin<<<KIN * HID / 256, 256>>>(W_in);
    k_packW<<<dim3(32, 16), 256>>>(Wh);
    k_packWo<<<HID * OUTD / 256, 256>>>(Wo);

    k_h0_mma<<<dim3(HID / 64, BS / 32), 256, SMEM_H0>>>(b_in, h0buf);

    k_steps_mma<<<dim3(32, 4), 256, SMEM_MMA>>>(h0buf, action, Wi, bi, bhn);

    k_out_mma<<<NT * BS / 64, 256, SMEM_OUT>>>(bo, out);
}

// round 13
// speedup vs baseline: 1.7492x; 1.0230x over previous
#include <cuda_runtime.h>
#include <cuda_bf16.h>
#include <cstdint>
#include <cstddef>

#define BS   256
#define HID  1024
#define NT   100
#define ACT  32
#define KIN  8000
#define G3   3072
#define OUTD 64

// ---------------- device scratch (allocation-free rule) ----------------
__device__ float g_h0[BS * HID];
__device__ unsigned g_bars[4 * 32];

// h history bf16 hi/lo: [t][b][hid] (A source AND k_out input)
__device__ __align__(16) unsigned short g_obf_hi[(size_t)NT * BS * HID];
__device__ __align__(16) unsigned short g_obf_lo[(size_t)NT * BS * HID];
// h0 bf16 image
__device__ __align__(16) unsigned short g_h0b_hi[BS * HID];
__device__ __align__(16) unsigned short g_h0b_lo[BS * HID];
// Wh packed bf16: [slice 32][k 1024][col 96], col = sub*48+gate*16+h16
__device__ __align__(16) unsigned short g_wBp_hi[32 * HID * 96];
__device__ __align__(16) unsigned short g_wBp_lo[32 * HID * 96];
// Wo packed bf16: [k 1024][n 64]
__device__ __align__(16) unsigned short g_wo_hi[HID * OUTD];
__device__ __align__(16) unsigned short g_wo_lo[HID * OUTD];
// W_in packed bf16: [k 8000][n 1024]
__device__ __align__(16) unsigned short g_win_hi[(size_t)KIN * HID];
__device__ __align__(16) unsigned short g_win_lo[(size_t)KIN * HID];
// X (history flattened) bf16: [m 256][k 8000]
__device__ __align__(16) unsigned short g_x_hi[BS * KIN];
__device__ __align__(16) unsigned short g_x_lo[BS * KIN];

// ---------------- helpers ----------------
__device__ __forceinline__ float fast_sigmoid(float x) {
    return __fdividef(1.0f, 1.0f + __expf(-x));
}
__device__ __forceinline__ float fast_tanh(float x) {
    float e = __expf(2.0f * x);
    return 1.0f - __fdividef(2.0f, e + 1.0f);
}
__device__ __forceinline__ void split2(float x, unsigned short& h, unsigned short& l) {
    __nv_bfloat16 hb = __float2bfloat16(x);
    float hf = __bfloat162float(hb);
    __nv_bfloat16 lb = __float2bfloat16(x - hf);
    h = *reinterpret_cast<unsigned short*>(&hb);
    l = *reinterpret_cast<unsigned short*>(&lb);
}
// split 8 consecutive floats -> uint4 hi + uint4 lo
__device__ __forceinline__ void split8(const float* src, uint4& H, uint4& L) {
    unsigned short* ph = (unsigned short*)&H;
    unsigned short* pl = (unsigned short*)&L;
    float4 v0 = *reinterpret_cast<const float4*>(src);
    float4 v1 = *reinterpret_cast<const float4*>(src + 4);
    split2(v0.x, ph[0], pl[0]); split2(v0.y, ph[1], pl[1]);
    split2(v0.z, ph[2], pl[2]); split2(v0.w, ph[3], pl[3]);
    split2(v1.x, ph[4], pl[4]); split2(v1.y, ph[5], pl[5]);
    split2(v1.z, ph[6], pl[6]); split2(v1.w, ph[7], pl[7]);
}

#define CP16(dst, src) asm volatile("cp.async.cg.shared.global [%0], [%1], 16;\n" :: "r"(dst), "l"(src))
#define CP_COMMIT()    asm volatile("cp.async.commit_group;\n")
#define CP_WAIT(n)     asm volatile("cp.async.wait_group %0;\n" :: "n"(n))

__device__ __forceinline__ uint32_t smem_u32(const void* p) {
    uint32_t a;
    asm("{ .reg .u64 t; cvta.to.shared.u64 t, %1; cvt.u32.u64 %0, t; }" : "=r"(a) : "l"(p));
    return a;
}
__device__ __forceinline__ void mma16816(float* c, const uint32_t* a, const uint32_t* b) {
    asm volatile("mma.sync.aligned.m16n8k16.row.col.f32.bf16.bf16.f32 "
        "{%0,%1,%2,%3}, {%4,%5,%6,%7}, {%8,%9}, {%0,%1,%2,%3};"
        : "+f"(c[0]), "+f"(c[1]), "+f"(c[2]), "+f"(c[3])
        : "r"(a[0]), "r"(a[1]), "r"(a[2]), "r"(a[3]), "r"(b[0]), "r"(b[1]));
}
#define LDSM4(r, addr)                                                          \
    asm volatile("ldmatrix.sync.aligned.m8n8.x4.shared.b16 {%0,%1,%2,%3}, [%4];"\
        : "=r"((r)[0]), "=r"((r)[1]), "=r"((r)[2]), "=r"((r)[3]) : "r"(addr))
#define LDSM4T(r, addr)                                                         \
    asm volatile("ldmatrix.sync.aligned.m8n8.x4.trans.shared.b16 {%0,%1,%2,%3}, [%4];" \
        : "=r"((r)[0]), "=r"((r)[1]), "=r"((r)[2]), "=r"((r)[3]) : "r"(addr))

// ===========================================================================
__global__ void k_zero() {
    if (threadIdx.x < 4 * 32) g_bars[threadIdx.x] = 0u;
}

// ===========================================================================
// k_packW: Wh -> [32][1024][96] bf16 hi/lo, vectorized. grid (32,16), 256 thr.
// ===========================================================================
__global__ void __launch_bounds__(256) k_packW(const float* __restrict__ Wh) {
    const int s = blockIdx.x, kg = blockIdx.y;
    for (int i = threadIdx.x; i < 64 * 12; i += 256) {
        int k = kg * 64 + i / 12;
        int c8 = (i % 12) * 8;               // multiple of 8, stays in one gate seg
        int sub = c8 / 48, rem = c8 % 48;
        int gate = rem / 16, h0 = rem % 16;
        const float* src = Wh + (size_t)k * G3 + gate * HID + s * 32 + sub * 16 + h0;
        uint4 H, L;
        split8(src, H, L);
        size_t d = ((size_t)s * HID + k) * 96 + c8;
        *reinterpret_cast<uint4*>(g_wBp_hi + d) = H;
        *reinterpret_cast<uint4*>(g_wBp_lo + d) = L;
    }
}

// ===========================================================================
// vectorized elementwise splits (8 elems/thread)
// ===========================================================================
__global__ void __launch_bounds__(256) k_packWo(const float* __restrict__ Wo) {
    size_t i = ((size_t)blockIdx.x * 256 + threadIdx.x) * 8;
    uint4 H, L;
    split8(Wo + i, H, L);
    *reinterpret_cast<uint4*>(g_wo_hi + i) = H;
    *reinterpret_cast<uint4*>(g_wo_lo + i) = L;
}
__global__ void __launch_bounds__(256) k_packWin(const float* __restrict__ Win) {
    size_t i = ((size_t)blockIdx.x * 256 + threadIdx.x) * 8;
    uint4 H, L;
    split8(Win + i, H, L);
    *reinterpret_cast<uint4*>(g_win_hi + i) = H;
    *reinterpret_cast<uint4*>(g_win_lo + i) = L;
}
__global__ void __launch_bounds__(256) k_cvtX(const float* __restrict__ X) {
    size_t i = ((size_t)blockIdx.x * 256 + threadIdx.x) * 8;
    uint4 H, L;
    split8(X + i, H, L);
    *reinterpret_cast<uint4*>(g_x_hi + i) = H;
    *reinterpret_cast<uint4*>(g_x_lo + i) = L;
}

// ===========================================================================
// k_h0_mma: h0 = relu(X_bf16 @ Win_bf16 + b_in)   (unchanged from R12)
// ===========================================================================
#define H_AH 0
#define H_AL 4608
#define H_BH 9216
#define H_BL 18432
#define HSTG2 27648
#define SMEM_H0 (3 * HSTG2)
#define H_NCH 125

__global__ void __launch_bounds__(256) k_h0_mma(const float* __restrict__ b_in,
                                                float* __restrict__ H0) {
    extern __shared__ char smem[];
    const uint32_t sb = smem_u32(smem);
    const int tid = threadIdx.x;
    const int w = tid >> 5, l = tid & 31;
    const int wm = w & 1;
    const int wn = w >> 1;
    const int lr = l >> 2;
    const int lc2 = (l & 3) * 2;
    const int m0 = blockIdx.y * 32, n0 = blockIdx.x * 64;

    const int a_row  = wm * 16 + (l & 15);
    const int a_koff = (l >> 4) * 8;
    const int b_krow = l & 15;
    const int b_lhalf = (l >> 4) * 8;

    const char* srcAH = (const char*)(g_x_hi + (size_t)m0 * KIN);
    const char* srcAL = (const char*)(g_x_lo + (size_t)m0 * KIN);

    auto load = [&](int ch, int st) {
        uint32_t base = sb + st * HSTG2;
        {
            int r = tid >> 3, sg = tid & 7;
            CP16(base + H_AH + r * 144 + sg * 16,
                 srcAH + (size_t)r * (KIN * 2) + ch * 128 + sg * 16);
            CP16(base + H_AL + r * 144 + sg * 16,
                 srcAL + (size_t)r * (KIN * 2) + ch * 128 + sg * 16);
        }
        #pragma unroll
        for (int i = tid; i < 512; i += 256) {
            int r = i >> 3, sg = i & 7;
            CP16(base + H_BH + r * 144 + sg * 16,
                 (const char*)g_win_hi + ((size_t)(ch * 64 + r) * HID + n0) * 2 + sg * 16);
            CP16(base + H_BL + r * 144 + sg * 16,
                 (const char*)g_win_lo + ((size_t)(ch * 64 + r) * HID + n0) * 2 + sg * 16);
        }
    };

    load(0, 0); CP_COMMIT();
    load(1, 1); CP_COMMIT();

    float c[2][4] = {};

    auto compute = [&](int st) {
        uint32_t base = sb + st * HSTG2;
        #pragma unroll
        for (int kk = 0; kk < 4; kk++) {
            const int k0 = kk * 16;
            uint32_t aH[4], aL[4];
            uint32_t adA = base + H_AH + a_row * 144 + (k0 + a_koff) * 2;
            LDSM4(aH, adA);
            LDSM4(aL, adA + (H_AL - H_AH));
            uint32_t bH[2][2], bL[2][2];
            uint32_t adB = base + H_BH + (k0 + b_krow) * 144 + (wn * 16 + b_lhalf) * 2;
            uint32_t r4[4];
            LDSM4T(r4, adB);
            bH[0][0] = r4[0]; bH[0][1] = r4[1]; bH[1][0] = r4[2]; bH[1][1] = r4[3];
            LDSM4T(r4, adB + (H_BL - H_BH));
            bL[0][0] = r4[0]; bL[0][1] = r4[1]; bL[1][0] = r4[2]; bL[1][1] = r4[3];
            #pragma unroll
            for (int g = 0; g < 2; g++) {
                mma16816(c[g], aH, bH[g]);
                mma16816(c[g], aH, bL[g]);
                mma16816(c[g], aL, bH[g]);
            }
        }
    };

    #pragma unroll 1
    for (int ch = 0; ch < H_NCH; ch++) {
        CP_WAIT(1);
        __syncthreads();
        compute(ch % 3);
        if (ch + 2 < H_NCH) load(ch + 2, (ch + 2) % 3);
        CP_COMMIT();
    }

    #pragma unroll
    for (int g = 0; g < 2; g++) {
        const int col = n0 + wn * 16 + g * 8 + lc2;
        float2 bv = *reinterpret_cast<const float2*>(b_in + col);
        #pragma unroll
        for (int rr = 0; rr < 2; rr++) {
            const int m = m0 + wm * 16 + lr + rr * 8;
            float v0 = c[g][2 * rr]     + bv.x;
            float v1 = c[g][2 * rr + 1] + bv.y;
            v0 = v0 > 0.f ? v0 : 0.f;
            v1 = v1 > 0.f ? v1 : 0.f;
            size_t d = (size_t)m * HID + col;
            *reinterpret_cast<float2*>(H0 + d) = make_float2(v0, v1);
            unsigned short h0h, h0l, h1h, h1l;
            split2(v0, h0h, h0l);
            split2(v1, h1h, h1l);
            *reinterpret_cast<uint32_t*>(g_h0b_hi + d) = ((uint32_t)h1h << 16) | h0h;
            *reinterpret_cast<uint32_t*>(g_h0b_lo + d) = ((uint32_t)h1l << 16) | h0l;
        }
    }
}

// ===========================================================================
// k_steps_mma v7: gi GEMM hoisted to step top (overlaps chunk-0 A latency).
// ===========================================================================
#define OFF_AH 0
#define OFF_AL 9216
#define OFF_BH 18432
#define OFF_BL 31744
#define STG_B  45056
#define APITCH_B 144
#define BPITCH_B 208
#define SM_WI  (3 * STG_B)
#define SM_AS  (SM_WI + 96 * 36 * 4)
#define SMEM_MMA (SM_AS + 2 * 64 * 36 * 4)  // 167424 B

__global__ void __launch_bounds__(256, 1) k_steps_mma(const float* __restrict__ h0,
                                                      const float* __restrict__ action,
                                                      const float* __restrict__ Wi,
                                                      const float* __restrict__ bi,
                                                      const float* __restrict__ bhn) {
    extern __shared__ char smem[];
    const uint32_t sb = smem_u32(smem);
    float* wi_s = reinterpret_cast<float*>(smem + SM_WI);
    float* a_s  = reinterpret_cast<float*>(smem + SM_AS);

    const int tid = threadIdx.x;
    const int w = tid >> 5, l = tid & 31;
    const int s = blockIdx.x;
    const int mq = blockIdx.y;
    const int wm = w & 3;
    const int wn = w >> 2;
    const int lr = l >> 2;
    const int lc2 = (l & 3) * 2;

    const int a_row  = wm * 16 + (l & 15);
    const int a_koff = (l >> 4) * 8;
    const int b_krow = l & 15;
    const int b_noff = wn * 48 + (l >> 4) * 8;

    const int hidbase = s * 32 + wn * 16;

    float bh[2][2];
    #pragma unroll
    for (int pp = 0; pp < 2; pp++) {
        float2 v = *reinterpret_cast<const float2*>(bhn + hidbase + pp * 8 + lc2);
        bh[pp][0] = v.x; bh[pp][1] = v.y;
    }
    float hpreg[2][2][2];
    #pragma unroll
    for (int rr = 0; rr < 2; rr++) {
        const int m = mq * 64 + wm * 16 + lr + rr * 8;
        #pragma unroll
        for (int pp = 0; pp < 2; pp++) {
            float2 v = *reinterpret_cast<const float2*>(h0 + (size_t)m * HID + hidbase + pp * 8 + lc2);
            hpreg[rr][pp][0] = v.x; hpreg[rr][pp][1] = v.y;
        }
    }

    for (int i = tid; i < 96 * 32; i += 256) {
        int col = i >> 5, k = i & 31;
        int gate = col >> 5, cl = col & 31;
        wi_s[col * 36 + k] = Wi[(size_t)k * G3 + gate * HID + s * 32 + cl];
    }
    __syncthreads();

    const char* srcBH = (const char*)(g_wBp_hi + (size_t)s * HID * 96);
    const char* srcBL = (const char*)(g_wBp_lo + (size_t)s * HID * 96);

    auto load_B = [&](int ch, int st) {
        uint32_t base = sb + st * STG_B;
        #pragma unroll
        for (int i = tid; i < 768; i += 256) {
            int r = i / 12, sg = i % 12;
            CP16(base + OFF_BH + r * BPITCH_B + sg * 16,
                 srcBH + ((size_t)(ch * 64 + r)) * 192 + sg * 16);
            CP16(base + OFF_BL + r * BPITCH_B + sg * 16,
                 srcBL + ((size_t)(ch * 64 + r)) * 192 + sg * 16);
        }
    };
    auto load_act = [&](int tt) {
        uint32_t ab = sb + SM_AS + (tt & 1) * (64 * 36 * 4);
        #pragma unroll
        for (int i = tid; i < 512; i += 256) {
            int row = i >> 3, seg = i & 7;
            const float* src = action + ((size_t)(mq * 64 + row) * NT + tt) * ACT + seg * 4;
            CP16(ab + row * 144 + seg * 16, src);
        }
    };

    load_B(0, 0); load_act(0); CP_COMMIT();
    load_B(1, 1); CP_COMMIT();

    #pragma unroll 1
    for (int t = 0; t < NT; t++) {
        const unsigned short* hsH = (t == 0) ? g_h0b_hi : g_obf_hi + (size_t)(t - 1) * BS * HID;
        const unsigned short* hsL = (t == 0) ? g_h0b_lo : g_obf_lo + (size_t)(t - 1) * BS * HID;
        const char* srcAH = (const char*)(hsH + (size_t)mq * 64 * HID);
        const char* srcAL = (const char*)(hsL + (size_t)mq * 64 * HID);

        auto load_A = [&](int ch, int st) {
            uint32_t base = sb + st * STG_B;
            #pragma unroll
            for (int i = tid; i < 512; i += 256) {
                int row = i >> 3, seg = i & 7;
                CP16(base + OFF_AH + row * APITCH_B + seg * 16,
                     srcAH + (size_t)row * (HID * 2) + ch * 128 + seg * 16);
                CP16(base + OFF_AL + row * APITCH_B + seg * 16,
                     srcAL + (size_t)row * (HID * 2) + ch * 128 + seg * 16);
            }
        };

        if (t > 0) {
            if (tid == 0) {
                unsigned* ctr = &g_bars[mq * 32];
                const unsigned target = 32u * (unsigned)t;
                atomicAdd(ctr, 1u);
                unsigned v;
                do {
                    asm volatile("ld.volatile.global.u32 %0, [%1];" : "=r"(v) : "l"(ctr));
                } while (v < target);
            }
            __syncthreads();
            __threadfence();
        }

        load_A(0, 0); CP_COMMIT();
        load_A(1, 1); CP_COMMIT();

        // ---- fused input GEMM (hoisted): giv = a_t @ Wi + bi.
        // Gated: act group (oldest pending) must be complete + cross-thread sync.
        CP_WAIT(3);
        __syncthreads();
        float giv[2][12];
        #pragma unroll
        for (int gate = 0; gate < 3; gate++)
            #pragma unroll
            for (int pp = 0; pp < 2; pp++) {
                float2 v = *reinterpret_cast<const float2*>(bi + gate * HID + hidbase + pp * 8 + lc2);
                giv[0][gate * 4 + pp * 2 + 0] = v.x;
                giv[0][gate * 4 + pp * 2 + 1] = v.y;
                giv[1][gate * 4 + pp * 2 + 0] = v.x;
                giv[1][gate * 4 + pp * 2 + 1] = v.y;
            }
        {
            const float* ab = a_s + (t & 1) * (64 * 36);
            const float* r0 = ab + (wm * 16 + lr) * 36;
            const float* r1 = r0 + 8 * 36;
            #pragma unroll
            for (int k4 = 0; k4 < 8; k4++) {
                float4 a0 = *reinterpret_cast<const float4*>(r0 + k4 * 4);
                float4 a1 = *reinterpret_cast<const float4*>(r1 + k4 * 4);
                #pragma unroll
                for (int gate = 0; gate < 3; gate++)
                    #pragma unroll
                    for (int pp = 0; pp < 2; pp++)
                        #pragma unroll
                        for (int e = 0; e < 2; e++) {
                            int col = gate * 32 + wn * 16 + pp * 8 + lc2 + e;
                            float4 wv = *reinterpret_cast<const float4*>(wi_s + col * 36 + k4 * 4);
                            int j = gate * 4 + pp * 2 + e;
                            giv[0][j] += a0.x * wv.x + a0.y * wv.y + a0.z * wv.z + a0.w * wv.w;
                            giv[1][j] += a1.x * wv.x + a1.y * wv.y + a1.z * wv.z + a1.w * wv.w;
                        }
            }
        }

        float c[6][4] = {};

        auto compute = [&](int st) {
            uint32_t base = sb + st * STG_B;
            #pragma unroll
            for (int kk = 0; kk < 4; kk++) {
                const int k0 = kk * 16;
                uint32_t aH[4], aL[4];
                uint32_t adA = base + OFF_AH + a_row * APITCH_B + (k0 + a_koff) * 2;
                LDSM4(aH, adA);
                LDSM4(aL, adA + (OFF_AL - OFF_AH));
                uint32_t bH[6][2], bL[6][2];
                #pragma unroll
                for (int g2 = 0; g2 < 3; g2++) {
                    uint32_t adB = base + OFF_BH + (k0 + b_krow) * BPITCH_B + (b_noff + g2 * 16) * 2;
                    uint32_t r4[4];
                    LDSM4T(r4, adB);
                    bH[g2 * 2][0] = r4[0]; bH[g2 * 2][1] = r4[1];
                    bH[g2 * 2 + 1][0] = r4[2]; bH[g2 * 2 + 1][1] = r4[3];
                    LDSM4T(r4, adB + (OFF_BL - OFF_BH));
                    bL[g2 * 2][0] = r4[0]; bL[g2 * 2][1] = r4[1];
                    bL[g2 * 2 + 1][0] = r4[2]; bL[g2 * 2 + 1][1] = r4[3];
                }
                #pragma unroll
                for (int g = 0; g < 6; g++) {
                    mma16816(c[g], aH, bH[g]);
                    mma16816(c[g], aH, bL[g]);
                    mma16816(c[g], aL, bH[g]);
                }
            }
        };

        #pragma unroll 1
        for (int ch = 0; ch < 16; ch++) {
            CP_WAIT(1);
            __syncthreads();
            compute(ch % 3);
            if (ch + 2 < 16) {
                int st2 = (ch + 2) % 3;
                load_A(ch + 2, st2);
                load_B(ch + 2, st2);
            }
            CP_COMMIT();
        }
        __syncthreads();

        if (t + 1 < NT) {
            load_B(0, 0); load_act(t + 1); CP_COMMIT();
            load_B(1, 1); CP_COMMIT();
        }

        // ---- epilogue: gates+blend; single bf16 hi/lo store ----
        #pragma unroll
        for (int rr = 0; rr < 2; rr++) {
            const int m = mq * 64 + wm * 16 + lr + rr * 8;
            #pragma unroll
            for (int pp = 0; pp < 2; pp++) {
                const int hid = hidbase + pp * 8 + lc2;
                float h[2];
                #pragma unroll
                for (int e = 0; e < 2; e++) {
                    float rv = c[pp][2 * rr + e];
                    float zv = c[2 + pp][2 * rr + e];
                    float nv = c[4 + pp][2 * rr + e];
                    float rg = fast_sigmoid(rv + giv[rr][0 * 4 + pp * 2 + e]);
                    float zg = fast_sigmoid(zv + giv[rr][1 * 4 + pp * 2 + e]);
                    float ng = fast_tanh(giv[rr][2 * 4 + pp * 2 + e] + rg * (nv + bh[pp][e]));
                    h[e] = (1.0f - zg) * ng + zg * hpreg[rr][pp][e];
                    hpreg[rr][pp][e] = h[e];
                }
                size_t d = ((size_t)t * BS + m) * HID + hid;
                unsigned short hi0, hi1, lo0, lo1;
                split2(h[0], hi0, lo0);
                split2(h[1], hi1, lo1);
                *reinterpret_cast<uint32_t*>(g_obf_hi + d) = ((uint32_t)hi1 << 16) | hi0;
                *reinterpret_cast<uint32_t*>(g_obf_lo + d) = ((uint32_t)lo1 << 16) | lo0;
            }
        }

        if (t + 1 < NT) {
            __threadfence();
            __syncthreads();
        }
    }
}

// ===========================================================================
// k_out_mma (unchanged from R12)
// ===========================================================================
#define O_AH 0
#define O_AL 9216
#define O_BH 18432
#define O_BL 27648
#define OSTG 36864
#define O_PITCH 144
#define SMEM_OUT (3 * OSTG)

__global__ void __launch_bounds__(256) k_out_mma(const float* __restrict__ bo,
                                                 float* __restrict__ out) {
    extern __shared__ char smem[];
    const uint32_t sb = smem_u32(smem);
    const int tid = threadIdx.x;
    const int w = tid >> 5, l = tid & 31;
    const int wm = w & 3;
    const int wn = w >> 2;
    const int lr = l >> 2;
    const int lc2 = (l & 3) * 2;
    const int R0 = blockIdx.x * 64;

    const int a_row  = wm * 16 + (l & 15);
    const int a_koff = (l >> 4) * 8;
    const int b_krow = l & 15;
    const int b_lhalf = (l >> 4) * 8;

    const char* srcAH = (const char*)(g_obf_hi + (size_t)R0 * HID);
    const char* srcAL = (const char*)(g_obf_lo + (size_t)R0 * HID);

    auto load = [&](int ch, int st) {
        uint32_t base = sb + st * OSTG;
        #pragma unroll
        for (int i = tid; i < 512; i += 256) {
            int r = i >> 3, sg = i & 7;
            CP16(base + O_AH + r * O_PITCH + sg * 16,
                 srcAH + (size_t)r * (HID * 2) + ch * 128 + sg * 16);
            CP16(base + O_AL + r * O_PITCH + sg * 16,
                 srcAL + (size_t)r * (HID * 2) + ch * 128 + sg * 16);
        }
        #pragma unroll
        for (int i = tid; i < 512; i += 256) {
            int r = i >> 3, sg = i & 7;
            CP16(base + O_BH + r * O_PITCH + sg * 16,
                 (const char*)g_wo_hi + ((size_t)(ch * 64 + r) * OUTD) * 2 + sg * 16);
            CP16(base + O_BL + r * O_PITCH + sg * 16,
                 (const char*)g_wo_lo + ((size_t)(ch * 64 + r) * OUTD) * 2 + sg * 16);
        }
    };

    load(0, 0); CP_COMMIT();
    load(1, 1); CP_COMMIT();

    float c[4][4] = {};

    auto compute = [&](int st) {
        uint32_t base = sb + st * OSTG;
        #pragma unroll
        for (int kk = 0; kk < 4; kk++) {
            const int k0 = kk * 16;
            uint32_t aH[4], aL[4];
            uint32_t adA = base + O_AH + a_row * O_PITCH + (k0 + a_koff) * 2;
            LDSM4(aH, adA);
            LDSM4(aL, adA + (O_AL - O_AH));
            uint32_t bH[4][2], bL[4][2];
            #pragma unroll
            for (int n16 = 0; n16 < 2; n16++) {
                uint32_t adB = base + O_BH + (k0 + b_krow) * O_PITCH
                             + (wn * 32 + n16 * 16 + b_lhalf) * 2;
                uint32_t r4[4];
                LDSM4T(r4, adB);
                bH[n16 * 2][0] = r4[0]; bH[n16 * 2][1] = r4[1];
                bH[n16 * 2 + 1][0] = r4[2]; bH[n16 * 2 + 1][1] = r4[3];
                LDSM4T(r4, adB + (O_BL - O_BH));
                bL[n16 * 2][0] = r4[0]; bL[n16 * 2][1] = r4[1];
                bL[n16 * 2 + 1][0] = r4[2]; bL[n16 * 2 + 1][1] = r4[3];
            }
            #pragma unroll
            for (int g = 0; g < 4; g++) {
                mma16816(c[g], aH, bH[g]);
                mma16816(c[g], aH, bL[g]);
                mma16816(c[g], aL, bH[g]);
            }
        }
    };

    #pragma unroll 1
    for (int ch = 0; ch < 16; ch++) {
        CP_WAIT(1);
        __syncthreads();
        compute(ch % 3);
        if (ch + 2 < 16) load(ch + 2, (ch + 2) % 3);
        CP_COMMIT();
    }

    #pragma unroll
    for (int g = 0; g < 4; g++) {
        const int col = wn * 32 + g * 8 + lc2;
        float2 bov = *reinterpret_cast<const float2*>(bo + col);
        #pragma unroll
        for (int rr = 0; rr < 2; rr++) {
            int R = R0 + wm * 16 + lr + rr * 8;
            int tt = R >> 8;
            int b  = R & (BS - 1);
            float2 o = make_float2(c[g][2 * rr] + bov.x, c[g][2 * rr + 1] + bov.y);
            *reinterpret_cast<float2*>(out + ((size_t)b * NT + tt) * OUTD + col) = o;
        }
    }
}

extern "C" void kernel_launch(void* const* d_in, const int* in_sizes, int n_in,
                              void* d_out, int out_size) {
    const float* history = (const float*)d_in[0];
    const float* action  = (const float*)d_in[1];
    const float* W_in    = (const float*)d_in[2];
    const float* b_in    = (const float*)d_in[3];
    const float* Wi      = (const float*)d_in[4];
    const float* bi      = (const float*)d_in[5];
    const float* Wh      = (const float*)d_in[6];
    const float* bhn     = (const float*)d_in[7];
    const float* Wo      = (const float*)d_in[8];
    const float* bo      = (const float*)d_in[9];
    float* out = (float*)d_out;

    float* h0buf = nullptr;
    cudaGetSymbolAddress((void**)&h0buf, g_h0);

    cudaFuncSetAttribute(k_h0_mma, cudaFuncAttributeMaxDynamicSharedMemorySize, SMEM_H0);
    cudaFuncSetAttribute(k_steps_mma, cudaFuncAttributeMaxDynamicSharedMemorySize, SMEM_MMA);
    cudaFuncSetAttribute(k_out_mma, cudaFuncAttributeMaxDynamicSharedMemorySize, SMEM_OUT);

    k_zero<<<1, 128>>>();
    k_cvtX<<<BS * KIN / (256 * 8), 256>>>(history);
    k_packWin<<<KIN * HID / (256 * 8), 256>>>(W_in);
    k_packW<<<dim3(32, 16), 256>>>(Wh);
    k_packWo<<<HID * OUTD / (256 * 8), 256>>>(Wo);

    k_h0_mma<<<dim3(HID / 64, BS / 32), 256, SMEM_H0>>>(b_in, h0buf);

    k_steps_mma<<<dim3(32, 4), 256, SMEM_MMA>>>(h0buf, action, Wi, bi, bhn);

    k_out_mma<<<NT * BS / 64, 256, SMEM_OUT>>>(bo, out);
}

// round 14
// speedup vs baseline: 1.7679x; 1.0107x over previous
#include <cuda_runtime.h>
#include <cuda_bf16.h>
#include <cstdint>
#include <cstddef>

#define BS   256
#define HID  1024
#define NT   100
#define ACT  32
#define KIN  8000
#define G3   3072
#define OUTD 64

// ---------------- device scratch (allocation-free rule) ----------------
__device__ float g_h0[BS * HID];
__device__ float g_h0p[2 * BS * HID];               // split-K partials
__device__ unsigned g_bars[4 * 32];

// h history bf16 hi/lo: [t][b][hid] (A source AND k_out input)
__device__ __align__(16) unsigned short g_obf_hi[(size_t)NT * BS * HID];
__device__ __align__(16) unsigned short g_obf_lo[(size_t)NT * BS * HID];
// h0 bf16 image
__device__ __align__(16) unsigned short g_h0b_hi[BS * HID];
__device__ __align__(16) unsigned short g_h0b_lo[BS * HID];
// Wh packed bf16: [slice 32][k 1024][col 96], col = sub*48+gate*16+h16
__device__ __align__(16) unsigned short g_wBp_hi[32 * HID * 96];
__device__ __align__(16) unsigned short g_wBp_lo[32 * HID * 96];
// Wo packed bf16: [k 1024][n 64]
__device__ __align__(16) unsigned short g_wo_hi[HID * OUTD];
__device__ __align__(16) unsigned short g_wo_lo[HID * OUTD];
// W_in packed bf16: [k 8000][n 1024]
__device__ __align__(16) unsigned short g_win_hi[(size_t)KIN * HID];
__device__ __align__(16) unsigned short g_win_lo[(size_t)KIN * HID];
// X (history flattened) bf16: [m 256][k 8000]
__device__ __align__(16) unsigned short g_x_hi[BS * KIN];
__device__ __align__(16) unsigned short g_x_lo[BS * KIN];

// ---------------- helpers ----------------
__device__ __forceinline__ float fast_sigmoid(float x) {
    return __fdividef(1.0f, 1.0f + __expf(-x));
}
__device__ __forceinline__ float fast_tanh(float x) {
    float e = __expf(2.0f * x);
    return 1.0f - __fdividef(2.0f, e + 1.0f);
}
__device__ __forceinline__ void split2(float x, unsigned short& h, unsigned short& l) {
    __nv_bfloat16 hb = __float2bfloat16(x);
    float hf = __bfloat162float(hb);
    __nv_bfloat16 lb = __float2bfloat16(x - hf);
    h = *reinterpret_cast<unsigned short*>(&hb);
    l = *reinterpret_cast<unsigned short*>(&lb);
}
__device__ __forceinline__ void split8(const float* src, uint4& H, uint4& L) {
    unsigned short* ph = (unsigned short*)&H;
    unsigned short* pl = (unsigned short*)&L;
    float4 v0 = *reinterpret_cast<const float4*>(src);
    float4 v1 = *reinterpret_cast<const float4*>(src + 4);
    split2(v0.x, ph[0], pl[0]); split2(v0.y, ph[1], pl[1]);
    split2(v0.z, ph[2], pl[2]); split2(v0.w, ph[3], pl[3]);
    split2(v1.x, ph[4], pl[4]); split2(v1.y, ph[5], pl[5]);
    split2(v1.z, ph[6], pl[6]); split2(v1.w, ph[7], pl[7]);
}

#define CP16(dst, src) asm volatile("cp.async.cg.shared.global [%0], [%1], 16;\n" :: "r"(dst), "l"(src))
#define CP_COMMIT()    asm volatile("cp.async.commit_group;\n")
#define CP_WAIT(n)     asm volatile("cp.async.wait_group %0;\n" :: "n"(n))

__device__ __forceinline__ uint32_t smem_u32(const void* p) {
    uint32_t a;
    asm("{ .reg .u64 t; cvta.to.shared.u64 t, %1; cvt.u32.u64 %0, t; }" : "=r"(a) : "l"(p));
    return a;
}
__device__ __forceinline__ void mma16816(float* c, const uint32_t* a, const uint32_t* b) {
    asm volatile("mma.sync.aligned.m16n8k16.row.col.f32.bf16.bf16.f32 "
        "{%0,%1,%2,%3}, {%4,%5,%6,%7}, {%8,%9}, {%0,%1,%2,%3};"
        : "+f"(c[0]), "+f"(c[1]), "+f"(c[2]), "+f"(c[3])
        : "r"(a[0]), "r"(a[1]), "r"(a[2]), "r"(a[3]), "r"(b[0]), "r"(b[1]));
}
#define LDSM4(r, addr)                                                          \
    asm volatile("ldmatrix.sync.aligned.m8n8.x4.shared.b16 {%0,%1,%2,%3}, [%4];"\
        : "=r"((r)[0]), "=r"((r)[1]), "=r"((r)[2]), "=r"((r)[3]) : "r"(addr))
#define LDSM4T(r, addr)                                                         \
    asm volatile("ldmatrix.sync.aligned.m8n8.x4.trans.shared.b16 {%0,%1,%2,%3}, [%4];" \
        : "=r"((r)[0]), "=r"((r)[1]), "=r"((r)[2]), "=r"((r)[3]) : "r"(addr))

// ===========================================================================
// k_prep: merged elementwise prep — barrier zero + cvtX + packWin + packWo.
// grid 5032 x 256, 8 elems/thread.
// ===========================================================================
#define NXV  ((size_t)BS * KIN / 8)          // 256000
#define NWV  ((size_t)KIN * HID / 8)         // 1024000
#define NOV  ((size_t)HID * OUTD / 8)        // 8192

__global__ void __launch_bounds__(256) k_prep(const float* __restrict__ X,
                                              const float* __restrict__ Win,
                                              const float* __restrict__ Wo) {
    if (blockIdx.x == 0 && threadIdx.x < 128) g_bars[threadIdx.x] = 0u;
    size_t vi = (size_t)blockIdx.x * 256 + threadIdx.x;
    uint4 H, L;
    if (vi < NXV) {
        size_t i = vi * 8;
        split8(X + i, H, L);
        *reinterpret_cast<uint4*>(g_x_hi + i) = H;
        *reinterpret_cast<uint4*>(g_x_lo + i) = L;
    } else if (vi < NXV + NWV) {
        size_t i = (vi - NXV) * 8;
        split8(Win + i, H, L);
        *reinterpret_cast<uint4*>(g_win_hi + i) = H;
        *reinterpret_cast<uint4*>(g_win_lo + i) = L;
    } else if (vi < NXV + NWV + NOV) {
        size_t i = (vi - NXV - NWV) * 8;
        split8(Wo + i, H, L);
        *reinterpret_cast<uint4*>(g_wo_hi + i) = H;
        *reinterpret_cast<uint4*>(g_wo_lo + i) = L;
    }
}

// ===========================================================================
// k_packW: Wh -> [32][1024][96] bf16 hi/lo, vectorized. grid (32,16), 256 thr.
// ===========================================================================
__global__ void __launch_bounds__(256) k_packW(const float* __restrict__ Wh) {
    const int s = blockIdx.x, kg = blockIdx.y;
    for (int i = threadIdx.x; i < 64 * 12; i += 256) {
        int k = kg * 64 + i / 12;
        int c8 = (i % 12) * 8;
        int sub = c8 / 48, rem = c8 % 48;
        int gate = rem / 16, h0 = rem % 16;
        const float* src = Wh + (size_t)k * G3 + gate * HID + s * 32 + sub * 16 + h0;
        uint4 H, L;
        split8(src, H, L);
        size_t d = ((size_t)s * HID + k) * 96 + c8;
        *reinterpret_cast<uint4*>(g_wBp_hi + d) = H;
        *reinterpret_cast<uint4*>(g_wBp_lo + d) = L;
    }
}

// ===========================================================================
// k_h0_mma2: split-K partials of X_bf16 @ Win_bf16.
// grid (16 ntile, 8 mtile, 2 kslice), 256 CTAs (2/SM), tile 32x64.
// kslice 0: chunks 0..62 (63), kslice 1: chunks 63..124 (62).
// ===========================================================================
#define H_AH 0
#define H_AL 4608
#define H_BH 9216
#define H_BL 18432
#define HSTG2 27648
#define SMEM_H0 (3 * HSTG2)     // 82944 -> 2 CTAs/SM

__global__ void __launch_bounds__(256) k_h0_mma2(float* __restrict__ H0P) {
    extern __shared__ char smem[];
    const uint32_t sb = smem_u32(smem);
    const int tid = threadIdx.x;
    const int w = tid >> 5, l = tid & 31;
    const int wm = w & 1;
    const int wn = w >> 1;
    const int lr = l >> 2;
    const int lc2 = (l & 3) * 2;
    const int m0 = blockIdx.y * 32, n0 = blockIdx.x * 64;
    const int z = blockIdx.z;
    const int c0 = z ? 63 : 0;
    const int nch = z ? 62 : 63;

    const int a_row  = wm * 16 + (l & 15);
    const int a_koff = (l >> 4) * 8;
    const int b_krow = l & 15;
    const int b_lhalf = (l >> 4) * 8;

    const char* srcAH = (const char*)(g_x_hi + (size_t)m0 * KIN);
    const char* srcAL = (const char*)(g_x_lo + (size_t)m0 * KIN);

    auto load = [&](int cha, int st) {   // cha = absolute chunk
        uint32_t base = sb + st * HSTG2;
        {
            int r = tid >> 3, sg = tid & 7;
            CP16(base + H_AH + r * 144 + sg * 16,
                 srcAH + (size_t)r * (KIN * 2) + cha * 128 + sg * 16);
            CP16(base + H_AL + r * 144 + sg * 16,
                 srcAL + (size_t)r * (KIN * 2) + cha * 128 + sg * 16);
        }
        #pragma unroll
        for (int i = tid; i < 512; i += 256) {
            int r = i >> 3, sg = i & 7;
            CP16(base + H_BH + r * 144 + sg * 16,
                 (const char*)g_win_hi + ((size_t)(cha * 64 + r) * HID + n0) * 2 + sg * 16);
            CP16(base + H_BL + r * 144 + sg * 16,
                 (const char*)g_win_lo + ((size_t)(cha * 64 + r) * HID + n0) * 2 + sg * 16);
        }
    };

    load(c0 + 0, 0); CP_COMMIT();
    load(c0 + 1, 1); CP_COMMIT();

    float c[2][4] = {};

    auto compute = [&](int st) {
        uint32_t base = sb + st * HSTG2;
        #pragma unroll
        for (int kk = 0; kk < 4; kk++) {
            const int k0 = kk * 16;
            uint32_t aH[4], aL[4];
            uint32_t adA = base + H_AH + a_row * 144 + (k0 + a_koff) * 2;
            LDSM4(aH, adA);
            LDSM4(aL, adA + (H_AL - H_AH));
            uint32_t bH[2][2], bL[2][2];
            uint32_t adB = base + H_BH + (k0 + b_krow) * 144 + (wn * 16 + b_lhalf) * 2;
            uint32_t r4[4];
            LDSM4T(r4, adB);
            bH[0][0] = r4[0]; bH[0][1] = r4[1]; bH[1][0] = r4[2]; bH[1][1] = r4[3];
            LDSM4T(r4, adB + (H_BL - H_BH));
            bL[0][0] = r4[0]; bL[0][1] = r4[1]; bL[1][0] = r4[2]; bL[1][1] = r4[3];
            #pragma unroll
            for (int g = 0; g < 2; g++) {
                mma16816(c[g], aH, bH[g]);
                mma16816(c[g], aH, bL[g]);
                mma16816(c[g], aL, bH[g]);
            }
        }
    };

    #pragma unroll 1
    for (int ch = 0; ch < nch; ch++) {
        CP_WAIT(1);
        __syncthreads();
        compute(ch % 3);
        if (ch + 2 < nch) load(c0 + ch + 2, (ch + 2) % 3);
        CP_COMMIT();
    }

    float* dst = H0P + (size_t)z * BS * HID;
    #pragma unroll
    for (int g = 0; g < 2; g++) {
        const int col = n0 + wn * 16 + g * 8 + lc2;
        #pragma unroll
        for (int rr = 0; rr < 2; rr++) {
            const int m = m0 + wm * 16 + lr + rr * 8;
            *reinterpret_cast<float2*>(dst + (size_t)m * HID + col) =
                make_float2(c[g][2 * rr], c[g][2 * rr + 1]);
        }
    }
}

// ===========================================================================
// k_h0fix: h0 = relu(p0 + p1 + b_in); writes fp32 + bf16 image. grid 128x256.
// ===========================================================================
__global__ void __launch_bounds__(256) k_h0fix(const float* __restrict__ b_in) {
    size_t i = ((size_t)blockIdx.x * 256 + threadIdx.x) * 8;
    float r[8];
    #pragma unroll
    for (int j = 0; j < 8; j += 4) {
        float4 a = *reinterpret_cast<const float4*>(g_h0p + i + j);
        float4 b = *reinterpret_cast<const float4*>(g_h0p + BS * HID + i + j);
        float4 bb = *reinterpret_cast<const float4*>(b_in + ((i + j) & (HID - 1)));
        r[j + 0] = a.x + b.x + bb.x;
        r[j + 1] = a.y + b.y + bb.y;
        r[j + 2] = a.z + b.z + bb.z;
        r[j + 3] = a.w + b.w + bb.w;
    }
    #pragma unroll
    for (int j = 0; j < 8; j++) r[j] = r[j] > 0.f ? r[j] : 0.f;
    *reinterpret_cast<float4*>(g_h0 + i)     = make_float4(r[0], r[1], r[2], r[3]);
    *reinterpret_cast<float4*>(g_h0 + i + 4) = make_float4(r[4], r[5], r[6], r[7]);
    uint4 H, L;
    unsigned short* ph = (unsigned short*)&H;
    unsigned short* pl = (unsigned short*)&L;
    #pragma unroll
    for (int j = 0; j < 8; j++) split2(r[j], ph[j], pl[j]);
    *reinterpret_cast<uint4*>(g_h0b_hi + i) = H;
    *reinterpret_cast<uint4*>(g_h0b_lo + i) = L;
}

// ===========================================================================
// k_steps_mma (unchanged from R13)
// ===========================================================================
#define OFF_AH 0
#define OFF_AL 9216
#define OFF_BH 18432
#define OFF_BL 31744
#define STG_B  45056
#define APITCH_B 144
#define BPITCH_B 208
#define SM_WI  (3 * STG_B)
#define SM_AS  (SM_WI + 96 * 36 * 4)
#define SMEM_MMA (SM_AS + 2 * 64 * 36 * 4)  // 167424 B

__global__ void __launch_bounds__(256, 1) k_steps_mma(const float* __restrict__ h0,
                                                      const float* __restrict__ action,
                                                      const float* __restrict__ Wi,
                                                      const float* __restrict__ bi,
                                                      const float* __restrict__ bhn) {
    extern __shared__ char smem[];
    const uint32_t sb = smem_u32(smem);
    float* wi_s = reinterpret_cast<float*>(smem + SM_WI);
    float* a_s  = reinterpret_cast<float*>(smem + SM_AS);

    const int tid = threadIdx.x;
    const int w = tid >> 5, l = tid & 31;
    const int s = blockIdx.x;
    const int mq = blockIdx.y;
    const int wm = w & 3;
    const int wn = w >> 2;
    const int lr = l >> 2;
    const int lc2 = (l & 3) * 2;

    const int a_row  = wm * 16 + (l & 15);
    const int a_koff = (l >> 4) * 8;
    const int b_krow = l & 15;
    const int b_noff = wn * 48 + (l >> 4) * 8;

    const int hidbase = s * 32 + wn * 16;

    float bh[2][2];
    #pragma unroll
    for (int pp = 0; pp < 2; pp++) {
        float2 v = *reinterpret_cast<const float2*>(bhn + hidbase + pp * 8 + lc2);
        bh[pp][0] = v.x; bh[pp][1] = v.y;
    }
    float hpreg[2][2][2];
    #pragma unroll
    for (int rr = 0; rr < 2; rr++) {
        const int m = mq * 64 + wm * 16 + lr + rr * 8;
        #pragma unroll
        for (int pp = 0; pp < 2; pp++) {
            float2 v = *reinterpret_cast<const float2*>(h0 + (size_t)m * HID + hidbase + pp * 8 + lc2);
            hpreg[rr][pp][0] = v.x; hpreg[rr][pp][1] = v.y;
        }
    }

    for (int i = tid; i < 96 * 32; i += 256) {
        int col = i >> 5, k = i & 31;
        int gate = col >> 5, cl = col & 31;
        wi_s[col * 36 + k] = Wi[(size_t)k * G3 + gate * HID + s * 32 + cl];
    }
    __syncthreads();

    const char* srcBH = (const char*)(g_wBp_hi + (size_t)s * HID * 96);
    const char* srcBL = (const char*)(g_wBp_lo + (size_t)s * HID * 96);

    auto load_B = [&](int ch, int st) {
        uint32_t base = sb + st * STG_B;
        #pragma unroll
        for (int i = tid; i < 768; i += 256) {
            int r = i / 12, sg = i % 12;
            CP16(base + OFF_BH + r * BPITCH_B + sg * 16,
                 srcBH + ((size_t)(ch * 64 + r)) * 192 + sg * 16);
            CP16(base + OFF_BL + r * BPITCH_B + sg * 16,
                 srcBL + ((size_t)(ch * 64 + r)) * 192 + sg * 16);
        }
    };
    auto load_act = [&](int tt) {
        uint32_t ab = sb + SM_AS + (tt & 1) * (64 * 36 * 4);
        #pragma unroll
        for (int i = tid; i < 512; i += 256) {
            int row = i >> 3, seg = i & 7;
            const float* src = action + ((size_t)(mq * 64 + row) * NT + tt) * ACT + seg * 4;
            CP16(ab + row * 144 + seg * 16, src);
        }
    };

    load_B(0, 0); load_act(0); CP_COMMIT();
    load_B(1, 1); CP_COMMIT();

    #pragma unroll 1
    for (int t = 0; t < NT; t++) {
        const unsigned short* hsH = (t == 0) ? g_h0b_hi : g_obf_hi + (size_t)(t - 1) * BS * HID;
        const unsigned short* hsL = (t == 0) ? g_h0b_lo : g_obf_lo + (size_t)(t - 1) * BS * HID;
        const char* srcAH = (const char*)(hsH + (size_t)mq * 64 * HID);
        const char* srcAL = (const char*)(hsL + (size_t)mq * 64 * HID);

        auto load_A = [&](int ch, int st) {
            uint32_t base = sb + st * STG_B;
            #pragma unroll
            for (int i = tid; i < 512; i += 256) {
                int row = i >> 3, seg = i & 7;
                CP16(base + OFF_AH + row * APITCH_B + seg * 16,
                     srcAH + (size_t)row * (HID * 2) + ch * 128 + seg * 16);
                CP16(base + OFF_AL + row * APITCH_B + seg * 16,
                     srcAL + (size_t)row * (HID * 2) + ch * 128 + seg * 16);
            }
        };

        if (t > 0) {
            if (tid == 0) {
                unsigned* ctr = &g_bars[mq * 32];
                const unsigned target = 32u * (unsigned)t;
                atomicAdd(ctr, 1u);
                unsigned v;
                do {
                    asm volatile("ld.volatile.global.u32 %0, [%1];" : "=r"(v) : "l"(ctr));
                } while (v < target);
            }
            __syncthreads();
            __threadfence();
        }

        load_A(0, 0); CP_COMMIT();
        load_A(1, 1); CP_COMMIT();

        // ---- fused input GEMM (hoisted; gated on act group) ----
        CP_WAIT(3);
        __syncthreads();
        float giv[2][12];
        #pragma unroll
        for (int gate = 0; gate < 3; gate++)
            #pragma unroll
            for (int pp = 0; pp < 2; pp++) {
                float2 v = *reinterpret_cast<const float2*>(bi + gate * HID + hidbase + pp * 8 + lc2);
                giv[0][gate * 4 + pp * 2 + 0] = v.x;
                giv[0][gate * 4 + pp * 2 + 1] = v.y;
                giv[1][gate * 4 + pp * 2 + 0] = v.x;
                giv[1][gate * 4 + pp * 2 + 1] = v.y;
            }
        {
            const float* ab = a_s + (t & 1) * (64 * 36);
            const float* r0 = ab + (wm * 16 + lr) * 36;
            const float* r1 = r0 + 8 * 36;
            #pragma unroll
            for (int k4 = 0; k4 < 8; k4++) {
                float4 a0 = *reinterpret_cast<const float4*>(r0 + k4 * 4);
                float4 a1 = *reinterpret_cast<const float4*>(r1 + k4 * 4);
                #pragma unroll
                for (int gate = 0; gate < 3; gate++)
                    #pragma unroll
                    for (int pp = 0; pp < 2; pp++)
                        #pragma unroll
                        for (int e = 0; e < 2; e++) {
                            int col = gate * 32 + wn * 16 + pp * 8 + lc2 + e;
                            float4 wv = *reinterpret_cast<const float4*>(wi_s + col * 36 + k4 * 4);
                            int j = gate * 4 + pp * 2 + e;
                            giv[0][j] += a0.x * wv.x + a0.y * wv.y + a0.z * wv.z + a0.w * wv.w;
                            giv[1][j] += a1.x * wv.x + a1.y * wv.y + a1.z * wv.z + a1.w * wv.w;
                        }
            }
        }

        float c[6][4] = {};

        auto compute = [&](int st) {
            uint32_t base = sb + st * STG_B;
            #pragma unroll
            for (int kk = 0; kk < 4; kk++) {
                const int k0 = kk * 16;
                uint32_t aH[4], aL[4];
                uint32_t adA = base + OFF_AH + a_row * APITCH_B + (k0 + a_koff) * 2;
                LDSM4(aH, adA);
                LDSM4(aL, adA + (OFF_AL - OFF_AH));
                uint32_t bH[6][2], bL[6][2];
                #pragma unroll
                for (int g2 = 0; g2 < 3; g2++) {
                    uint32_t adB = base + OFF_BH + (k0 + b_krow) * BPITCH_B + (b_noff + g2 * 16) * 2;
                    uint32_t r4[4];
                    LDSM4T(r4, adB);
                    bH[g2 * 2][0] = r4[0]; bH[g2 * 2][1] = r4[1];
                    bH[g2 * 2 + 1][0] = r4[2]; bH[g2 * 2 + 1][1] = r4[3];
                    LDSM4T(r4, adB + (OFF_BL - OFF_BH));
                    bL[g2 * 2][0] = r4[0]; bL[g2 * 2][1] = r4[1];
                    bL[g2 * 2 + 1][0] = r4[2]; bL[g2 * 2 + 1][1] = r4[3];
                }
                #pragma unroll
                for (int g = 0; g < 6; g++) {
                    mma16816(c[g], aH, bH[g]);
                    mma16816(c[g], aH, bL[g]);
                    mma16816(c[g], aL, bH[g]);
                }
            }
        };

        #pragma unroll 1
        for (int ch = 0; ch < 16; ch++) {
            CP_WAIT(1);
            __syncthreads();
            compute(ch % 3);
            if (ch + 2 < 16) {
                int st2 = (ch + 2) % 3;
                load_A(ch + 2, st2);
                load_B(ch + 2, st2);
            }
            CP_COMMIT();
        }
        __syncthreads();

        if (t + 1 < NT) {
            load_B(0, 0); load_act(t + 1); CP_COMMIT();
            load_B(1, 1); CP_COMMIT();
        }

        // ---- epilogue: gates+blend; single bf16 hi/lo store ----
        #pragma unroll
        for (int rr = 0; rr < 2; rr++) {
            const int m = mq * 64 + wm * 16 + lr + rr * 8;
            #pragma unroll
            for (int pp = 0; pp < 2; pp++) {
                const int hid = hidbase + pp * 8 + lc2;
                float h[2];
                #pragma unroll
                for (int e = 0; e < 2; e++) {
                    float rv = c[pp][2 * rr + e];
                    float zv = c[2 + pp][2 * rr + e];
                    float nv = c[4 + pp][2 * rr + e];
                    float rg = fast_sigmoid(rv + giv[rr][0 * 4 + pp * 2 + e]);
                    float zg = fast_sigmoid(zv + giv[rr][1 * 4 + pp * 2 + e]);
                    float ng = fast_tanh(giv[rr][2 * 4 + pp * 2 + e] + rg * (nv + bh[pp][e]));
                    h[e] = (1.0f - zg) * ng + zg * hpreg[rr][pp][e];
                    hpreg[rr][pp][e] = h[e];
                }
                size_t d = ((size_t)t * BS + m) * HID + hid;
                unsigned short hi0, hi1, lo0, lo1;
                split2(h[0], hi0, lo0);
                split2(h[1], hi1, lo1);
                *reinterpret_cast<uint32_t*>(g_obf_hi + d) = ((uint32_t)hi1 << 16) | hi0;
                *reinterpret_cast<uint32_t*>(g_obf_lo + d) = ((uint32_t)lo1 << 16) | lo0;
            }
        }

        if (t + 1 < NT) {
            __threadfence();
            __syncthreads();
        }
    }
}

// ===========================================================================
// k_out_mma (unchanged from R13)
// ===========================================================================
#define O_AH 0
#define O_AL 9216
#define O_BH 18432
#define O_BL 27648
#define OSTG 36864
#define O_PITCH 144
#define SMEM_OUT (3 * OSTG)

__global__ void __launch_bounds__(256) k_out_mma(const float* __restrict__ bo,
                                                 float* __restrict__ out) {
    extern __shared__ char smem[];
    const uint32_t sb = smem_u32(smem);
    const int tid = threadIdx.x;
    const int w = tid >> 5, l = tid & 31;
    const int wm = w & 3;
    const int wn = w >> 2;
    const int lr = l >> 2;
    const int lc2 = (l & 3) * 2;
    const int R0 = blockIdx.x * 64;

    const int a_row  = wm * 16 + (l & 15);
    const int a_koff = (l >> 4) * 8;
    const int b_krow = l & 15;
    const int b_lhalf = (l >> 4) * 8;

    const char* srcAH = (const char*)(g_obf_hi + (size_t)R0 * HID);
    const char* srcAL = (const char*)(g_obf_lo + (size_t)R0 * HID);

    auto load = [&](int ch, int st) {
        uint32_t base = sb + st * OSTG;
        #pragma unroll
        for (int i = tid; i < 512; i += 256) {
            int r = i >> 3, sg = i & 7;
            CP16(base + O_AH + r * O_PITCH + sg * 16,
                 srcAH + (size_t)r * (HID * 2) + ch * 128 + sg * 16);
            CP16(base + O_AL + r * O_PITCH + sg * 16,
                 srcAL + (size_t)r * (HID * 2) + ch * 128 + sg * 16);
        }
        #pragma unroll
        for (int i = tid; i < 512; i += 256) {
            int r = i >> 3, sg = i & 7;
            CP16(base + O_BH + r * O_PITCH + sg * 16,
                 (const char*)g_wo_hi + ((size_t)(ch * 64 + r) * OUTD) * 2 + sg * 16);
            CP16(base + O_BL + r * O_PITCH + sg * 16,
                 (const char*)g_wo_lo + ((size_t)(ch * 64 + r) * OUTD) * 2 + sg * 16);
        }
    };

    load(0, 0); CP_COMMIT();
    load(1, 1); CP_COMMIT();

    float c[4][4] = {};

    auto compute = [&](int st) {
        uint32_t base = sb + st * OSTG;
        #pragma unroll
        for (int kk = 0; kk < 4; kk++) {
            const int k0 = kk * 16;
            uint32_t aH[4], aL[4];
            uint32_t adA = base + O_AH + a_row * O_PITCH + (k0 + a_koff) * 2;
            LDSM4(aH, adA);
            LDSM4(aL, adA + (O_AL - O_AH));
            uint32_t bH[4][2], bL[4][2];
            #pragma unroll
            for (int n16 = 0; n16 < 2; n16++) {
                uint32_t adB = base + O_BH + (k0 + b_krow) * O_PITCH
                             + (wn * 32 + n16 * 16 + b_lhalf) * 2;
                uint32_t r4[4];
                LDSM4T(r4, adB);
                bH[n16 * 2][0] = r4[0]; bH[n16 * 2][1] = r4[1];
                bH[n16 * 2 + 1][0] = r4[2]; bH[n16 * 2 + 1][1] = r4[3];
                LDSM4T(r4, adB + (O_BL - O_BH));
                bL[n16 * 2][0] = r4[0]; bL[n16 * 2][1] = r4[1];
                bL[n16 * 2 + 1][0] = r4[2]; bL[n16 * 2 + 1][1] = r4[3];
            }
            #pragma unroll
            for (int g = 0; g < 4; g++) {
                mma16816(c[g], aH, bH[g]);
                mma16816(c[g], aH, bL[g]);
                mma16816(c[g], aL, bH[g]);
            }
        }
    };

    #pragma unroll 1
    for (int ch = 0; ch < 16; ch++) {
        CP_WAIT(1);
        __syncthreads();
        compute(ch % 3);
        if (ch + 2 < 16) load(ch + 2, (ch + 2) % 3);
        CP_COMMIT();
    }

    #pragma unroll
    for (int g = 0; g < 4; g++) {
        const int col = wn * 32 + g * 8 + lc2;
        float2 bov = *reinterpret_cast<const float2*>(bo + col);
        #pragma unroll
        for (int rr = 0; rr < 2; rr++) {
            int R = R0 + wm * 16 + lr + rr * 8;
            int tt = R >> 8;
            int b  = R & (BS - 1);
            float2 o = make_float2(c[g][2 * rr] + bov.x, c[g][2 * rr + 1] + bov.y);
            *reinterpret_cast<float2*>(out + ((size_t)b * NT + tt) * OUTD + col) = o;
        }
    }
}

extern "C" void kernel_launch(void* const* d_in, const int* in_sizes, int n_in,
                              void* d_out, int out_size) {
    const float* history = (const float*)d_in[0];
    const float* action  = (const float*)d_in[1];
    const float* W_in    = (const float*)d_in[2];
    const float* b_in    = (const float*)d_in[3];
    const float* Wi      = (const float*)d_in[4];
    const float* bi      = (const float*)d_in[5];
    const float* Wh      = (const float*)d_in[6];
    const float* bhn     = (const float*)d_in[7];
    const float* Wo      = (const float*)d_in[8];
    const float* bo      = (const float*)d_in[9];
    float* out = (float*)d_out;

    float *h0buf = nullptr, *h0pbuf = nullptr;
    cudaGetSymbolAddress((void**)&h0buf, g_h0);
    cudaGetSymbolAddress((void**)&h0pbuf, g_h0p);

    cudaFuncSetAttribute(k_h0_mma2, cudaFuncAttributeMaxDynamicSharedMemorySize, SMEM_H0);
    cudaFuncSetAttribute(k_steps_mma, cudaFuncAttributeMaxDynamicSharedMemorySize, SMEM_MMA);
    cudaFuncSetAttribute(k_out_mma, cudaFuncAttributeMaxDynamicSharedMemorySize, SMEM_OUT);

    k_prep<<<5032, 256>>>(history, W_in, Wo);
    k_packW<<<dim3(32, 16), 256>>>(Wh);

    k_h0_mma2<<<dim3(HID / 64, BS / 32, 2), 256, SMEM_H0>>>(h0pbuf);
    k_h0fix<<<BS * HID / (256 * 8), 256>>>(b_in);

    k_steps_mma<<<dim3(32, 4), 256, SMEM_MMA>>>(h0buf, action, Wi, bi, bhn);

    k_out_mma<<<NT * BS / 64, 256, SMEM_OUT>>>(bo, out);
}

// round 15
// speedup vs baseline: 1.7771x; 1.0052x over previous
#include <cuda_runtime.h>
#include <cuda_bf16.h>
#include <cstdint>
#include <cstddef>

#define BS   256
#define HID  1024
#define NT   100
#define ACT  32
#define KIN  8000
#define G3   3072
#define OUTD 64

// ---------------- device scratch (allocation-free rule) ----------------
__device__ float g_h0[BS * HID];
__device__ float g_h0p[2 * BS * HID];               // split-K partials
__device__ unsigned g_bars[4 * 32];

// h history bf16 hi/lo: [t][b][hid] (A source AND k_out input)
__device__ __align__(16) unsigned short g_obf_hi[(size_t)NT * BS * HID];
__device__ __align__(16) unsigned short g_obf_lo[(size_t)NT * BS * HID];
// h0 bf16 image
__device__ __align__(16) unsigned short g_h0b_hi[BS * HID];
__device__ __align__(16) unsigned short g_h0b_lo[BS * HID];
// Wh packed bf16: [slice 32][k 1024][col 96], col = sub*48+gate*16+h16
__device__ __align__(16) unsigned short g_wBp_hi[32 * HID * 96];
__device__ __align__(16) unsigned short g_wBp_lo[32 * HID * 96];
// Wo packed bf16: [k 1024][n 64]
__device__ __align__(16) unsigned short g_wo_hi[HID * OUTD];
__device__ __align__(16) unsigned short g_wo_lo[HID * OUTD];
// W_in packed bf16: [k 8000][n 1024]
__device__ __align__(16) unsigned short g_win_hi[(size_t)KIN * HID];
__device__ __align__(16) unsigned short g_win_lo[(size_t)KIN * HID];
// X (history flattened) bf16: [m 256][k 8000]
__device__ __align__(16) unsigned short g_x_hi[BS * KIN];
__device__ __align__(16) unsigned short g_x_lo[BS * KIN];

// ---------------- helpers ----------------
__device__ __forceinline__ float fast_sigmoid(float x) {
    return __fdividef(1.0f, 1.0f + __expf(-x));
}
__device__ __forceinline__ float fast_tanh(float x) {
    float e = __expf(2.0f * x);
    return 1.0f - __fdividef(2.0f, e + 1.0f);
}
__device__ __forceinline__ void split2(float x, unsigned short& h, unsigned short& l) {
    __nv_bfloat16 hb = __float2bfloat16(x);
    float hf = __bfloat162float(hb);
    __nv_bfloat16 lb = __float2bfloat16(x - hf);
    h = *reinterpret_cast<unsigned short*>(&hb);
    l = *reinterpret_cast<unsigned short*>(&lb);
}
__device__ __forceinline__ void split8(const float* src, uint4& H, uint4& L) {
    unsigned short* ph = (unsigned short*)&H;
    unsigned short* pl = (unsigned short*)&L;
    float4 v0 = *reinterpret_cast<const float4*>(src);
    float4 v1 = *reinterpret_cast<const float4*>(src + 4);
    split2(v0.x, ph[0], pl[0]); split2(v0.y, ph[1], pl[1]);
    split2(v0.z, ph[2], pl[2]); split2(v0.w, ph[3], pl[3]);
    split2(v1.x, ph[4], pl[4]); split2(v1.y, ph[5], pl[5]);
    split2(v1.z, ph[6], pl[6]); split2(v1.w, ph[7], pl[7]);
}

#define CP16(dst, src) asm volatile("cp.async.cg.shared.global [%0], [%1], 16;\n" :: "r"(dst), "l"(src))
#define CP_COMMIT()    asm volatile("cp.async.commit_group;\n")
#define CP_WAIT(n)     asm volatile("cp.async.wait_group %0;\n" :: "n"(n))

__device__ __forceinline__ uint32_t smem_u32(const void* p) {
    uint32_t a;
    asm("{ .reg .u64 t; cvta.to.shared.u64 t, %1; cvt.u32.u64 %0, t; }" : "=r"(a) : "l"(p));
    return a;
}
__device__ __forceinline__ void mma16816(float* c, const uint32_t* a, const uint32_t* b) {
    asm volatile("mma.sync.aligned.m16n8k16.row.col.f32.bf16.bf16.f32 "
        "{%0,%1,%2,%3}, {%4,%5,%6,%7}, {%8,%9}, {%0,%1,%2,%3};"
        : "+f"(c[0]), "+f"(c[1]), "+f"(c[2]), "+f"(c[3])
        : "r"(a[0]), "r"(a[1]), "r"(a[2]), "r"(a[3]), "r"(b[0]), "r"(b[1]));
}
#define LDSM4(r, addr)                                                          \
    asm volatile("ldmatrix.sync.aligned.m8n8.x4.shared.b16 {%0,%1,%2,%3}, [%4];"\
        : "=r"((r)[0]), "=r"((r)[1]), "=r"((r)[2]), "=r"((r)[3]) : "r"(addr))
#define LDSM4T(r, addr)                                                         \
    asm volatile("ldmatrix.sync.aligned.m8n8.x4.trans.shared.b16 {%0,%1,%2,%3}, [%4];" \
        : "=r"((r)[0]), "=r"((r)[1]), "=r"((r)[2]), "=r"((r)[3]) : "r"(addr))

// ===========================================================================
// k_prep: merged elementwise prep — barrier zero + cvtX + packWin + packWo.
// ===========================================================================
#define NXV  ((size_t)BS * KIN / 8)
#define NWV  ((size_t)KIN * HID / 8)
#define NOV  ((size_t)HID * OUTD / 8)

__global__ void __launch_bounds__(256) k_prep(const float* __restrict__ X,
                                              const float* __restrict__ Win,
                                              const float* __restrict__ Wo) {
    if (blockIdx.x == 0 && threadIdx.x < 128) g_bars[threadIdx.x] = 0u;
    size_t vi = (size_t)blockIdx.x * 256 + threadIdx.x;
    uint4 H, L;
    if (vi < NXV) {
        size_t i = vi * 8;
        split8(X + i, H, L);
        *reinterpret_cast<uint4*>(g_x_hi + i) = H;
        *reinterpret_cast<uint4*>(g_x_lo + i) = L;
    } else if (vi < NXV + NWV) {
        size_t i = (vi - NXV) * 8;
        split8(Win + i, H, L);
        *reinterpret_cast<uint4*>(g_win_hi + i) = H;
        *reinterpret_cast<uint4*>(g_win_lo + i) = L;
    } else if (vi < NXV + NWV + NOV) {
        size_t i = (vi - NXV - NWV) * 8;
        split8(Wo + i, H, L);
        *reinterpret_cast<uint4*>(g_wo_hi + i) = H;
        *reinterpret_cast<uint4*>(g_wo_lo + i) = L;
    }
}

// ===========================================================================
// k_packW: Wh -> [32][1024][96] bf16 hi/lo, vectorized. grid (32,16), 256 thr.
// ===========================================================================
__global__ void __launch_bounds__(256) k_packW(const float* __restrict__ Wh) {
    const int s = blockIdx.x, kg = blockIdx.y;
    for (int i = threadIdx.x; i < 64 * 12; i += 256) {
        int k = kg * 64 + i / 12;
        int c8 = (i % 12) * 8;
        int sub = c8 / 48, rem = c8 % 48;
        int gate = rem / 16, h0 = rem % 16;
        const float* src = Wh + (size_t)k * G3 + gate * HID + s * 32 + sub * 16 + h0;
        uint4 H, L;
        split8(src, H, L);
        size_t d = ((size_t)s * HID + k) * 96 + c8;
        *reinterpret_cast<uint4*>(g_wBp_hi + d) = H;
        *reinterpret_cast<uint4*>(g_wBp_lo + d) = L;
    }
}

// ===========================================================================
// k_h0_mma2: split-K partials of X_bf16 @ Win_bf16. (unchanged from R14)
// ===========================================================================
#define H_AH 0
#define H_AL 4608
#define H_BH 9216
#define H_BL 18432
#define HSTG2 27648
#define SMEM_H0 (3 * HSTG2)

__global__ void __launch_bounds__(256) k_h0_mma2(float* __restrict__ H0P) {
    extern __shared__ char smem[];
    const uint32_t sb = smem_u32(smem);
    const int tid = threadIdx.x;
    const int w = tid >> 5, l = tid & 31;
    const int wm = w & 1;
    const int wn = w >> 1;
    const int lr = l >> 2;
    const int lc2 = (l & 3) * 2;
    const int m0 = blockIdx.y * 32, n0 = blockIdx.x * 64;
    const int z = blockIdx.z;
    const int c0 = z ? 63 : 0;
    const int nch = z ? 62 : 63;

    const int a_row  = wm * 16 + (l & 15);
    const int a_koff = (l >> 4) * 8;
    const int b_krow = l & 15;
    const int b_lhalf = (l >> 4) * 8;

    const char* srcAH = (const char*)(g_x_hi + (size_t)m0 * KIN);
    const char* srcAL = (const char*)(g_x_lo + (size_t)m0 * KIN);

    auto load = [&](int cha, int st) {
        uint32_t base = sb + st * HSTG2;
        {
            int r = tid >> 3, sg = tid & 7;
            CP16(base + H_AH + r * 144 + sg * 16,
                 srcAH + (size_t)r * (KIN * 2) + cha * 128 + sg * 16);
            CP16(base + H_AL + r * 144 + sg * 16,
                 srcAL + (size_t)r * (KIN * 2) + cha * 128 + sg * 16);
        }
        #pragma unroll
        for (int i = tid; i < 512; i += 256) {
            int r = i >> 3, sg = i & 7;
            CP16(base + H_BH + r * 144 + sg * 16,
                 (const char*)g_win_hi + ((size_t)(cha * 64 + r) * HID + n0) * 2 + sg * 16);
            CP16(base + H_BL + r * 144 + sg * 16,
                 (const char*)g_win_lo + ((size_t)(cha * 64 + r) * HID + n0) * 2 + sg * 16);
        }
    };

    load(c0 + 0, 0); CP_COMMIT();
    load(c0 + 1, 1); CP_COMMIT();

    float c[2][4] = {};

    auto compute = [&](int st) {
        uint32_t base = sb + st * HSTG2;
        #pragma unroll
        for (int kk = 0; kk < 4; kk++) {
            const int k0 = kk * 16;
            uint32_t aH[4], aL[4];
            uint32_t adA = base + H_AH + a_row * 144 + (k0 + a_koff) * 2;
            LDSM4(aH, adA);
            LDSM4(aL, adA + (H_AL - H_AH));
            uint32_t bH[2][2], bL[2][2];
            uint32_t adB = base + H_BH + (k0 + b_krow) * 144 + (wn * 16 + b_lhalf) * 2;
            uint32_t r4[4];
            LDSM4T(r4, adB);
            bH[0][0] = r4[0]; bH[0][1] = r4[1]; bH[1][0] = r4[2]; bH[1][1] = r4[3];
            LDSM4T(r4, adB + (H_BL - H_BH));
            bL[0][0] = r4[0]; bL[0][1] = r4[1]; bL[1][0] = r4[2]; bL[1][1] = r4[3];
            #pragma unroll
            for (int g = 0; g < 2; g++) {
                mma16816(c[g], aH, bH[g]);
                mma16816(c[g], aH, bL[g]);
                mma16816(c[g], aL, bH[g]);
            }
        }
    };

    #pragma unroll 1
    for (int ch = 0; ch < nch; ch++) {
        CP_WAIT(1);
        __syncthreads();
        compute(ch % 3);
        if (ch + 2 < nch) load(c0 + ch + 2, (ch + 2) % 3);
        CP_COMMIT();
    }

    float* dst = H0P + (size_t)z * BS * HID;
    #pragma unroll
    for (int g = 0; g < 2; g++) {
        const int col = n0 + wn * 16 + g * 8 + lc2;
        #pragma unroll
        for (int rr = 0; rr < 2; rr++) {
            const int m = m0 + wm * 16 + lr + rr * 8;
            *reinterpret_cast<float2*>(dst + (size_t)m * HID + col) =
                make_float2(c[g][2 * rr], c[g][2 * rr + 1]);
        }
    }
}

// ===========================================================================
// k_h0fix (unchanged from R14)
// ===========================================================================
__global__ void __launch_bounds__(256) k_h0fix(const float* __restrict__ b_in) {
    size_t i = ((size_t)blockIdx.x * 256 + threadIdx.x) * 8;
    float r[8];
    #pragma unroll
    for (int j = 0; j < 8; j += 4) {
        float4 a = *reinterpret_cast<const float4*>(g_h0p + i + j);
        float4 b = *reinterpret_cast<const float4*>(g_h0p + BS * HID + i + j);
        float4 bb = *reinterpret_cast<const float4*>(b_in + ((i + j) & (HID - 1)));
        r[j + 0] = a.x + b.x + bb.x;
        r[j + 1] = a.y + b.y + bb.y;
        r[j + 2] = a.z + b.z + bb.z;
        r[j + 3] = a.w + b.w + bb.w;
    }
    #pragma unroll
    for (int j = 0; j < 8; j++) r[j] = r[j] > 0.f ? r[j] : 0.f;
    *reinterpret_cast<float4*>(g_h0 + i)     = make_float4(r[0], r[1], r[2], r[3]);
    *reinterpret_cast<float4*>(g_h0 + i + 4) = make_float4(r[4], r[5], r[6], r[7]);
    uint4 H, L;
    unsigned short* ph = (unsigned short*)&H;
    unsigned short* pl = (unsigned short*)&L;
    #pragma unroll
    for (int j = 0; j < 8; j++) split2(r[j], ph[j], pl[j]);
    *reinterpret_cast<uint4*>(g_h0b_hi + i) = H;
    *reinterpret_cast<uint4*>(g_h0b_lo + i) = L;
}

// ===========================================================================
// k_steps_mma v8: gi GEMM interleaved into the chunk loop (1 k4-slice per
// chunk for ch<8), upfront gating sync removed.
// ===========================================================================
#define OFF_AH 0
#define OFF_AL 9216
#define OFF_BH 18432
#define OFF_BL 31744
#define STG_B  45056
#define APITCH_B 144
#define BPITCH_B 208
#define SM_WI  (3 * STG_B)
#define SM_AS  (SM_WI + 96 * 36 * 4)
#define SMEM_MMA (SM_AS + 2 * 64 * 36 * 4)  // 167424 B

__global__ void __launch_bounds__(256, 1) k_steps_mma(const float* __restrict__ h0,
                                                      const float* __restrict__ action,
                                                      const float* __restrict__ Wi,
                                                      const float* __restrict__ bi,
                                                      const float* __restrict__ bhn) {
    extern __shared__ char smem[];
    const uint32_t sb = smem_u32(smem);
    float* wi_s = reinterpret_cast<float*>(smem + SM_WI);
    float* a_s  = reinterpret_cast<float*>(smem + SM_AS);

    const int tid = threadIdx.x;
    const int w = tid >> 5, l = tid & 31;
    const int s = blockIdx.x;
    const int mq = blockIdx.y;
    const int wm = w & 3;
    const int wn = w >> 2;
    const int lr = l >> 2;
    const int lc2 = (l & 3) * 2;

    const int a_row  = wm * 16 + (l & 15);
    const int a_koff = (l >> 4) * 8;
    const int b_krow = l & 15;
    const int b_noff = wn * 48 + (l >> 4) * 8;

    const int hidbase = s * 32 + wn * 16;

    float bh[2][2];
    #pragma unroll
    for (int pp = 0; pp < 2; pp++) {
        float2 v = *reinterpret_cast<const float2*>(bhn + hidbase + pp * 8 + lc2);
        bh[pp][0] = v.x; bh[pp][1] = v.y;
    }
    float hpreg[2][2][2];
    #pragma unroll
    for (int rr = 0; rr < 2; rr++) {
        const int m = mq * 64 + wm * 16 + lr + rr * 8;
        #pragma unroll
        for (int pp = 0; pp < 2; pp++) {
            float2 v = *reinterpret_cast<const float2*>(h0 + (size_t)m * HID + hidbase + pp * 8 + lc2);
            hpreg[rr][pp][0] = v.x; hpreg[rr][pp][1] = v.y;
        }
    }

    for (int i = tid; i < 96 * 32; i += 256) {
        int col = i >> 5, k = i & 31;
        int gate = col >> 5, cl = col & 31;
        wi_s[col * 36 + k] = Wi[(size_t)k * G3 + gate * HID + s * 32 + cl];
    }
    __syncthreads();

    const char* srcBH = (const char*)(g_wBp_hi + (size_t)s * HID * 96);
    const char* srcBL = (const char*)(g_wBp_lo + (size_t)s * HID * 96);

    auto load_B = [&](int ch, int st) {
        uint32_t base = sb + st * STG_B;
        #pragma unroll
        for (int i = tid; i < 768; i += 256) {
            int r = i / 12, sg = i % 12;
            CP16(base + OFF_BH + r * BPITCH_B + sg * 16,
                 srcBH + ((size_t)(ch * 64 + r)) * 192 + sg * 16);
            CP16(base + OFF_BL + r * BPITCH_B + sg * 16,
                 srcBL + ((size_t)(ch * 64 + r)) * 192 + sg * 16);
        }
    };
    auto load_act = [&](int tt) {
        uint32_t ab = sb + SM_AS + (tt & 1) * (64 * 36 * 4);
        #pragma unroll
        for (int i = tid; i < 512; i += 256) {
            int row = i >> 3, seg = i & 7;
            const float* src = action + ((size_t)(mq * 64 + row) * NT + tt) * ACT + seg * 4;
            CP16(ab + row * 144 + seg * 16, src);
        }
    };

    load_B(0, 0); load_act(0); CP_COMMIT();
    load_B(1, 1); CP_COMMIT();

    #pragma unroll 1
    for (int t = 0; t < NT; t++) {
        const unsigned short* hsH = (t == 0) ? g_h0b_hi : g_obf_hi + (size_t)(t - 1) * BS * HID;
        const unsigned short* hsL = (t == 0) ? g_h0b_lo : g_obf_lo + (size_t)(t - 1) * BS * HID;
        const char* srcAH = (const char*)(hsH + (size_t)mq * 64 * HID);
        const char* srcAL = (const char*)(hsL + (size_t)mq * 64 * HID);

        auto load_A = [&](int ch, int st) {
            uint32_t base = sb + st * STG_B;
            #pragma unroll
            for (int i = tid; i < 512; i += 256) {
                int row = i >> 3, seg = i & 7;
                CP16(base + OFF_AH + row * APITCH_B + seg * 16,
                     srcAH + (size_t)row * (HID * 2) + ch * 128 + seg * 16);
                CP16(base + OFF_AL + row * APITCH_B + seg * 16,
                     srcAL + (size_t)row * (HID * 2) + ch * 128 + seg * 16);
            }
        };

        if (t > 0) {
            if (tid == 0) {
                unsigned* ctr = &g_bars[mq * 32];
                const unsigned target = 32u * (unsigned)t;
                atomicAdd(ctr, 1u);
                unsigned v;
                do {
                    asm volatile("ld.volatile.global.u32 %0, [%1];" : "=r"(v) : "l"(ctr));
                } while (v < target);
            }
            __syncthreads();
            __threadfence();
        }

        load_A(0, 0); CP_COMMIT();
        load_A(1, 1); CP_COMMIT();

        // giv accumulators initialized from bi; filled incrementally in-loop.
        float giv[2][12];
        #pragma unroll
        for (int gate = 0; gate < 3; gate++)
            #pragma unroll
            for (int pp = 0; pp < 2; pp++) {
                float2 v = *reinterpret_cast<const float2*>(bi + gate * HID + hidbase + pp * 8 + lc2);
                giv[0][gate * 4 + pp * 2 + 0] = v.x;
                giv[0][gate * 4 + pp * 2 + 1] = v.y;
                giv[1][gate * 4 + pp * 2 + 0] = v.x;
                giv[1][gate * 4 + pp * 2 + 1] = v.y;
            }

        const float* ab = a_s + (t & 1) * (64 * 36);
        const float* gr0 = ab + (wm * 16 + lr) * 36;
        const float* gr1 = gr0 + 8 * 36;

        auto gi_piece = [&](int k4) {
            float4 a0 = *reinterpret_cast<const float4*>(gr0 + k4 * 4);
            float4 a1 = *reinterpret_cast<const float4*>(gr1 + k4 * 4);
            #pragma unroll
            for (int gate = 0; gate < 3; gate++)
                #pragma unroll
                for (int pp = 0; pp < 2; pp++)
                    #pragma unroll
                    for (int e = 0; e < 2; e++) {
                        int col = gate * 32 + wn * 16 + pp * 8 + lc2 + e;
                        float4 wv = *reinterpret_cast<const float4*>(wi_s + col * 36 + k4 * 4);
                        int j = gate * 4 + pp * 2 + e;
                        giv[0][j] += a0.x * wv.x + a0.y * wv.y + a0.z * wv.z + a0.w * wv.w;
                        giv[1][j] += a1.x * wv.x + a1.y * wv.y + a1.z * wv.z + a1.w * wv.w;
                    }
        };

        float c[6][4] = {};

        auto compute = [&](int st) {
            uint32_t base = sb + st * STG_B;
            #pragma unroll
            for (int kk = 0; kk < 4; kk++) {
                const int k0 = kk * 16;
                uint32_t aH[4], aL[4];
                uint32_t adA = base + OFF_AH + a_row * APITCH_B + (k0 + a_koff) * 2;
                LDSM4(aH, adA);
                LDSM4(aL, adA + (OFF_AL - OFF_AH));
                uint32_t bH[6][2], bL[6][2];
                #pragma unroll
                for (int g2 = 0; g2 < 3; g2++) {
                    uint32_t adB = base + OFF_BH + (k0 + b_krow) * BPITCH_B + (b_noff + g2 * 16) * 2;
                    uint32_t r4[4];
                    LDSM4T(r4, adB);
                    bH[g2 * 2][0] = r4[0]; bH[g2 * 2][1] = r4[1];
                    bH[g2 * 2 + 1][0] = r4[2]; bH[g2 * 2 + 1][1] = r4[3];
                    LDSM4T(r4, adB + (OFF_BL - OFF_BH));
                    bL[g2 * 2][0] = r4[0]; bL[g2 * 2][1] = r4[1];
                    bL[g2 * 2 + 1][0] = r4[2]; bL[g2 * 2 + 1][1] = r4[3];
                }
                #pragma unroll
                for (int g = 0; g < 6; g++) {
                    mma16816(c[g], aH, bH[g]);
                    mma16816(c[g], aH, bL[g]);
                    mma16816(c[g], aL, bH[g]);
                }
            }
        };

        #pragma unroll 1
        for (int ch = 0; ch < 16; ch++) {
            CP_WAIT(1);
            __syncthreads();
            compute(ch % 3);
            if (ch < 8) gi_piece(ch);     // FMA pipe fills gaps under mma/ldsm
            if (ch + 2 < 16) {
                int st2 = (ch + 2) % 3;
                load_A(ch + 2, st2);
                load_B(ch + 2, st2);
            }
            CP_COMMIT();
        }
        __syncthreads();

        if (t + 1 < NT) {
            load_B(0, 0); load_act(t + 1); CP_COMMIT();
            load_B(1, 1); CP_COMMIT();
        }

        // ---- epilogue: gates+blend; single bf16 hi/lo store ----
        #pragma unroll
        for (int rr = 0; rr < 2; rr++) {
            const int m = mq * 64 + wm * 16 + lr + rr * 8;
            #pragma unroll
            for (int pp = 0; pp < 2; pp++) {
                const int hid = hidbase + pp * 8 + lc2;
                float h[2];
                #pragma unroll
                for (int e = 0; e < 2; e++) {
                    float rv = c[pp][2 * rr + e];
                    float zv = c[2 + pp][2 * rr + e];
                    float nv = c[4 + pp][2 * rr + e];
                    float rg = fast_sigmoid(rv + giv[rr][0 * 4 + pp * 2 + e]);
                    float zg = fast_sigmoid(zv + giv[rr][1 * 4 + pp * 2 + e]);
                    float ng = fast_tanh(giv[rr][2 * 4 + pp * 2 + e] + rg * (nv + bh[pp][e]));
                    h[e] = (1.0f - zg) * ng + zg * hpreg[rr][pp][e];
                    hpreg[rr][pp][e] = h[e];
                }
                size_t d = ((size_t)t * BS + m) * HID + hid;
                unsigned short hi0, hi1, lo0, lo1;
                split2(h[0], hi0, lo0);
                split2(h[1], hi1, lo1);
                *reinterpret_cast<uint32_t*>(g_obf_hi + d) = ((uint32_t)hi1 << 16) | hi0;
                *reinterpret_cast<uint32_t*>(g_obf_lo + d) = ((uint32_t)lo1 << 16) | lo0;
            }
        }

        if (t + 1 < NT) {
            __threadfence();
            __syncthreads();
        }
    }
}

// ===========================================================================
// k_out_mma (unchanged from R14)
// ===========================================================================
#define O_AH 0
#define O_AL 9216
#define O_BH 18432
#define O_BL 27648
#define OSTG 36864
#define O_PITCH 144
#define SMEM_OUT (3 * OSTG)

__global__ void __launch_bounds__(256) k_out_mma(const float* __restrict__ bo,
                                                 float* __restrict__ out) {
    extern __shared__ char smem[];
    const uint32_t sb = smem_u32(smem);
    const int tid = threadIdx.x;
    const int w = tid >> 5, l = tid & 31;
    const int wm = w & 3;
    const int wn = w >> 2;
    const int lr = l >> 2;
    const int lc2 = (l & 3) * 2;
    const int R0 = blockIdx.x * 64;

    const int a_row  = wm * 16 + (l & 15);
    const int a_koff = (l >> 4) * 8;
    const int b_krow = l & 15;
    const int b_lhalf = (l >> 4) * 8;

    const char* srcAH = (const char*)(g_obf_hi + (size_t)R0 * HID);
    const char* srcAL = (const char*)(g_obf_lo + (size_t)R0 * HID);

    auto load = [&](int ch, int st) {
        uint32_t base = sb + st * OSTG;
        #pragma unroll
        for (int i = tid; i < 512; i += 256) {
            int r = i >> 3, sg = i & 7;
            CP16(base + O_AH + r * O_PITCH + sg * 16,
                 srcAH + (size_t)r * (HID * 2) + ch * 128 + sg * 16);
            CP16(base + O_AL + r * O_PITCH + sg * 16,
                 srcAL + (size_t)r * (HID * 2) + ch * 128 + sg * 16);
        }
        #pragma unroll
        for (int i = tid; i < 512; i += 256) {
            int r = i >> 3, sg = i & 7;
            CP16(base + O_BH + r * O_PITCH + sg * 16,
                 (const char*)g_wo_hi + ((size_t)(ch * 64 + r) * OUTD) * 2 + sg * 16);
            CP16(base + O_BL + r * O_PITCH + sg * 16,
                 (const char*)g_wo_lo + ((size_t)(ch * 64 + r) * OUTD) * 2 + sg * 16);
        }
    };

    load(0, 0); CP_COMMIT();
    load(1, 1); CP_COMMIT();

    float c[4][4] = {};

    auto compute = [&](int st) {
        uint32_t base = sb + st * OSTG;
        #pragma unroll
        for (int kk = 0; kk < 4; kk++) {
            const int k0 = kk * 16;
            uint32_t aH[4], aL[4];
            uint32_t adA = base + O_AH + a_row * O_PITCH + (k0 + a_koff) * 2;
            LDSM4(aH, adA);
            LDSM4(aL, adA + (O_AL - O_AH));
            uint32_t bH[4][2], bL[4][2];
            #pragma unroll
            for (int n16 = 0; n16 < 2; n16++) {
                uint32_t adB = base + O_BH + (k0 + b_krow) * O_PITCH
                             + (wn * 32 + n16 * 16 + b_lhalf) * 2;
                uint32_t r4[4];
                LDSM4T(r4, adB);
                bH[n16 * 2][0] = r4[0]; bH[n16 * 2][1] = r4[1];
                bH[n16 * 2 + 1][0] = r4[2]; bH[n16 * 2 + 1][1] = r4[3];
                LDSM4T(r4, adB + (O_BL - O_BH));
                bL[n16 * 2][0] = r4[0]; bL[n16 * 2][1] = r4[1];
                bL[n16 * 2 + 1][0] = r4[2]; bL[n16 * 2 + 1][1] = r4[3];
            }
            #pragma unroll
            for (int g = 0; g < 4; g++) {
                mma16816(c[g], aH, bH[g]);
                mma16816(c[g], aH, bL[g]);
                mma16816(c[g], aL, bH[g]);
            }
        }
    };

    #pragma unroll 1
    for (int ch = 0; ch < 16; ch++) {
        CP_WAIT(1);
        __syncthreads();
        compute(ch % 3);
        if (ch + 2 < 16) load(ch + 2, (ch + 2) % 3);
        CP_COMMIT();
    }

    #pragma unroll
    for (int g = 0; g < 4; g++) {
        const int col = wn * 32 + g * 8 + lc2;
        float2 bov = *reinterpret_cast<const float2*>(bo + col);
        #pragma unroll
        for (int rr = 0; rr < 2; rr++) {
            int R = R0 + wm * 16 + lr + rr * 8;
            int tt = R >> 8;
            int b  = R & (BS - 1);
            float2 o = make_float2(c[g][2 * rr] + bov.x, c[g][2 * rr + 1] + bov.y);
            *reinterpret_cast<float2*>(out + ((size_t)b * NT + tt) * OUTD + col) = o;
        }
    }
}

extern "C" void kernel_launch(void* const* d_in, const int* in_sizes, int n_in,
                              void* d_out, int out_size) {
    const float* history = (const float*)d_in[0];
    const float* action  = (const float*)d_in[1];
    const float* W_in    = (const float*)d_in[2];
    const float* b_in    = (const float*)d_in[3];
    const float* Wi      = (const float*)d_in[4];
    const float* bi      = (const float*)d_in[5];
    const float* Wh      = (const float*)d_in[6];
    const float* bhn     = (const float*)d_in[7];
    const float* Wo      = (const float*)d_in[8];
    const float* bo      = (const float*)d_in[9];
    float* out = (float*)d_out;

    float *h0buf = nullptr, *h0pbuf = nullptr;
    cudaGetSymbolAddress((void**)&h0buf, g_h0);
    cudaGetSymbolAddress((void**)&h0pbuf, g_h0p);

    cudaFuncSetAttribute(k_h0_mma2, cudaFuncAttributeMaxDynamicSharedMemorySize, SMEM_H0);
    cudaFuncSetAttribute(k_steps_mma, cudaFuncAttributeMaxDynamicSharedMemorySize, SMEM_MMA);
    cudaFuncSetAttribute(k_out_mma, cudaFuncAttributeMaxDynamicSharedMemorySize, SMEM_OUT);

    k_prep<<<5032, 256>>>(history, W_in, Wo);
    k_packW<<<dim3(32, 16), 256>>>(Wh);

    k_h0_mma2<<<dim3(HID / 64, BS / 32, 2), 256, SMEM_H0>>>(h0pbuf);
    k_h0fix<<<BS * HID / (256 * 8), 256>>>(b_in);

    k_steps_mma<<<dim3(32, 4), 256, SMEM_MMA>>>(h0buf, action, Wi, bi, bhn);

    k_out_mma<<<NT * BS / 64, 256, SMEM_OUT>>>(bo, out);
}

// round 16
// speedup vs baseline: 1.8732x; 1.0541x over previous
#include <cuda_runtime.h>
#include <cuda_bf16.h>
#include <cstdint>
#include <cstddef>

#define BS   256
#define HID  1024
#define NT   100
#define ACT  32
#define KIN  8000
#define G3   3072
#define OUTD 64

// ---------------- device scratch (allocation-free rule) ----------------
__device__ float g_h0[BS * HID];
__device__ float g_h0p[2 * BS * HID];
__device__ unsigned g_bars[4 * 32];

__device__ __align__(16) unsigned short g_obf_hi[(size_t)NT * BS * HID];
__device__ __align__(16) unsigned short g_obf_lo[(size_t)NT * BS * HID];
__device__ __align__(16) unsigned short g_h0b_hi[BS * HID];
__device__ __align__(16) unsigned short g_h0b_lo[BS * HID];
__device__ __align__(16) unsigned short g_wBp_hi[32 * HID * 96];
__device__ __align__(16) unsigned short g_wBp_lo[32 * HID * 96];
__device__ __align__(16) unsigned short g_wo_hi[HID * OUTD];
__device__ __align__(16) unsigned short g_wo_lo[HID * OUTD];
__device__ __align__(16) unsigned short g_win_hi[(size_t)KIN * HID];
__device__ __align__(16) unsigned short g_win_lo[(size_t)KIN * HID];
__device__ __align__(16) unsigned short g_x_hi[BS * KIN];
__device__ __align__(16) unsigned short g_x_lo[BS * KIN];

// ---------------- helpers ----------------
__device__ __forceinline__ float fast_sigmoid(float x) {
    return __fdividef(1.0f, 1.0f + __expf(-x));
}
__device__ __forceinline__ float fast_tanh(float x) {
    float e = __expf(2.0f * x);
    return 1.0f - __fdividef(2.0f, e + 1.0f);
}
__device__ __forceinline__ void split2(float x, unsigned short& h, unsigned short& l) {
    __nv_bfloat16 hb = __float2bfloat16(x);
    float hf = __bfloat162float(hb);
    __nv_bfloat16 lb = __float2bfloat16(x - hf);
    h = *reinterpret_cast<unsigned short*>(&hb);
    l = *reinterpret_cast<unsigned short*>(&lb);
}
__device__ __forceinline__ void split8(const float* src, uint4& H, uint4& L) {
    unsigned short* ph = (unsigned short*)&H;
    unsigned short* pl = (unsigned short*)&L;
    float4 v0 = *reinterpret_cast<const float4*>(src);
    float4 v1 = *reinterpret_cast<const float4*>(src + 4);
    split2(v0.x, ph[0], pl[0]); split2(v0.y, ph[1], pl[1]);
    split2(v0.z, ph[2], pl[2]); split2(v0.w, ph[3], pl[3]);
    split2(v1.x, ph[4], pl[4]); split2(v1.y, ph[5], pl[5]);
    split2(v1.z, ph[6], pl[6]); split2(v1.w, ph[7], pl[7]);
}

#define CP16(dst, src) asm volatile("cp.async.cg.shared.global [%0], [%1], 16;\n" :: "r"(dst), "l"(src))
#define CP_COMMIT()    asm volatile("cp.async.commit_group;\n")
#define CP_WAIT(n)     asm volatile("cp.async.wait_group %0;\n" :: "n"(n))

__device__ __forceinline__ uint32_t smem_u32(const void* p) {
    uint32_t a;
    asm("{ .reg .u64 t; cvta.to.shared.u64 t, %1; cvt.u32.u64 %0, t; }" : "=r"(a) : "l"(p));
    return a;
}
__device__ __forceinline__ void mma16816(float* c, const uint32_t* a, const uint32_t* b) {
    asm volatile("mma.sync.aligned.m16n8k16.row.col.f32.bf16.bf16.f32 "
        "{%0,%1,%2,%3}, {%4,%5,%6,%7}, {%8,%9}, {%0,%1,%2,%3};"
        : "+f"(c[0]), "+f"(c[1]), "+f"(c[2]), "+f"(c[3])
        : "r"(a[0]), "r"(a[1]), "r"(a[2]), "r"(a[3]), "r"(b[0]), "r"(b[1]));
}
#define LDSM4(r, addr)                                                          \
    asm volatile("ldmatrix.sync.aligned.m8n8.x4.shared.b16 {%0,%1,%2,%3}, [%4];"\
        : "=r"((r)[0]), "=r"((r)[1]), "=r"((r)[2]), "=r"((r)[3]) : "r"(addr))
#define LDSM4T(r, addr)                                                         \
    asm volatile("ldmatrix.sync.aligned.m8n8.x4.trans.shared.b16 {%0,%1,%2,%3}, [%4];" \
        : "=r"((r)[0]), "=r"((r)[1]), "=r"((r)[2]), "=r"((r)[3]) : "r"(addr))

// ===========================================================================
// k_prep (unchanged)
// ===========================================================================
#define NXV  ((size_t)BS * KIN / 8)
#define NWV  ((size_t)KIN * HID / 8)
#define NOV  ((size_t)HID * OUTD / 8)

__global__ void __launch_bounds__(256) k_prep(const float* __restrict__ X,
                                              const float* __restrict__ Win,
                                              const float* __restrict__ Wo) {
    if (blockIdx.x == 0 && threadIdx.x < 128) g_bars[threadIdx.x] = 0u;
    size_t vi = (size_t)blockIdx.x * 256 + threadIdx.x;
    uint4 H, L;
    if (vi < NXV) {
        size_t i = vi * 8;
        split8(X + i, H, L);
        *reinterpret_cast<uint4*>(g_x_hi + i) = H;
        *reinterpret_cast<uint4*>(g_x_lo + i) = L;
    } else if (vi < NXV + NWV) {
        size_t i = (vi - NXV) * 8;
        split8(Win + i, H, L);
        *reinterpret_cast<uint4*>(g_win_hi + i) = H;
        *reinterpret_cast<uint4*>(g_win_lo + i) = L;
    } else if (vi < NXV + NWV + NOV) {
        size_t i = (vi - NXV - NWV) * 8;
        split8(Wo + i, H, L);
        *reinterpret_cast<uint4*>(g_wo_hi + i) = H;
        *reinterpret_cast<uint4*>(g_wo_lo + i) = L;
    }
}

// ===========================================================================
// k_packW (unchanged)
// ===========================================================================
__global__ void __launch_bounds__(256) k_packW(const float* __restrict__ Wh) {
    const int s = blockIdx.x, kg = blockIdx.y;
    for (int i = threadIdx.x; i < 64 * 12; i += 256) {
        int k = kg * 64 + i / 12;
        int c8 = (i % 12) * 8;
        int sub = c8 / 48, rem = c8 % 48;
        int gate = rem / 16, h0 = rem % 16;
        const float* src = Wh + (size_t)k * G3 + gate * HID + s * 32 + sub * 16 + h0;
        uint4 H, L;
        split8(src, H, L);
        size_t d = ((size_t)s * HID + k) * 96 + c8;
        *reinterpret_cast<uint4*>(g_wBp_hi + d) = H;
        *reinterpret_cast<uint4*>(g_wBp_lo + d) = L;
    }
}

// ===========================================================================
// k_h0_mma2 (unchanged)
// ===========================================================================
#define H_AH 0
#define H_AL 4608
#define H_BH 9216
#define H_BL 18432
#define HSTG2 27648
#define SMEM_H0 (3 * HSTG2)

__global__ void __launch_bounds__(256) k_h0_mma2(float* __restrict__ H0P) {
    extern __shared__ char smem[];
    const uint32_t sb = smem_u32(smem);
    const int tid = threadIdx.x;
    const int w = tid >> 5, l = tid & 31;
    const int wm = w & 1;
    const int wn = w >> 1;
    const int lr = l >> 2;
    const int lc2 = (l & 3) * 2;
    const int m0 = blockIdx.y * 32, n0 = blockIdx.x * 64;
    const int z = blockIdx.z;
    const int c0 = z ? 63 : 0;
    const int nch = z ? 62 : 63;

    const int a_row  = wm * 16 + (l & 15);
    const int a_koff = (l >> 4) * 8;
    const int b_krow = l & 15;
    const int b_lhalf = (l >> 4) * 8;

    const char* srcAH = (const char*)(g_x_hi + (size_t)m0 * KIN);
    const char* srcAL = (const char*)(g_x_lo + (size_t)m0 * KIN);

    auto load = [&](int cha, int st) {
        uint32_t base = sb + st * HSTG2;
        {
            int r = tid >> 3, sg = tid & 7;
            CP16(base + H_AH + r * 144 + sg * 16,
                 srcAH + (size_t)r * (KIN * 2) + cha * 128 + sg * 16);
            CP16(base + H_AL + r * 144 + sg * 16,
                 srcAL + (size_t)r * (KIN * 2) + cha * 128 + sg * 16);
        }
        #pragma unroll
        for (int i = tid; i < 512; i += 256) {
            int r = i >> 3, sg = i & 7;
            CP16(base + H_BH + r * 144 + sg * 16,
                 (const char*)g_win_hi + ((size_t)(cha * 64 + r) * HID + n0) * 2 + sg * 16);
            CP16(base + H_BL + r * 144 + sg * 16,
                 (const char*)g_win_lo + ((size_t)(cha * 64 + r) * HID + n0) * 2 + sg * 16);
        }
    };

    load(c0 + 0, 0); CP_COMMIT();
    load(c0 + 1, 1); CP_COMMIT();

    float c[2][4] = {};

    auto compute = [&](int st) {
        uint32_t base = sb + st * HSTG2;
        #pragma unroll
        for (int kk = 0; kk < 4; kk++) {
            const int k0 = kk * 16;
            uint32_t aH[4], aL[4];
            uint32_t adA = base + H_AH + a_row * 144 + (k0 + a_koff) * 2;
            LDSM4(aH, adA);
            LDSM4(aL, adA + (H_AL - H_AH));
            uint32_t bH[2][2], bL[2][2];
            uint32_t adB = base + H_BH + (k0 + b_krow) * 144 + (wn * 16 + b_lhalf) * 2;
            uint32_t r4[4];
            LDSM4T(r4, adB);
            bH[0][0] = r4[0]; bH[0][1] = r4[1]; bH[1][0] = r4[2]; bH[1][1] = r4[3];
            LDSM4T(r4, adB + (H_BL - H_BH));
            bL[0][0] = r4[0]; bL[0][1] = r4[1]; bL[1][0] = r4[2]; bL[1][1] = r4[3];
            #pragma unroll
            for (int g = 0; g < 2; g++) {
                mma16816(c[g], aH, bH[g]);
                mma16816(c[g], aH, bL[g]);
                mma16816(c[g], aL, bH[g]);
            }
        }
    };

    #pragma unroll 1
    for (int ch = 0; ch < nch; ch++) {
        CP_WAIT(1);
        __syncthreads();
        compute(ch % 3);
        if (ch + 2 < nch) load(c0 + ch + 2, (ch + 2) % 3);
        CP_COMMIT();
    }

    float* dst = H0P + (size_t)z * BS * HID;
    #pragma unroll
    for (int g = 0; g < 2; g++) {
        const int col = n0 + wn * 16 + g * 8 + lc2;
        #pragma unroll
        for (int rr = 0; rr < 2; rr++) {
            const int m = m0 + wm * 16 + lr + rr * 8;
            *reinterpret_cast<float2*>(dst + (size_t)m * HID + col) =
                make_float2(c[g][2 * rr], c[g][2 * rr + 1]);
        }
    }
}

// ===========================================================================
// k_h0fix (unchanged)
// ===========================================================================
__global__ void __launch_bounds__(256) k_h0fix(const float* __restrict__ b_in) {
    size_t i = ((size_t)blockIdx.x * 256 + threadIdx.x) * 8;
    float r[8];
    #pragma unroll
    for (int j = 0; j < 8; j += 4) {
        float4 a = *reinterpret_cast<const float4*>(g_h0p + i + j);
        float4 b = *reinterpret_cast<const float4*>(g_h0p + BS * HID + i + j);
        float4 bb = *reinterpret_cast<const float4*>(b_in + ((i + j) & (HID - 1)));
        r[j + 0] = a.x + b.x + bb.x;
        r[j + 1] = a.y + b.y + bb.y;
        r[j + 2] = a.z + b.z + bb.z;
        r[j + 3] = a.w + b.w + bb.w;
    }
    #pragma unroll
    for (int j = 0; j < 8; j++) r[j] = r[j] > 0.f ? r[j] : 0.f;
    *reinterpret_cast<float4*>(g_h0 + i)     = make_float4(r[0], r[1], r[2], r[3]);
    *reinterpret_cast<float4*>(g_h0 + i + 4) = make_float4(r[4], r[5], r[6], r[7]);
    uint4 H, L;
    unsigned short* ph = (unsigned short*)&H;
    unsigned short* pl = (unsigned short*)&L;
    #pragma unroll
    for (int j = 0; j < 8; j++) split2(r[j], ph[j], pl[j]);
    *reinterpret_cast<uint4*>(g_h0b_hi + i) = H;
    *reinterpret_cast<uint4*>(g_h0b_lo + i) = L;
}

// ===========================================================================
// k_steps_mma v9: warp grid 2m x 2n x 2k — B ldsm redundancy 4x -> 2x.
// Cross-k reduction via stage-2 smem once per step; epilogue on wk==0 warps.
// ===========================================================================
#define OFF_AH 0
#define OFF_AL 9216
#define OFF_BH 18432
#define OFF_BL 31744
#define STG_B  45056
#define APITCH_B 144
#define BPITCH_B 208
#define SM_WI  (3 * STG_B)
#define SM_AS  (SM_WI + 96 * 36 * 4)
#define SMEM_MMA (SM_AS + 2 * 64 * 36 * 4)  // 167424 B

__global__ void __launch_bounds__(256, 1) k_steps_mma(const float* __restrict__ h0,
                                                      const float* __restrict__ action,
                                                      const float* __restrict__ Wi,
                                                      const float* __restrict__ bi,
                                                      const float* __restrict__ bhn) {
    extern __shared__ char smem[];
    const uint32_t sb = smem_u32(smem);
    float* wi_s = reinterpret_cast<float*>(smem + SM_WI);
    float* a_s  = reinterpret_cast<float*>(smem + SM_AS);
    float* red  = reinterpret_cast<float*>(smem + 2 * STG_B);  // stage-2 reuse

    const int tid = threadIdx.x;
    const int w = tid >> 5, l = tid & 31;
    const int s = blockIdx.x;
    const int mq = blockIdx.y;
    const int wm = w & 1;            // m half: rows wm*32 .. wm*32+31 (2 m16)
    const int wn = (w >> 1) & 1;     // hid sub (16 cols)
    const int wk = w >> 2;           // k half of each chunk
    const int lr = l >> 2;
    const int lc2 = (l & 3) * 2;

    const int a_koff = (l >> 4) * 8;
    const int b_krow = l & 15;
    const int b_noff = wn * 48 + (l >> 4) * 8;

    const int hidbase = s * 32 + wn * 16;

    float bh[2][2];
    #pragma unroll
    for (int pp = 0; pp < 2; pp++) {
        float2 v = *reinterpret_cast<const float2*>(bhn + hidbase + pp * 8 + lc2);
        bh[pp][0] = v.x; bh[pp][1] = v.y;
    }
    // h_prev regs: [mb][rr][pp][e]
    float hpreg[2][2][2][2];
    #pragma unroll
    for (int mb = 0; mb < 2; mb++)
        #pragma unroll
        for (int rr = 0; rr < 2; rr++) {
            const int m = mq * 64 + wm * 32 + mb * 16 + rr * 8 + lr;
            #pragma unroll
            for (int pp = 0; pp < 2; pp++) {
                float2 v = *reinterpret_cast<const float2*>(h0 + (size_t)m * HID + hidbase + pp * 8 + lc2);
                hpreg[mb][rr][pp][0] = v.x; hpreg[mb][rr][pp][1] = v.y;
            }
        }

    for (int i = tid; i < 96 * 32; i += 256) {
        int col = i >> 5, k = i & 31;
        int gate = col >> 5, cl = col & 31;
        wi_s[col * 36 + k] = Wi[(size_t)k * G3 + gate * HID + s * 32 + cl];
    }
    __syncthreads();

    const char* srcBH = (const char*)(g_wBp_hi + (size_t)s * HID * 96);
    const char* srcBL = (const char*)(g_wBp_lo + (size_t)s * HID * 96);

    auto load_B = [&](int ch, int st) {
        uint32_t base = sb + st * STG_B;
        #pragma unroll
        for (int i = tid; i < 768; i += 256) {
            int r = i / 12, sg = i % 12;
            CP16(base + OFF_BH + r * BPITCH_B + sg * 16,
                 srcBH + ((size_t)(ch * 64 + r)) * 192 + sg * 16);
            CP16(base + OFF_BL + r * BPITCH_B + sg * 16,
                 srcBL + ((size_t)(ch * 64 + r)) * 192 + sg * 16);
        }
    };
    auto load_act = [&](int tt) {
        uint32_t ab2 = sb + SM_AS + (tt & 1) * (64 * 36 * 4);
        #pragma unroll
        for (int i = tid; i < 512; i += 256) {
            int row = i >> 3, seg = i & 7;
            const float* src = action + ((size_t)(mq * 64 + row) * NT + tt) * ACT + seg * 4;
            CP16(ab2 + row * 144 + seg * 16, src);
        }
    };

    load_B(0, 0); load_act(0); CP_COMMIT();
    load_B(1, 1); CP_COMMIT();

    #pragma unroll 1
    for (int t = 0; t < NT; t++) {
        const unsigned short* hsH = (t == 0) ? g_h0b_hi : g_obf_hi + (size_t)(t - 1) * BS * HID;
        const unsigned short* hsL = (t == 0) ? g_h0b_lo : g_obf_lo + (size_t)(t - 1) * BS * HID;
        const char* srcAH = (const char*)(hsH + (size_t)mq * 64 * HID);
        const char* srcAL = (const char*)(hsL + (size_t)mq * 64 * HID);

        auto load_A = [&](int ch, int st) {
            uint32_t base = sb + st * STG_B;
            #pragma unroll
            for (int i = tid; i < 512; i += 256) {
                int row = i >> 3, seg = i & 7;
                CP16(base + OFF_AH + row * APITCH_B + seg * 16,
                     srcAH + (size_t)row * (HID * 2) + ch * 128 + seg * 16);
                CP16(base + OFF_AL + row * APITCH_B + seg * 16,
                     srcAL + (size_t)row * (HID * 2) + ch * 128 + seg * 16);
            }
        };

        if (t > 0) {
            if (tid == 0) {
                unsigned* ctr = &g_bars[mq * 32];
                const unsigned target = 32u * (unsigned)t;
                atomicAdd(ctr, 1u);
                unsigned v;
                do {
                    asm volatile("ld.volatile.global.u32 %0, [%1];" : "=r"(v) : "l"(ctr));
                } while (v < target);
            }
            __syncthreads();
            __threadfence();
        }

        load_A(0, 0); CP_COMMIT();
        load_A(1, 1); CP_COMMIT();

        // giv accumulators [mb*2+rr][12], init from bi (used by wk==0 only)
        float giv[4][12];
        #pragma unroll
        for (int gate = 0; gate < 3; gate++)
            #pragma unroll
            for (int pp = 0; pp < 2; pp++) {
                float2 v = *reinterpret_cast<const float2*>(bi + gate * HID + hidbase + pp * 8 + lc2);
                #pragma unroll
                for (int mr = 0; mr < 4; mr++) {
                    giv[mr][gate * 4 + pp * 2 + 0] = v.x;
                    giv[mr][gate * 4 + pp * 2 + 1] = v.y;
                }
            }

        const float* ab = a_s + (t & 1) * (64 * 36);

        auto gi_piece = [&](int k4) {
            float4 a[4];
            #pragma unroll
            for (int mr = 0; mr < 4; mr++)
                a[mr] = *reinterpret_cast<const float4*>(
                    ab + (wm * 32 + (mr >> 1) * 16 + (mr & 1) * 8 + lr) * 36 + k4 * 4);
            #pragma unroll
            for (int gate = 0; gate < 3; gate++)
                #pragma unroll
                for (int pp = 0; pp < 2; pp++)
                    #pragma unroll
                    for (int e = 0; e < 2; e++) {
                        int col = gate * 32 + wn * 16 + pp * 8 + lc2 + e;
                        float4 wv = *reinterpret_cast<const float4*>(wi_s + col * 36 + k4 * 4);
                        int j = gate * 4 + pp * 2 + e;
                        #pragma unroll
                        for (int mr = 0; mr < 4; mr++)
                            giv[mr][j] += a[mr].x * wv.x + a[mr].y * wv.y
                                        + a[mr].z * wv.z + a[mr].w * wv.w;
                    }
        };

        float c[6][2][4] = {};   // [gate*2+pp][mb][frag]

        auto compute = [&](int st) {
            uint32_t base = sb + st * STG_B;
            #pragma unroll
            for (int kki = 0; kki < 2; kki++) {
                const int k0 = (wk * 2 + kki) * 16;
                uint32_t aH[2][4], aL[2][4];
                #pragma unroll
                for (int mb = 0; mb < 2; mb++) {
                    uint32_t adA = base + OFF_AH
                                 + (wm * 32 + mb * 16 + (l & 15)) * APITCH_B
                                 + (k0 + a_koff) * 2;
                    LDSM4(aH[mb], adA);
                    LDSM4(aL[mb], adA + (OFF_AL - OFF_AH));
                }
                uint32_t bH[6][2], bL[6][2];
                #pragma unroll
                for (int g2 = 0; g2 < 3; g2++) {
                    uint32_t adB = base + OFF_BH + (k0 + b_krow) * BPITCH_B + (b_noff + g2 * 16) * 2;
                    uint32_t r4[4];
                    LDSM4T(r4, adB);
                    bH[g2 * 2][0] = r4[0]; bH[g2 * 2][1] = r4[1];
                    bH[g2 * 2 + 1][0] = r4[2]; bH[g2 * 2 + 1][1] = r4[3];
                    LDSM4T(r4, adB + (OFF_BL - OFF_BH));
                    bL[g2 * 2][0] = r4[0]; bL[g2 * 2][1] = r4[1];
                    bL[g2 * 2 + 1][0] = r4[2]; bL[g2 * 2 + 1][1] = r4[3];
                }
                #pragma unroll
                for (int g = 0; g < 6; g++)
                    #pragma unroll
                    for (int mb = 0; mb < 2; mb++) {
                        mma16816(c[g][mb], aH[mb], bH[g]);
                        mma16816(c[g][mb], aH[mb], bL[g]);
                        mma16816(c[g][mb], aL[mb], bH[g]);
                    }
            }
        };

        #pragma unroll 1
        for (int ch = 0; ch < 16; ch++) {
            CP_WAIT(1);
            __syncthreads();
            compute(ch % 3);
            if (wk == 0 && ch < 8) gi_piece(ch);
            if (ch + 2 < 16) {
                int st2 = (ch + 2) % 3;
                load_A(ch + 2, st2);
                load_B(ch + 2, st2);
            }
            CP_COMMIT();
        }
        __syncthreads();   // computes done; stages 0/1 refillable; stage 2 free

        // wk==1 warps dump partial accumulators into stage-2 smem
        if (wk == 1) {
            int slot = ((w & 3) * 32 + l) * 52;
            #pragma unroll
            for (int g = 0; g < 6; g++)
                #pragma unroll
                for (int mb = 0; mb < 2; mb++)
                    *reinterpret_cast<float4*>(red + slot + (g * 2 + mb) * 4) =
                        *reinterpret_cast<const float4*>(c[g][mb]);
        }

        if (t + 1 < NT) {
            load_B(0, 0); load_act(t + 1); CP_COMMIT();
            load_B(1, 1); CP_COMMIT();
        }
        __syncthreads();   // partials visible

        if (wk == 0) {
            int slot = ((w & 3) * 32 + l) * 52;
            #pragma unroll
            for (int g = 0; g < 6; g++)
                #pragma unroll
                for (int mb = 0; mb < 2; mb++) {
                    float4 p = *reinterpret_cast<const float4*>(red + slot + (g * 2 + mb) * 4);
                    c[g][mb][0] += p.x; c[g][mb][1] += p.y;
                    c[g][mb][2] += p.z; c[g][mb][3] += p.w;
                }

            // ---- epilogue: gates+blend; single bf16 hi/lo store ----
            #pragma unroll
            for (int mb = 0; mb < 2; mb++)
                #pragma unroll
                for (int rr = 0; rr < 2; rr++) {
                    const int m = mq * 64 + wm * 32 + mb * 16 + rr * 8 + lr;
                    const int mr = mb * 2 + rr;
                    #pragma unroll
                    for (int pp = 0; pp < 2; pp++) {
                        const int hid = hidbase + pp * 8 + lc2;
                        float h[2];
                        #pragma unroll
                        for (int e = 0; e < 2; e++) {
                            float rv = c[0 + pp][mb][2 * rr + e];
                            float zv = c[2 + pp][mb][2 * rr + e];
                            float nv = c[4 + pp][mb][2 * rr + e];
                            float rg = fast_sigmoid(rv + giv[mr][0 * 4 + pp * 2 + e]);
                            float zg = fast_sigmoid(zv + giv[mr][1 * 4 + pp * 2 + e]);
                            float ng = fast_tanh(giv[mr][2 * 4 + pp * 2 + e] + rg * (nv + bh[pp][e]));
                            h[e] = (1.0f - zg) * ng + zg * hpreg[mb][rr][pp][e];
                            hpreg[mb][rr][pp][e] = h[e];
                        }
                        size_t d = ((size_t)t * BS + m) * HID + hid;
                        unsigned short hi0, hi1, lo0, lo1;
                        split2(h[0], hi0, lo0);
                        split2(h[1], hi1, lo1);
                        *reinterpret_cast<uint32_t*>(g_obf_hi + d) = ((uint32_t)hi1 << 16) | hi0;
                        *reinterpret_cast<uint32_t*>(g_obf_lo + d) = ((uint32_t)lo1 << 16) | lo0;
                    }
                }
        }

        if (t + 1 < NT) {
            __threadfence();
            __syncthreads();
        }
    }
}

// ===========================================================================
// k_out_mma (unchanged)
// ===========================================================================
#define O_AH 0
#define O_AL 9216
#define O_BH 18432
#define O_BL 27648
#define OSTG 36864
#define O_PITCH 144
#define SMEM_OUT (3 * OSTG)

__global__ void __launch_bounds__(256) k_out_mma(const float* __restrict__ bo,
                                                 float* __restrict__ out) {
    extern __shared__ char smem[];
    const uint32_t sb = smem_u32(smem);
    const int tid = threadIdx.x;
    const int w = tid >> 5, l = tid & 31;
    const int wm = w & 3;
    const int wn = w >> 2;
    const int lr = l >> 2;
    const int lc2 = (l & 3) * 2;
    const int R0 = blockIdx.x * 64;

    const int a_row  = wm * 16 + (l & 15);
    const int a_koff = (l >> 4) * 8;
    const int b_krow = l & 15;
    const int b_lhalf = (l >> 4) * 8;

    const char* srcAH = (const char*)(g_obf_hi + (size_t)R0 * HID);
    const char* srcAL = (const char*)(g_obf_lo + (size_t)R0 * HID);

    auto load = [&](int ch, int st) {
        uint32_t base = sb + st * OSTG;
        #pragma unroll
        for (int i = tid; i < 512; i += 256) {
            int r = i >> 3, sg = i & 7;
            CP16(base + O_AH + r * O_PITCH + sg * 16,
                 srcAH + (size_t)r * (HID * 2) + ch * 128 + sg * 16);
            CP16(base + O_AL + r * O_PITCH + sg * 16,
                 srcAL + (size_t)r * (HID * 2) + ch * 128 + sg * 16);
        }
        #pragma unroll
        for (int i = tid; i < 512; i += 256) {
            int r = i >> 3, sg = i & 7;
            CP16(base + O_BH + r * O_PITCH + sg * 16,
                 (const char*)g_wo_hi + ((size_t)(ch * 64 + r) * OUTD) * 2 + sg * 16);
            CP16(base + O_BL + r * O_PITCH + sg * 16,
                 (const char*)g_wo_lo + ((size_t)(ch * 64 + r) * OUTD) * 2 + sg * 16);
        }
    };

    load(0, 0); CP_COMMIT();
    load(1, 1); CP_COMMIT();

    float c[4][4] = {};

    auto compute = [&](int st) {
        uint32_t base = sb + st * OSTG;
        #pragma unroll
        for (int kk = 0; kk < 4; kk++) {
            const int k0 = kk * 16;
            uint32_t aH[4], aL[4];
            uint32_t adA = base + O_AH + a_row * O_PITCH + (k0 + a_koff) * 2;
            LDSM4(aH, adA);
            LDSM4(aL, adA + (O_AL - O_AH));
            uint32_t bH[4][2], bL[4][2];
            #pragma unroll
            for (int n16 = 0; n16 < 2; n16++) {
                uint32_t adB = base + O_BH + (k0 + b_krow) * O_PITCH
                             + (wn * 32 + n16 * 16 + b_lhalf) * 2;
                uint32_t r4[4];
                LDSM4T(r4, adB);
                bH[n16 * 2][0] = r4[0]; bH[n16 * 2][1] = r4[1];
                bH[n16 * 2 + 1][0] = r4[2]; bH[n16 * 2 + 1][1] = r4[3];
                LDSM4T(r4, adB + (O_BL - O_BH));
                bL[n16 * 2][0] = r4[0]; bL[n16 * 2][1] = r4[1];
                bL[n16 * 2 + 1][0] = r4[2]; bL[n16 * 2 + 1][1] = r4[3];
            }
            #pragma unroll
            for (int g = 0; g < 4; g++) {
                mma16816(c[g], aH, bH[g]);
                mma16816(c[g], aH, bL[g]);
                mma16816(c[g], aL, bH[g]);
            }
        }
    };

    #pragma unroll 1
    for (int ch = 0; ch < 16; ch++) {
        CP_WAIT(1);
        __syncthreads();
        compute(ch % 3);
        if (ch + 2 < 16) load(ch + 2, (ch + 2) % 3);
        CP_COMMIT();
    }

    #pragma unroll
    for (int g = 0; g < 4; g++) {
        const int col = wn * 32 + g * 8 + lc2;
        float2 bov = *reinterpret_cast<const float2*>(bo + col);
        #pragma unroll
        for (int rr = 0; rr < 2; rr++) {
            int R = R0 + wm * 16 + lr + rr * 8;
            int tt = R >> 8;
            int b  = R & (BS - 1);
            float2 o = make_float2(c[g][2 * rr] + bov.x, c[g][2 * rr + 1] + bov.y);
            *reinterpret_cast<float2*>(out + ((size_t)b * NT + tt) * OUTD + col) = o;
        }
    }
}

extern "C" void kernel_launch(void* const* d_in, const int* in_sizes, int n_in,
                              void* d_out, int out_size) {
    const float* history = (const float*)d_in[0];
    const float* action  = (const float*)d_in[1];
    const float* W_in    = (const float*)d_in[2];
    const float* b_in    = (const float*)d_in[3];
    const float* Wi      = (const float*)d_in[4];
    const float* bi      = (const float*)d_in[5];
    const float* Wh      = (const float*)d_in[6];
    const float* bhn     = (const float*)d_in[7];
    const float* Wo      = (const float*)d_in[8];
    const float* bo      = (const float*)d_in[9];
    float* out = (float*)d_out;

    float *h0buf = nullptr, *h0pbuf = nullptr;
    cudaGetSymbolAddress((void**)&h0buf, g_h0);
    cudaGetSymbolAddress((void**)&h0pbuf, g_h0p);

    cudaFuncSetAttribute(k_h0_mma2, cudaFuncAttributeMaxDynamicSharedMemorySize, SMEM_H0);
    cudaFuncSetAttribute(k_steps_mma, cudaFuncAttributeMaxDynamicSharedMemorySize, SMEM_MMA);
    cudaFuncSetAttribute(k_out_mma, cudaFuncAttributeMaxDynamicSharedMemorySize, SMEM_OUT);

    k_prep<<<5032, 256>>>(history, W_in, Wo);
    k_packW<<<dim3(32, 16), 256>>>(Wh);

    k_h0_mma2<<<dim3(HID / 64, BS / 32, 2), 256, SMEM_H0>>>(h0pbuf);
    k_h0fix<<<BS * HID / (256 * 8), 256>>>(b_in);

    k_steps_mma<<<dim3(32, 4), 256, SMEM_MMA>>>(h0buf, action, Wi, bi, bhn);

    k_out_mma<<<NT * BS / 64, 256, SMEM_OUT>>>(bo, out);
}